// round 1
// baseline (speedup 1.0000x reference)
#include <cuda_runtime.h>
#include <math.h>

#define B_   16
#define LT   512
#define LI   576
#define TD   768
#define ID   1024
#define HID  2048
#define NH   8
#define HD   256
#define FFD  128

// Scratch (device globals; no allocation allowed in kernel_launch)
__device__ float g_Q[B_ * LT * HID];
__device__ float g_K[B_ * LI * HID];
__device__ float g_V[B_ * LI * HID];
__device__ float g_X[B_ * LT * HID];
__device__ float g_O[B_ * LT * TD];
__device__ float g_H[B_ * LT * FFD];
__device__ float g_F[B_ * LT * TD];

// ---------------------------------------------------------------------------
// Tiled SGEMM: C[M,N] = A[M,K] @ W[K,N] + bias  (optional ReLU)
// BM=BN=128, BK=16, 256 threads, 8x8 micro-tile per thread.
// Requires M%128==0, N%128==0, K%16==0 (all shapes here satisfy this).
// ---------------------------------------------------------------------------
__global__ __launch_bounds__(256, 2)
void sgemm_bias(const float* __restrict__ A, const float* __restrict__ W,
                const float* __restrict__ bias, float* __restrict__ C,
                int M, int N, int Kd, int relu)
{
    __shared__ float As[16][128];   // transposed A tile: As[k][m]
    __shared__ float Bs[16][128];   // Bs[k][n]

    const int tid = threadIdx.x;
    const int bm  = blockIdx.y * 128;
    const int bn  = blockIdx.x * 128;
    const int ty  = tid >> 4;        // 0..15
    const int tx  = tid & 15;        // 0..15

    const int ar  = tid >> 1;        // 0..127  (A row within tile)
    const int ak  = (tid & 1) << 3;  // 0 or 8  (A k offset)
    const int bkr = tid >> 4;        // 0..15   (B k row)
    const int bn8 = (tid & 15) << 3; // 0..120  (B n offset)

    const float* Aptr = A + (size_t)(bm + ar) * Kd + ak;
    const float* Wptr = W + (size_t)bkr * N + bn + bn8;

    float acc[8][8];
#pragma unroll
    for (int i = 0; i < 8; i++)
#pragma unroll
        for (int j = 0; j < 8; j++) acc[i][j] = 0.0f;

    for (int k0 = 0; k0 < Kd; k0 += 16) {
        float4 a0 = *(const float4*)(Aptr + k0);
        float4 a1 = *(const float4*)(Aptr + k0 + 4);
        float4 b0 = *(const float4*)(Wptr + (size_t)k0 * N);
        float4 b1 = *(const float4*)(Wptr + (size_t)k0 * N + 4);
        __syncthreads();
        As[ak + 0][ar] = a0.x; As[ak + 1][ar] = a0.y;
        As[ak + 2][ar] = a0.z; As[ak + 3][ar] = a0.w;
        As[ak + 4][ar] = a1.x; As[ak + 5][ar] = a1.y;
        As[ak + 6][ar] = a1.z; As[ak + 7][ar] = a1.w;
        *(float4*)&Bs[bkr][bn8]     = b0;
        *(float4*)&Bs[bkr][bn8 + 4] = b1;
        __syncthreads();
#pragma unroll
        for (int k = 0; k < 16; k++) {
            float a[8], b[8];
            *(float4*)(a)     = *(const float4*)&As[k][ty * 8];
            *(float4*)(a + 4) = *(const float4*)&As[k][ty * 8 + 4];
            *(float4*)(b)     = *(const float4*)&Bs[k][tx * 8];
            *(float4*)(b + 4) = *(const float4*)&Bs[k][tx * 8 + 4];
#pragma unroll
            for (int i = 0; i < 8; i++)
#pragma unroll
                for (int j = 0; j < 8; j++)
                    acc[i][j] = fmaf(a[i], b[j], acc[i][j]);
        }
    }

#pragma unroll
    for (int i = 0; i < 8; i++) {
        const int m = bm + ty * 8 + i;
#pragma unroll
        for (int j = 0; j < 8; j += 4) {
            const int n = bn + tx * 8 + j;
            float4 v;
            v.x = acc[i][j + 0] + bias[n + 0];
            v.y = acc[i][j + 1] + bias[n + 1];
            v.z = acc[i][j + 2] + bias[n + 2];
            v.w = acc[i][j + 3] + bias[n + 3];
            if (relu) {
                v.x = fmaxf(v.x, 0.0f); v.y = fmaxf(v.y, 0.0f);
                v.z = fmaxf(v.z, 0.0f); v.w = fmaxf(v.w, 0.0f);
            }
            *(float4*)&C[(size_t)m * N + n] = v;
        }
    }
}

// ---------------------------------------------------------------------------
// Flash-style attention: per (b, h, q-tile of 64): online-softmax over
// 9 key tiles of 64. Head dim 256. O accumulator 4 rows x 16 cols / thread.
// ---------------------------------------------------------------------------
#define DPAD 264   // padded stride for 256-wide head-dim tiles (bank spread)
#define SPAD 68    // padded stride for 64-wide score tiles
#define ATT_SMEM_FLOATS (64 * DPAD * 2 + 64 * SPAD + 192)
#define ATT_SMEM_BYTES  (ATT_SMEM_FLOATS * sizeof(float))

__global__ __launch_bounds__(256, 1)
void attn_kernel(const float* __restrict__ Qg, const float* __restrict__ Kg,
                 const float* __restrict__ Vg, float* __restrict__ Xg)
{
    extern __shared__ float sm[];
    float* Qs   = sm;                    // [64][DPAD]
    float* KVs  = Qs + 64 * DPAD;        // [64][DPAD]
    float* Ss   = KVs + 64 * DPAD;       // [64][SPAD]
    float* mrow = Ss + 64 * SPAD;        // [64]
    float* lrow = mrow + 64;             // [64]
    float* rsc  = lrow + 64;             // [64]

    const int tid   = threadIdx.x;
    const int qt    = blockIdx.x;   // 0..7
    const int h     = blockIdx.y;   // 0..7
    const int b     = blockIdx.z;   // 0..15
    const int qbase  = b * LT + qt * 64;
    const int kvbase = b * LI;
    const int hcol   = h * HD;
    const int ty = tid >> 4, tx = tid & 15;
    const int ld_d = (tid & 63) << 2;   // 0..252 step 4
    const int ld_r = tid >> 6;          // 0..3

    // Load Q tile [64][256]
#pragma unroll
    for (int i = 0; i < 16; i++) {
        const int q = ld_r + i * 4;
        *(float4*)&Qs[q * DPAD + ld_d] =
            *(const float4*)&Qg[(size_t)(qbase + q) * HID + hcol + ld_d];
    }
    if (tid < 64) { mrow[tid] = -1e30f; lrow[tid] = 0.0f; }

    float o[4][16];
#pragma unroll
    for (int i = 0; i < 4; i++)
#pragma unroll
        for (int j = 0; j < 16; j++) o[i][j] = 0.0f;

    for (int st = 0; st < 9; st++) {
        __syncthreads();  // prev-iter PV reads of KVs/Ss complete (and Q load, iter 0)
        // Load K tile
#pragma unroll
        for (int i = 0; i < 16; i++) {
            const int kk = ld_r + i * 4;
            *(float4*)&KVs[kk * DPAD + ld_d] =
                *(const float4*)&Kg[(size_t)(kvbase + st * 64 + kk) * HID + hcol + ld_d];
        }
        __syncthreads();

        // S[64][64] = Q . K^T, 4x4 per thread
        float s[4][4];
#pragma unroll
        for (int i = 0; i < 4; i++)
#pragma unroll
            for (int j = 0; j < 4; j++) s[i][j] = 0.0f;

#pragma unroll 4
        for (int d = 0; d < HD; d += 4) {
            float qv[16], kv[16];
#pragma unroll
            for (int i = 0; i < 4; i++)
                *(float4*)(qv + 4 * i) = *(const float4*)&Qs[(ty * 4 + i) * DPAD + d];
#pragma unroll
            for (int j = 0; j < 4; j++)
                *(float4*)(kv + 4 * j) = *(const float4*)&KVs[(tx * 4 + j) * DPAD + d];
#pragma unroll
            for (int i = 0; i < 4; i++)
#pragma unroll
                for (int j = 0; j < 4; j++) {
                    s[i][j] = fmaf(qv[4 * i + 0], kv[4 * j + 0], s[i][j]);
                    s[i][j] = fmaf(qv[4 * i + 1], kv[4 * j + 1], s[i][j]);
                    s[i][j] = fmaf(qv[4 * i + 2], kv[4 * j + 2], s[i][j]);
                    s[i][j] = fmaf(qv[4 * i + 3], kv[4 * j + 3], s[i][j]);
                }
        }
#pragma unroll
        for (int i = 0; i < 4; i++)
#pragma unroll
            for (int j = 0; j < 4; j++)
                Ss[(ty * 4 + i) * SPAD + tx * 4 + j] = s[i][j] * 0.0625f;  // / sqrt(256)
        __syncthreads();

        // Online softmax row pass (64 threads, one row each)
        if (tid < 64) {
            float* srow = &Ss[tid * SPAD];
            const float mold = mrow[tid];
            float tm = mold;
#pragma unroll 8
            for (int k2 = 0; k2 < 64; k2++) tm = fmaxf(tm, srow[k2]);
            const float sc = __expf(mold - tm);
            float ps = 0.0f;
#pragma unroll 8
            for (int k2 = 0; k2 < 64; k2++) {
                const float e = __expf(srow[k2] - tm);
                srow[k2] = e;
                ps += e;
            }
            lrow[tid] = lrow[tid] * sc + ps;
            mrow[tid] = tm;
            rsc[tid]  = sc;
        }
        __syncthreads();

        // Load V tile (reuse KVs — S compute already synced past K reads)
#pragma unroll
        for (int i = 0; i < 16; i++) {
            const int kk = ld_r + i * 4;
            *(float4*)&KVs[kk * DPAD + ld_d] =
                *(const float4*)&Vg[(size_t)(kvbase + st * 64 + kk) * HID + hcol + ld_d];
        }
        __syncthreads();

        // Rescale O and accumulate O += P @ V
        float rs[4];
#pragma unroll
        for (int i = 0; i < 4; i++) rs[i] = rsc[ty * 4 + i];
#pragma unroll
        for (int i = 0; i < 4; i++)
#pragma unroll
            for (int j = 0; j < 16; j++) o[i][j] *= rs[i];

#pragma unroll 4
        for (int k2 = 0; k2 < 64; k2++) {
            float sv[4];
#pragma unroll
            for (int i = 0; i < 4; i++) sv[i] = Ss[(ty * 4 + i) * SPAD + k2];
            float vv[16];
#pragma unroll
            for (int j = 0; j < 4; j++)
                *(float4*)(vv + 4 * j) = *(const float4*)&KVs[k2 * DPAD + tx * 16 + j * 4];
#pragma unroll
            for (int i = 0; i < 4; i++)
#pragma unroll
                for (int j = 0; j < 16; j++)
                    o[i][j] = fmaf(sv[i], vv[j], o[i][j]);
        }
    }
    __syncthreads();

    // Finalize: O / l  ->  X[b, q, h*256 + d]
#pragma unroll
    for (int i = 0; i < 4; i++) {
        const float linv = 1.0f / lrow[ty * 4 + i];
#pragma unroll
        for (int j = 0; j < 4; j++) {
            float4 v;
            v.x = o[i][j * 4 + 0] * linv;
            v.y = o[i][j * 4 + 1] * linv;
            v.z = o[i][j * 4 + 2] * linv;
            v.w = o[i][j * 4 + 3] * linv;
            *(float4*)&Xg[(size_t)(qbase + ty * 4 + i) * HID + hcol + tx * 16 + j * 4] = v;
        }
    }
}

// ---------------------------------------------------------------------------
// Residual + LayerNorm epilogue: Y = LN(OUT + FF) * gamma + beta
// One block (256 threads) per row of 768.
// ---------------------------------------------------------------------------
__device__ __forceinline__ float block_sum(float x, float* red)
{
#pragma unroll
    for (int off = 16; off > 0; off >>= 1)
        x += __shfl_xor_sync(0xffffffffu, x, off);
    const int w = threadIdx.x >> 5;
    if ((threadIdx.x & 31) == 0) red[w] = x;
    __syncthreads();
    if (threadIdx.x < 32) {
        float y = (threadIdx.x < 8) ? red[threadIdx.x] : 0.0f;
#pragma unroll
        for (int off = 4; off > 0; off >>= 1)
            y += __shfl_xor_sync(0xffffffffu, y, off);
        if (threadIdx.x == 0) red[0] = y;
    }
    __syncthreads();
    const float r = red[0];
    __syncthreads();
    return r;
}

__global__ __launch_bounds__(256)
void ffln_kernel(const float* __restrict__ OUT, const float* __restrict__ FF,
                 const float* __restrict__ gamma, const float* __restrict__ beta,
                 float* __restrict__ Y)
{
    __shared__ float red[8];
    const int r = blockIdx.x;
    const int tid = threadIdx.x;
    float v[3];
#pragma unroll
    for (int i = 0; i < 3; i++) {
        const int idx = tid + i * 256;
        v[i] = OUT[(size_t)r * TD + idx] + FF[(size_t)r * TD + idx];
    }
    const float mu = block_sum(v[0] + v[1] + v[2], red) * (1.0f / 768.0f);
    const float d0 = v[0] - mu, d1 = v[1] - mu, d2 = v[2] - mu;
    const float var = block_sum(d0 * d0 + d1 * d1 + d2 * d2, red) * (1.0f / 768.0f);
    const float rstd = rsqrtf(var + 1e-5f);
#pragma unroll
    for (int i = 0; i < 3; i++) {
        const int idx = tid + i * 256;
        Y[(size_t)r * TD + idx] = (v[i] - mu) * rstd * gamma[idx] + beta[idx];
    }
}

// ---------------------------------------------------------------------------
extern "C" void kernel_launch(void* const* d_in, const int* in_sizes, int n_in,
                              void* d_out, int out_size)
{
    const float* text  = (const float*)d_in[0];
    const float* image = (const float*)d_in[1];
    const float* wq = (const float*)d_in[2];
    const float* bq = (const float*)d_in[3];
    const float* wk = (const float*)d_in[4];
    const float* bk = (const float*)d_in[5];
    const float* wv = (const float*)d_in[6];
    const float* bv = (const float*)d_in[7];
    const float* wr = (const float*)d_in[8];
    const float* br = (const float*)d_in[9];
    const float* w1 = (const float*)d_in[10];
    const float* b1 = (const float*)d_in[11];
    const float* w2 = (const float*)d_in[12];
    const float* b2 = (const float*)d_in[13];
    const float* gamma = (const float*)d_in[14];
    const float* beta  = (const float*)d_in[15];
    float* Y = (float*)d_out;

    float *Q, *K, *V, *X, *O, *H, *F;
    cudaGetSymbolAddress((void**)&Q, g_Q);
    cudaGetSymbolAddress((void**)&K, g_K);
    cudaGetSymbolAddress((void**)&V, g_V);
    cudaGetSymbolAddress((void**)&X, g_X);
    cudaGetSymbolAddress((void**)&O, g_O);
    cudaGetSymbolAddress((void**)&H, g_H);
    cudaGetSymbolAddress((void**)&F, g_F);

    cudaFuncSetAttribute(attn_kernel, cudaFuncAttributeMaxDynamicSharedMemorySize,
                         (int)ATT_SMEM_BYTES);

    // Projections
    sgemm_bias<<<dim3(HID / 128, (B_ * LT) / 128), 256>>>(text,  wq, bq, Q, B_ * LT, HID, TD, 0);
    sgemm_bias<<<dim3(HID / 128, (B_ * LI) / 128), 256>>>(image, wk, bk, K, B_ * LI, HID, ID, 0);
    sgemm_bias<<<dim3(HID / 128, (B_ * LI) / 128), 256>>>(image, wv, bv, V, B_ * LI, HID, ID, 0);

    // Attention
    attn_kernel<<<dim3(LT / 64, NH, B_), 256, ATT_SMEM_BYTES>>>(Q, K, V, X);

    // Output projection + FF
    sgemm_bias<<<dim3(TD / 128,  (B_ * LT) / 128), 256>>>(X, wr, br, O, B_ * LT, TD,  HID, 0);
    sgemm_bias<<<dim3(FFD / 128, (B_ * LT) / 128), 256>>>(O, w1, b1, H, B_ * LT, FFD, TD,  1);
    sgemm_bias<<<dim3(TD / 128,  (B_ * LT) / 128), 256>>>(H, w2, b2, F, B_ * LT, TD,  FFD, 0);

    // Residual + LayerNorm
    ffln_kernel<<<B_ * LT, 256>>>(O, F, gamma, beta, Y);
}

// round 3
// speedup vs baseline: 1.2287x; 1.2287x over previous
#include <cuda_runtime.h>
#include <cuda_bf16.h>
#include <cstdint>
#include <math.h>

#define B_   16
#define LT   512
#define LI   576
#define TD   768
#define ID   1024
#define HID  2048
#define NH   8
#define HD   256
#define FFD  128

// Scratch (device globals; no allocation allowed in kernel_launch)
__device__ float g_Q[B_ * LT * HID];
__device__ float g_K[B_ * LI * HID];
__device__ float g_V[B_ * LI * HID];
__device__ float g_X[B_ * LT * HID];
__device__ float g_O[B_ * LT * TD];
__device__ float g_H[B_ * LT * FFD];
__device__ float g_F[B_ * LT * TD];

// ===========================================================================
// bf16 3-term split GEMM on mma.sync (m16n8k16, f32 accum)
// C[M,N] = A[M,K] @ W[K,N] + bias (optional ReLU), fp32 in/out.
// Block tile 128x128, BK=32, 256 threads = 8 warps, warp tile 64x32.
// Double-buffered smem, padded stride 36 bf16 (72B) -> conflict-free LDS.
// Requires M%128==0, N%128==0, K%32==0.
// ===========================================================================
#define GPAD   36                  // bf16 elements per row (32 + 4 pad)
#define TILE_E (128 * GPAD)        // 4608 bf16 per tile
#define STG_E  (4 * TILE_E)        // AHI, ALO, BHI, BLO
#define GSMEM_BYTES (2 * STG_E * 2)  // 2 stages * bytes

__device__ __forceinline__ void hmma16816(float* c, const uint32_t* a, const uint32_t* b)
{
    asm volatile(
        "mma.sync.aligned.m16n8k16.row.col.f32.bf16.bf16.f32 "
        "{%0,%1,%2,%3}, {%4,%5,%6,%7}, {%8,%9}, {%0,%1,%2,%3};"
        : "+f"(c[0]), "+f"(c[1]), "+f"(c[2]), "+f"(c[3])
        : "r"(a[0]), "r"(a[1]), "r"(a[2]), "r"(a[3]), "r"(b[0]), "r"(b[1]));
}

__device__ __forceinline__ uint32_t pack_hi(float x0, float x1)
{
    __nv_bfloat162 h = __floats2bfloat162_rn(x0, x1);
    return *(uint32_t*)&h;
}
__device__ __forceinline__ uint32_t pack_lo(float x0, float x1, uint32_t hi)
{
    __nv_bfloat162 hv = *(__nv_bfloat162*)&hi;
    float r0 = x0 - __bfloat162float(hv.x);
    float r1 = x1 - __bfloat162float(hv.y);
    __nv_bfloat162 l = __floats2bfloat162_rn(r0, r1);
    return *(uint32_t*)&l;
}

__global__ __launch_bounds__(256)
void gemm_mma(const float* __restrict__ A, const float* __restrict__ W,
              const float* __restrict__ bias, float* __restrict__ C,
              int M, int N, int Kd, int relu)
{
    extern __shared__ __nv_bfloat16 smb[];

    const int tid  = threadIdx.x;
    const int wid  = tid >> 5;
    const int lane = tid & 31;
    const int bm   = blockIdx.y * 128;
    const int bn   = blockIdx.x * 128;

    const int wm = (wid >> 2) * 64;     // warp m offset (0 or 64)
    const int wn = (wid & 3) * 32;      // warp n offset (0,32,64,96)
    const int g  = lane >> 2;           // 0..7
    const int t2 = (lane & 3) * 2;      // 0,2,4,6

    // --- loader mappings ---
    const int a_row = tid >> 1;              // 0..127
    const int a_kb  = (tid & 1) * 16;        // 0 or 16
    const int b_k   = tid >> 5;              // 0..7 (+= 8 per pass)
    const int b_n   = lane;                  // 0..31 (+= 32 per group)

    float acc[4][4][4];
#pragma unroll
    for (int i = 0; i < 4; i++)
#pragma unroll
        for (int j = 0; j < 4; j++)
#pragma unroll
            for (int l = 0; l < 4; l++) acc[i][j][l] = 0.0f;

    const int NC = Kd >> 5;

    float4 apf[4];
    float  bpf[16];

    // ---- prologue: load chunk 0 ----
    {
        const float* Ap = A + (size_t)(bm + a_row) * Kd + a_kb;
#pragma unroll
        for (int i = 0; i < 4; i++) apf[i] = *(const float4*)(Ap + i * 4);
#pragma unroll
        for (int p = 0; p < 4; p++)
#pragma unroll
            for (int ng = 0; ng < 4; ng++)
                bpf[p * 4 + ng] = W[(size_t)(b_k + p * 8) * N + bn + ng * 32 + b_n];
    }
    // store chunk 0 -> stage 0
    {
        __nv_bfloat16* AHI = smb;
        __nv_bfloat16* ALO = smb + TILE_E;
        __nv_bfloat16* BHI = smb + 2 * TILE_E;
        __nv_bfloat16* BLO = smb + 3 * TILE_E;
#pragma unroll
        for (int i = 0; i < 4; i++) {
            const int kk = a_kb + i * 4;
            uint32_t h0 = pack_hi(apf[i].x, apf[i].y);
            uint32_t h1 = pack_hi(apf[i].z, apf[i].w);
            uint32_t l0 = pack_lo(apf[i].x, apf[i].y, h0);
            uint32_t l1 = pack_lo(apf[i].z, apf[i].w, h1);
            *(uint32_t*)&AHI[a_row * GPAD + kk]     = h0;
            *(uint32_t*)&AHI[a_row * GPAD + kk + 2] = h1;
            *(uint32_t*)&ALO[a_row * GPAD + kk]     = l0;
            *(uint32_t*)&ALO[a_row * GPAD + kk + 2] = l1;
        }
#pragma unroll
        for (int p = 0; p < 4; p++)
#pragma unroll
            for (int ng = 0; ng < 4; ng++) {
                const float x = bpf[p * 4 + ng];
                const int n = ng * 32 + b_n, k = b_k + p * 8;
                __nv_bfloat16 h = __float2bfloat16(x);
                BHI[n * GPAD + k] = h;
                BLO[n * GPAD + k] = __float2bfloat16(x - __bfloat162float(h));
            }
    }
    __syncthreads();

    for (int c = 0; c < NC; c++) {
        const int s = c & 1;
        const __nv_bfloat16* AHI = smb + s * STG_E;
        const __nv_bfloat16* ALO = AHI + TILE_E;
        const __nv_bfloat16* BHI = AHI + 2 * TILE_E;
        const __nv_bfloat16* BLO = AHI + 3 * TILE_E;

        // prefetch next chunk into regs
        if (c + 1 < NC) {
            const int k0 = (c + 1) << 5;
            const float* Ap = A + (size_t)(bm + a_row) * Kd + k0 + a_kb;
#pragma unroll
            for (int i = 0; i < 4; i++) apf[i] = *(const float4*)(Ap + i * 4);
#pragma unroll
            for (int p = 0; p < 4; p++)
#pragma unroll
                for (int ng = 0; ng < 4; ng++)
                    bpf[p * 4 + ng] = W[(size_t)(k0 + b_k + p * 8) * N + bn + ng * 32 + b_n];
        }

        // compute: 2 k16 steps
#pragma unroll
        for (int ks = 0; ks < 2; ks++) {
            const int kf = ks * 16 + t2;
            uint32_t ah[4][4], al[4][4], bh[4][2], bl[4][2];
#pragma unroll
            for (int mt = 0; mt < 4; mt++) {
                const int r0 = (wm + mt * 16 + g) * GPAD + kf;
                const int r1 = r0 + 8 * GPAD;
                ah[mt][0] = *(const uint32_t*)&AHI[r0];
                ah[mt][1] = *(const uint32_t*)&AHI[r1];
                ah[mt][2] = *(const uint32_t*)&AHI[r0 + 8];
                ah[mt][3] = *(const uint32_t*)&AHI[r1 + 8];
                al[mt][0] = *(const uint32_t*)&ALO[r0];
                al[mt][1] = *(const uint32_t*)&ALO[r1];
                al[mt][2] = *(const uint32_t*)&ALO[r0 + 8];
                al[mt][3] = *(const uint32_t*)&ALO[r1 + 8];
            }
#pragma unroll
            for (int nt = 0; nt < 4; nt++) {
                const int n0 = (wn + nt * 8 + g) * GPAD + kf;
                bh[nt][0] = *(const uint32_t*)&BHI[n0];
                bh[nt][1] = *(const uint32_t*)&BHI[n0 + 8];
                bl[nt][0] = *(const uint32_t*)&BLO[n0];
                bl[nt][1] = *(const uint32_t*)&BLO[n0 + 8];
            }
#pragma unroll
            for (int mt = 0; mt < 4; mt++)
#pragma unroll
                for (int nt = 0; nt < 4; nt++) {
                    hmma16816(acc[mt][nt], ah[mt], bh[nt]);
                    hmma16816(acc[mt][nt], ah[mt], bl[nt]);
                    hmma16816(acc[mt][nt], al[mt], bh[nt]);
                }
        }

        // store next chunk to other stage
        if (c + 1 < NC) {
            __nv_bfloat16* nAHI = smb + ((c + 1) & 1) * STG_E;
            __nv_bfloat16* nALO = nAHI + TILE_E;
            __nv_bfloat16* nBHI = nAHI + 2 * TILE_E;
            __nv_bfloat16* nBLO = nAHI + 3 * TILE_E;
#pragma unroll
            for (int i = 0; i < 4; i++) {
                const int kk = a_kb + i * 4;
                uint32_t h0 = pack_hi(apf[i].x, apf[i].y);
                uint32_t h1 = pack_hi(apf[i].z, apf[i].w);
                uint32_t l0 = pack_lo(apf[i].x, apf[i].y, h0);
                uint32_t l1 = pack_lo(apf[i].z, apf[i].w, h1);
                *(uint32_t*)&nAHI[a_row * GPAD + kk]     = h0;
                *(uint32_t*)&nAHI[a_row * GPAD + kk + 2] = h1;
                *(uint32_t*)&nALO[a_row * GPAD + kk]     = l0;
                *(uint32_t*)&nALO[a_row * GPAD + kk + 2] = l1;
            }
#pragma unroll
            for (int p = 0; p < 4; p++)
#pragma unroll
                for (int ng = 0; ng < 4; ng++) {
                    const float x = bpf[p * 4 + ng];
                    const int n = ng * 32 + b_n, k = b_k + p * 8;
                    __nv_bfloat16 h = __float2bfloat16(x);
                    nBHI[n * GPAD + k] = h;
                    nBLO[n * GPAD + k] = __float2bfloat16(x - __bfloat162float(h));
                }
        }
        __syncthreads();
    }

    // ---- epilogue ----
#pragma unroll
    for (int mt = 0; mt < 4; mt++) {
        const int r0 = bm + wm + mt * 16 + g;
#pragma unroll
        for (int nt = 0; nt < 4; nt++) {
            const int cn = bn + wn + nt * 8 + t2;
            float2 v0, v1;
            v0.x = acc[mt][nt][0] + bias[cn];
            v0.y = acc[mt][nt][1] + bias[cn + 1];
            v1.x = acc[mt][nt][2] + bias[cn];
            v1.y = acc[mt][nt][3] + bias[cn + 1];
            if (relu) {
                v0.x = fmaxf(v0.x, 0.0f); v0.y = fmaxf(v0.y, 0.0f);
                v1.x = fmaxf(v1.x, 0.0f); v1.y = fmaxf(v1.y, 0.0f);
            }
            *(float2*)&C[(size_t)r0 * N + cn]       = v0;
            *(float2*)&C[(size_t)(r0 + 8) * N + cn] = v1;
        }
    }
}

// ---------------------------------------------------------------------------
// Flash-style attention (SIMT fp32, unchanged from R1)
// ---------------------------------------------------------------------------
#define DPAD 264
#define SPAD 68
#define ATT_SMEM_FLOATS (64 * DPAD * 2 + 64 * SPAD + 192)
#define ATT_SMEM_BYTES  (ATT_SMEM_FLOATS * sizeof(float))

__global__ __launch_bounds__(256, 1)
void attn_kernel(const float* __restrict__ Qg, const float* __restrict__ Kg,
                 const float* __restrict__ Vg, float* __restrict__ Xg)
{
    extern __shared__ float sm[];
    float* Qs   = sm;
    float* KVs  = Qs + 64 * DPAD;
    float* Ss   = KVs + 64 * DPAD;
    float* mrow = Ss + 64 * SPAD;
    float* lrow = mrow + 64;
    float* rsc  = lrow + 64;

    const int tid   = threadIdx.x;
    const int qt    = blockIdx.x;
    const int h     = blockIdx.y;
    const int b     = blockIdx.z;
    const int qbase  = b * LT + qt * 64;
    const int kvbase = b * LI;
    const int hcol   = h * HD;
    const int ty = tid >> 4, tx = tid & 15;
    const int ld_d = (tid & 63) << 2;
    const int ld_r = tid >> 6;

#pragma unroll
    for (int i = 0; i < 16; i++) {
        const int q = ld_r + i * 4;
        *(float4*)&Qs[q * DPAD + ld_d] =
            *(const float4*)&Qg[(size_t)(qbase + q) * HID + hcol + ld_d];
    }
    if (tid < 64) { mrow[tid] = -1e30f; lrow[tid] = 0.0f; }

    float o[4][16];
#pragma unroll
    for (int i = 0; i < 4; i++)
#pragma unroll
        for (int j = 0; j < 16; j++) o[i][j] = 0.0f;

    for (int st = 0; st < 9; st++) {
        __syncthreads();
#pragma unroll
        for (int i = 0; i < 16; i++) {
            const int kk = ld_r + i * 4;
            *(float4*)&KVs[kk * DPAD + ld_d] =
                *(const float4*)&Kg[(size_t)(kvbase + st * 64 + kk) * HID + hcol + ld_d];
        }
        __syncthreads();

        float s[4][4];
#pragma unroll
        for (int i = 0; i < 4; i++)
#pragma unroll
            for (int j = 0; j < 4; j++) s[i][j] = 0.0f;

#pragma unroll 4
        for (int d = 0; d < HD; d += 4) {
            float qv[16], kv[16];
#pragma unroll
            for (int i = 0; i < 4; i++)
                *(float4*)(qv + 4 * i) = *(const float4*)&Qs[(ty * 4 + i) * DPAD + d];
#pragma unroll
            for (int j = 0; j < 4; j++)
                *(float4*)(kv + 4 * j) = *(const float4*)&KVs[(tx * 4 + j) * DPAD + d];
#pragma unroll
            for (int i = 0; i < 4; i++)
#pragma unroll
                for (int j = 0; j < 4; j++) {
                    s[i][j] = fmaf(qv[4 * i + 0], kv[4 * j + 0], s[i][j]);
                    s[i][j] = fmaf(qv[4 * i + 1], kv[4 * j + 1], s[i][j]);
                    s[i][j] = fmaf(qv[4 * i + 2], kv[4 * j + 2], s[i][j]);
                    s[i][j] = fmaf(qv[4 * i + 3], kv[4 * j + 3], s[i][j]);
                }
        }
#pragma unroll
        for (int i = 0; i < 4; i++)
#pragma unroll
            for (int j = 0; j < 4; j++)
                Ss[(ty * 4 + i) * SPAD + tx * 4 + j] = s[i][j] * 0.0625f;
        __syncthreads();

        if (tid < 64) {
            float* srow = &Ss[tid * SPAD];
            const float mold = mrow[tid];
            float tm = mold;
#pragma unroll 8
            for (int k2 = 0; k2 < 64; k2++) tm = fmaxf(tm, srow[k2]);
            const float sc = __expf(mold - tm);
            float ps = 0.0f;
#pragma unroll 8
            for (int k2 = 0; k2 < 64; k2++) {
                const float e = __expf(srow[k2] - tm);
                srow[k2] = e;
                ps += e;
            }
            lrow[tid] = lrow[tid] * sc + ps;
            mrow[tid] = tm;
            rsc[tid]  = sc;
        }
        __syncthreads();

#pragma unroll
        for (int i = 0; i < 16; i++) {
            const int kk = ld_r + i * 4;
            *(float4*)&KVs[kk * DPAD + ld_d] =
                *(const float4*)&Vg[(size_t)(kvbase + st * 64 + kk) * HID + hcol + ld_d];
        }
        __syncthreads();

        float rs[4];
#pragma unroll
        for (int i = 0; i < 4; i++) rs[i] = rsc[ty * 4 + i];
#pragma unroll
        for (int i = 0; i < 4; i++)
#pragma unroll
            for (int j = 0; j < 16; j++) o[i][j] *= rs[i];

#pragma unroll 4
        for (int k2 = 0; k2 < 64; k2++) {
            float sv[4];
#pragma unroll
            for (int i = 0; i < 4; i++) sv[i] = Ss[(ty * 4 + i) * SPAD + k2];
            float vv[16];
#pragma unroll
            for (int j = 0; j < 4; j++)
                *(float4*)(vv + 4 * j) = *(const float4*)&KVs[k2 * DPAD + tx * 16 + j * 4];
#pragma unroll
            for (int i = 0; i < 4; i++)
#pragma unroll
                for (int j = 0; j < 16; j++)
                    o[i][j] = fmaf(sv[i], vv[j], o[i][j]);
        }
    }
    __syncthreads();

#pragma unroll
    for (int i = 0; i < 4; i++) {
        const float linv = 1.0f / lrow[ty * 4 + i];
#pragma unroll
        for (int j = 0; j < 4; j++) {
            float4 v;
            v.x = o[i][j * 4 + 0] * linv;
            v.y = o[i][j * 4 + 1] * linv;
            v.z = o[i][j * 4 + 2] * linv;
            v.w = o[i][j * 4 + 3] * linv;
            *(float4*)&Xg[(size_t)(qbase + ty * 4 + i) * HID + hcol + tx * 16 + j * 4] = v;
        }
    }
}

// ---------------------------------------------------------------------------
// Residual + LayerNorm epilogue
// ---------------------------------------------------------------------------
__device__ __forceinline__ float block_sum(float x, float* red)
{
#pragma unroll
    for (int off = 16; off > 0; off >>= 1)
        x += __shfl_xor_sync(0xffffffffu, x, off);
    const int w = threadIdx.x >> 5;
    if ((threadIdx.x & 31) == 0) red[w] = x;
    __syncthreads();
    if (threadIdx.x < 32) {
        float y = (threadIdx.x < 8) ? red[threadIdx.x] : 0.0f;
#pragma unroll
        for (int off = 4; off > 0; off >>= 1)
            y += __shfl_xor_sync(0xffffffffu, y, off);
        if (threadIdx.x == 0) red[0] = y;
    }
    __syncthreads();
    const float r = red[0];
    __syncthreads();
    return r;
}

__global__ __launch_bounds__(256)
void ffln_kernel(const float* __restrict__ OUT, const float* __restrict__ FF,
                 const float* __restrict__ gamma, const float* __restrict__ beta,
                 float* __restrict__ Y)
{
    __shared__ float red[8];
    const int r = blockIdx.x;
    const int tid = threadIdx.x;
    float v[3];
#pragma unroll
    for (int i = 0; i < 3; i++) {
        const int idx = tid + i * 256;
        v[i] = OUT[(size_t)r * TD + idx] + FF[(size_t)r * TD + idx];
    }
    const float mu = block_sum(v[0] + v[1] + v[2], red) * (1.0f / 768.0f);
    const float d0 = v[0] - mu, d1 = v[1] - mu, d2 = v[2] - mu;
    const float var = block_sum(d0 * d0 + d1 * d1 + d2 * d2, red) * (1.0f / 768.0f);
    const float rstd = rsqrtf(var + 1e-5f);
#pragma unroll
    for (int i = 0; i < 3; i++) {
        const int idx = tid + i * 256;
        Y[(size_t)r * TD + idx] = (v[i] - mu) * rstd * gamma[idx] + beta[idx];
    }
}

// ---------------------------------------------------------------------------
extern "C" void kernel_launch(void* const* d_in, const int* in_sizes, int n_in,
                              void* d_out, int out_size)
{
    const float* text  = (const float*)d_in[0];
    const float* image = (const float*)d_in[1];
    const float* wq = (const float*)d_in[2];
    const float* bq = (const float*)d_in[3];
    const float* wk = (const float*)d_in[4];
    const float* bk = (const float*)d_in[5];
    const float* wv = (const float*)d_in[6];
    const float* bv = (const float*)d_in[7];
    const float* wr = (const float*)d_in[8];
    const float* br = (const float*)d_in[9];
    const float* w1 = (const float*)d_in[10];
    const float* b1 = (const float*)d_in[11];
    const float* w2 = (const float*)d_in[12];
    const float* b2 = (const float*)d_in[13];
    const float* gamma = (const float*)d_in[14];
    const float* beta  = (const float*)d_in[15];
    float* Y = (float*)d_out;

    float *Q, *K, *V, *X, *O, *H, *F;
    cudaGetSymbolAddress((void**)&Q, g_Q);
    cudaGetSymbolAddress((void**)&K, g_K);
    cudaGetSymbolAddress((void**)&V, g_V);
    cudaGetSymbolAddress((void**)&X, g_X);
    cudaGetSymbolAddress((void**)&O, g_O);
    cudaGetSymbolAddress((void**)&H, g_H);
    cudaGetSymbolAddress((void**)&F, g_F);

    cudaFuncSetAttribute(gemm_mma, cudaFuncAttributeMaxDynamicSharedMemorySize, GSMEM_BYTES);
    cudaFuncSetAttribute(attn_kernel, cudaFuncAttributeMaxDynamicSharedMemorySize,
                         (int)ATT_SMEM_BYTES);

    // Projections (tensor core bf16 3-term)
    gemm_mma<<<dim3(HID / 128, (B_ * LT) / 128), 256, GSMEM_BYTES>>>(text,  wq, bq, Q, B_ * LT, HID, TD, 0);
    gemm_mma<<<dim3(HID / 128, (B_ * LI) / 128), 256, GSMEM_BYTES>>>(image, wk, bk, K, B_ * LI, HID, ID, 0);
    gemm_mma<<<dim3(HID / 128, (B_ * LI) / 128), 256, GSMEM_BYTES>>>(image, wv, bv, V, B_ * LI, HID, ID, 0);

    // Attention (SIMT fp32)
    attn_kernel<<<dim3(LT / 64, NH, B_), 256, ATT_SMEM_BYTES>>>(Q, K, V, X);

    // Output projection + FF (tensor core)
    gemm_mma<<<dim3(TD / 128,  (B_ * LT) / 128), 256, GSMEM_BYTES>>>(X, wr, br, O, B_ * LT, TD,  HID, 0);
    gemm_mma<<<dim3(FFD / 128, (B_ * LT) / 128), 256, GSMEM_BYTES>>>(O, w1, b1, H, B_ * LT, FFD, TD,  1);
    gemm_mma<<<dim3(TD / 128,  (B_ * LT) / 128), 256, GSMEM_BYTES>>>(H, w2, b2, F, B_ * LT, TD,  FFD, 0);

    // Residual + LayerNorm
    ffln_kernel<<<B_ * LT, 256>>>(O, F, gamma, beta, Y);
}

// round 4
// speedup vs baseline: 2.7857x; 2.2673x over previous
#include <cuda_runtime.h>
#include <cuda_bf16.h>
#include <cstdint>
#include <math.h>

#define B_   16
#define LT   512
#define LI   576
#define TD   768
#define ID   1024
#define HID  2048
#define NH   8
#define HD   256
#define FFD  128

// Scratch (device globals)
__device__ __nv_bfloat16 g_Qh[B_ * LT * HID];
__device__ __nv_bfloat16 g_Ql[B_ * LT * HID];
__device__ __nv_bfloat16 g_Kh[B_ * LI * HID];
__device__ __nv_bfloat16 g_Kl[B_ * LI * HID];
__device__ __nv_bfloat16 g_Vh[B_ * LI * HID];
__device__ __nv_bfloat16 g_Vl[B_ * LI * HID];
__device__ float g_X[B_ * LT * HID];
__device__ float g_O[B_ * LT * TD];
__device__ float g_H[B_ * LT * FFD];
__device__ float g_F[B_ * LT * TD];

// ===========================================================================
// mma.sync helpers
// ===========================================================================
__device__ __forceinline__ void hmma16816(float* c, const uint32_t* a, const uint32_t* b)
{
    asm volatile(
        "mma.sync.aligned.m16n8k16.row.col.f32.bf16.bf16.f32 "
        "{%0,%1,%2,%3}, {%4,%5,%6,%7}, {%8,%9}, {%0,%1,%2,%3};"
        : "+f"(c[0]), "+f"(c[1]), "+f"(c[2]), "+f"(c[3])
        : "r"(a[0]), "r"(a[1]), "r"(a[2]), "r"(a[3]), "r"(b[0]), "r"(b[1]));
}
__device__ __forceinline__ void hmma2(float* c, const uint32_t* a, uint32_t b0, uint32_t b1)
{
    asm volatile(
        "mma.sync.aligned.m16n8k16.row.col.f32.bf16.bf16.f32 "
        "{%0,%1,%2,%3}, {%4,%5,%6,%7}, {%8,%9}, {%0,%1,%2,%3};"
        : "+f"(c[0]), "+f"(c[1]), "+f"(c[2]), "+f"(c[3])
        : "r"(a[0]), "r"(a[1]), "r"(a[2]), "r"(a[3]), "r"(b0), "r"(b1));
}
__device__ __forceinline__ void ldsm4(uint32_t* r, uint32_t addr)
{
    asm volatile("ldmatrix.sync.aligned.m8n8.x4.shared.b16 {%0,%1,%2,%3}, [%4];"
                 : "=r"(r[0]), "=r"(r[1]), "=r"(r[2]), "=r"(r[3]) : "r"(addr));
}
__device__ __forceinline__ void ldsm4t(uint32_t* r, uint32_t addr)
{
    asm volatile("ldmatrix.sync.aligned.m8n8.x4.trans.shared.b16 {%0,%1,%2,%3}, [%4];"
                 : "=r"(r[0]), "=r"(r[1]), "=r"(r[2]), "=r"(r[3]) : "r"(addr));
}
__device__ __forceinline__ uint32_t smem_u32(const void* p) {
    uint32_t a;
    asm("{ .reg .u64 t; cvta.to.shared.u64 t, %1; cvt.u32.u64 %0, t; }" : "=r"(a) : "l"(p));
    return a;
}
__device__ __forceinline__ uint32_t pack_hi(float x0, float x1)
{
    __nv_bfloat162 h = __floats2bfloat162_rn(x0, x1);
    return *(uint32_t*)&h;
}
__device__ __forceinline__ uint32_t pack_lo(float x0, float x1, uint32_t hi)
{
    __nv_bfloat162 hv = *(__nv_bfloat162*)&hi;
    float r0 = x0 - __bfloat162float(hv.x);
    float r1 = x1 - __bfloat162float(hv.y);
    __nv_bfloat162 l = __floats2bfloat162_rn(r0, r1);
    return *(uint32_t*)&l;
}

// ===========================================================================
// bf16 3-term split GEMM (m16n8k16). C = A @ W + bias.
// Outputs: optional fp32 Cf; optional bf16 hi/lo (Chi/Clo) with scale folded.
// Block 128x128, BK=32, 256 threads, warp tile 64x32.
// ===========================================================================
#define GPAD   36
#define TILE_E (128 * GPAD)
#define STG_E  (4 * TILE_E)
#define GSMEM_BYTES (2 * STG_E * 2)

__global__ __launch_bounds__(256)
void gemm_mma(const float* __restrict__ A, const float* __restrict__ W,
              const float* __restrict__ bias,
              float* __restrict__ Cf,
              __nv_bfloat16* __restrict__ Chi, __nv_bfloat16* __restrict__ Clo,
              int M, int N, int Kd, int relu, float oscale)
{
    extern __shared__ __nv_bfloat16 smb[];

    const int tid  = threadIdx.x;
    const int wid  = tid >> 5;
    const int lane = tid & 31;
    const int bm   = blockIdx.y * 128;
    const int bn   = blockIdx.x * 128;

    const int wm = (wid >> 2) * 64;
    const int wn = (wid & 3) * 32;
    const int g  = lane >> 2;
    const int t2 = (lane & 3) * 2;

    const int a_row = tid >> 1;
    const int a_kb  = (tid & 1) * 16;
    const int b_k   = tid >> 5;
    const int b_n   = lane;

    float acc[4][4][4];
#pragma unroll
    for (int i = 0; i < 4; i++)
#pragma unroll
        for (int j = 0; j < 4; j++)
#pragma unroll
            for (int l = 0; l < 4; l++) acc[i][j][l] = 0.0f;

    const int NC = Kd >> 5;
    float4 apf[4];
    float  bpf[16];

    {
        const float* Ap = A + (size_t)(bm + a_row) * Kd + a_kb;
#pragma unroll
        for (int i = 0; i < 4; i++) apf[i] = *(const float4*)(Ap + i * 4);
#pragma unroll
        for (int p = 0; p < 4; p++)
#pragma unroll
            for (int ng = 0; ng < 4; ng++)
                bpf[p * 4 + ng] = W[(size_t)(b_k + p * 8) * N + bn + ng * 32 + b_n];
    }
    {
        __nv_bfloat16* AHI = smb;
        __nv_bfloat16* ALO = smb + TILE_E;
        __nv_bfloat16* BHI = smb + 2 * TILE_E;
        __nv_bfloat16* BLO = smb + 3 * TILE_E;
#pragma unroll
        for (int i = 0; i < 4; i++) {
            const int kk = a_kb + i * 4;
            uint32_t h0 = pack_hi(apf[i].x, apf[i].y);
            uint32_t h1 = pack_hi(apf[i].z, apf[i].w);
            uint32_t l0 = pack_lo(apf[i].x, apf[i].y, h0);
            uint32_t l1 = pack_lo(apf[i].z, apf[i].w, h1);
            *(uint32_t*)&AHI[a_row * GPAD + kk]     = h0;
            *(uint32_t*)&AHI[a_row * GPAD + kk + 2] = h1;
            *(uint32_t*)&ALO[a_row * GPAD + kk]     = l0;
            *(uint32_t*)&ALO[a_row * GPAD + kk + 2] = l1;
        }
#pragma unroll
        for (int p = 0; p < 4; p++)
#pragma unroll
            for (int ng = 0; ng < 4; ng++) {
                const float x = bpf[p * 4 + ng];
                const int n = ng * 32 + b_n, k = b_k + p * 8;
                __nv_bfloat16 h = __float2bfloat16(x);
                BHI[n * GPAD + k] = h;
                BLO[n * GPAD + k] = __float2bfloat16(x - __bfloat162float(h));
            }
    }
    __syncthreads();

    for (int c = 0; c < NC; c++) {
        const int s = c & 1;
        const __nv_bfloat16* AHI = smb + s * STG_E;
        const __nv_bfloat16* ALO = AHI + TILE_E;
        const __nv_bfloat16* BHI = AHI + 2 * TILE_E;
        const __nv_bfloat16* BLO = AHI + 3 * TILE_E;

        if (c + 1 < NC) {
            const int k0 = (c + 1) << 5;
            const float* Ap = A + (size_t)(bm + a_row) * Kd + k0 + a_kb;
#pragma unroll
            for (int i = 0; i < 4; i++) apf[i] = *(const float4*)(Ap + i * 4);
#pragma unroll
            for (int p = 0; p < 4; p++)
#pragma unroll
                for (int ng = 0; ng < 4; ng++)
                    bpf[p * 4 + ng] = W[(size_t)(k0 + b_k + p * 8) * N + bn + ng * 32 + b_n];
        }

#pragma unroll
        for (int ks = 0; ks < 2; ks++) {
            const int kf = ks * 16 + t2;
            uint32_t ah[4][4], al[4][4], bh[4][2], bl[4][2];
#pragma unroll
            for (int mt = 0; mt < 4; mt++) {
                const int r0 = (wm + mt * 16 + g) * GPAD + kf;
                const int r1 = r0 + 8 * GPAD;
                ah[mt][0] = *(const uint32_t*)&AHI[r0];
                ah[mt][1] = *(const uint32_t*)&AHI[r1];
                ah[mt][2] = *(const uint32_t*)&AHI[r0 + 8];
                ah[mt][3] = *(const uint32_t*)&AHI[r1 + 8];
                al[mt][0] = *(const uint32_t*)&ALO[r0];
                al[mt][1] = *(const uint32_t*)&ALO[r1];
                al[mt][2] = *(const uint32_t*)&ALO[r0 + 8];
                al[mt][3] = *(const uint32_t*)&ALO[r1 + 8];
            }
#pragma unroll
            for (int nt = 0; nt < 4; nt++) {
                const int n0 = (wn + nt * 8 + g) * GPAD + kf;
                bh[nt][0] = *(const uint32_t*)&BHI[n0];
                bh[nt][1] = *(const uint32_t*)&BHI[n0 + 8];
                bl[nt][0] = *(const uint32_t*)&BLO[n0];
                bl[nt][1] = *(const uint32_t*)&BLO[n0 + 8];
            }
#pragma unroll
            for (int mt = 0; mt < 4; mt++)
#pragma unroll
                for (int nt = 0; nt < 4; nt++) {
                    hmma16816(acc[mt][nt], ah[mt], bh[nt]);
                    hmma16816(acc[mt][nt], ah[mt], bl[nt]);
                    hmma16816(acc[mt][nt], al[mt], bh[nt]);
                }
        }

        if (c + 1 < NC) {
            __nv_bfloat16* nAHI = smb + ((c + 1) & 1) * STG_E;
            __nv_bfloat16* nALO = nAHI + TILE_E;
            __nv_bfloat16* nBHI = nAHI + 2 * TILE_E;
            __nv_bfloat16* nBLO = nAHI + 3 * TILE_E;
#pragma unroll
            for (int i = 0; i < 4; i++) {
                const int kk = a_kb + i * 4;
                uint32_t h0 = pack_hi(apf[i].x, apf[i].y);
                uint32_t h1 = pack_hi(apf[i].z, apf[i].w);
                uint32_t l0 = pack_lo(apf[i].x, apf[i].y, h0);
                uint32_t l1 = pack_lo(apf[i].z, apf[i].w, h1);
                *(uint32_t*)&nAHI[a_row * GPAD + kk]     = h0;
                *(uint32_t*)&nAHI[a_row * GPAD + kk + 2] = h1;
                *(uint32_t*)&nALO[a_row * GPAD + kk]     = l0;
                *(uint32_t*)&nALO[a_row * GPAD + kk + 2] = l1;
            }
#pragma unroll
            for (int p = 0; p < 4; p++)
#pragma unroll
                for (int ng = 0; ng < 4; ng++) {
                    const float x = bpf[p * 4 + ng];
                    const int n = ng * 32 + b_n, k = b_k + p * 8;
                    __nv_bfloat16 h = __float2bfloat16(x);
                    nBHI[n * GPAD + k] = h;
                    nBLO[n * GPAD + k] = __float2bfloat16(x - __bfloat162float(h));
                }
        }
        __syncthreads();
    }

    // ---- epilogue ----
#pragma unroll
    for (int mt = 0; mt < 4; mt++) {
        const int r0 = bm + wm + mt * 16 + g;
#pragma unroll
        for (int nt = 0; nt < 4; nt++) {
            const int cn = bn + wn + nt * 8 + t2;
            float2 v0, v1;
            v0.x = acc[mt][nt][0] + bias[cn];
            v0.y = acc[mt][nt][1] + bias[cn + 1];
            v1.x = acc[mt][nt][2] + bias[cn];
            v1.y = acc[mt][nt][3] + bias[cn + 1];
            if (relu) {
                v0.x = fmaxf(v0.x, 0.0f); v0.y = fmaxf(v0.y, 0.0f);
                v1.x = fmaxf(v1.x, 0.0f); v1.y = fmaxf(v1.y, 0.0f);
            }
            v0.x *= oscale; v0.y *= oscale; v1.x *= oscale; v1.y *= oscale;
            if (Cf) {
                *(float2*)&Cf[(size_t)r0 * N + cn]       = v0;
                *(float2*)&Cf[(size_t)(r0 + 8) * N + cn] = v1;
            }
            if (Chi) {
                uint32_t h0 = pack_hi(v0.x, v0.y);
                uint32_t h1 = pack_hi(v1.x, v1.y);
                *(uint32_t*)&Chi[(size_t)r0 * N + cn]       = h0;
                *(uint32_t*)&Chi[(size_t)(r0 + 8) * N + cn] = h1;
                *(uint32_t*)&Clo[(size_t)r0 * N + cn]       = pack_lo(v0.x, v0.y, h0);
                *(uint32_t*)&Clo[(size_t)(r0 + 8) * N + cn] = pack_lo(v1.x, v1.y, h1);
            }
        }
    }
}

// ===========================================================================
// HMMA flash attention. q-tile 128 (8 warps x 16 rows), kv-tile 32, 18 iters.
// 3-term bf16 split for both QK^T and PV. Warp-local online softmax.
// ===========================================================================
#define ASD 264
#define ASMEM_BYTES ((2 * 128 + 4 * 32) * ASD * 2)   // 202752

__global__ __launch_bounds__(256, 1)
void attn2(const __nv_bfloat16* __restrict__ Qh, const __nv_bfloat16* __restrict__ Ql,
           const __nv_bfloat16* __restrict__ Kh, const __nv_bfloat16* __restrict__ Kl,
           const __nv_bfloat16* __restrict__ Vh, const __nv_bfloat16* __restrict__ Vl,
           float* __restrict__ Xg)
{
    extern __shared__ __nv_bfloat16 sm2[];
    __nv_bfloat16* sQh = sm2;
    __nv_bfloat16* sQl = sQh + 128 * ASD;
    __nv_bfloat16* sKh = sQl + 128 * ASD;
    __nv_bfloat16* sKl = sKh + 32 * ASD;
    __nv_bfloat16* sVh = sKl + 32 * ASD;
    __nv_bfloat16* sVl = sVh + 32 * ASD;

    const int tid  = threadIdx.x;
    const int wid  = tid >> 5;
    const int lane = tid & 31;
    const int qt = blockIdx.x, h = blockIdx.y, b = blockIdx.z;
    const int qrow0  = b * LT + qt * 128;
    const int kvrow0 = b * LI;
    const int hcol   = h * HD;

    // load Q tile (128 x 256, hi+lo)
#pragma unroll
    for (int i = 0; i < 16; i++) {
        const int gi = tid + i * 256;
        const int r = gi >> 5, c8 = (gi & 31) << 3;
        const size_t ga = (size_t)(qrow0 + r) * HID + hcol + c8;
        *(float4*)&sQh[r * ASD + c8] = *(const float4*)&Qh[ga];
        *(float4*)&sQl[r * ASD + c8] = *(const float4*)&Ql[ga];
    }

    // per-thread ldmatrix base addresses
    const int lrow = lane & 15, lc8 = (lane >> 4) << 3;
    const uint32_t aQh = smem_u32(sQh) + (uint32_t)(((wid * 16 + lrow) * ASD + lc8) * 2);
    const uint32_t aQl = smem_u32(sQl) + (uint32_t)(((wid * 16 + lrow) * ASD + lc8) * 2);
    const uint32_t aKh = smem_u32(sKh) + (uint32_t)((lrow * ASD + lc8) * 2);
    const uint32_t aKl = smem_u32(sKl) + (uint32_t)((lrow * ASD + lc8) * 2);
    const uint32_t aVh = smem_u32(sVh) + (uint32_t)((lrow * ASD + lc8) * 2);
    const uint32_t aVl = smem_u32(sVl) + (uint32_t)((lrow * ASD + lc8) * 2);

    float o[32][4];
#pragma unroll
    for (int i = 0; i < 32; i++)
#pragma unroll
        for (int j = 0; j < 4; j++) o[i][j] = 0.0f;
    float m0 = -1e30f, m1 = -1e30f, l0 = 0.0f, l1 = 0.0f;

    for (int st = 0; st < 18; st++) {
        __syncthreads();
        // load K/V tile (32 x 256, hi+lo each)
#pragma unroll
        for (int i = 0; i < 4; i++) {
            const int gi = tid + i * 256;
            const int r = gi >> 5, c8 = (gi & 31) << 3;
            const size_t ga = (size_t)(kvrow0 + st * 32 + r) * HID + hcol + c8;
            *(float4*)&sKh[r * ASD + c8] = *(const float4*)&Kh[ga];
            *(float4*)&sKl[r * ASD + c8] = *(const float4*)&Kl[ga];
            *(float4*)&sVh[r * ASD + c8] = *(const float4*)&Vh[ga];
            *(float4*)&sVl[r * ASD + c8] = *(const float4*)&Vl[ga];
        }
        __syncthreads();

        // ---- S = Q K^T (scaled; scale folded into Q) ----
        float s[4][4];
#pragma unroll
        for (int i = 0; i < 4; i++)
#pragma unroll
            for (int j = 0; j < 4; j++) s[i][j] = 0.0f;

#pragma unroll
        for (int dc = 0; dc < 16; dc++) {
            uint32_t qh[4], ql[4], kh[4], kl[4];
            ldsm4(qh, aQh + dc * 32);
            ldsm4(ql, aQl + dc * 32);
            ldsm4(kh, aKh + dc * 32);
            ldsm4(kl, aKl + dc * 32);
            hmma2(s[0], qh, kh[0], kh[2]);
            hmma2(s[1], qh, kh[1], kh[3]);
            hmma2(s[0], qh, kl[0], kl[2]);
            hmma2(s[1], qh, kl[1], kl[3]);
            hmma2(s[0], ql, kh[0], kh[2]);
            hmma2(s[1], ql, kh[1], kh[3]);
            ldsm4(kh, aKh + 16 * ASD * 2 + dc * 32);
            ldsm4(kl, aKl + 16 * ASD * 2 + dc * 32);
            hmma2(s[2], qh, kh[0], kh[2]);
            hmma2(s[3], qh, kh[1], kh[3]);
            hmma2(s[2], qh, kl[0], kl[2]);
            hmma2(s[3], qh, kl[1], kl[3]);
            hmma2(s[2], ql, kh[0], kh[2]);
            hmma2(s[3], ql, kh[1], kh[3]);
        }

        // ---- online softmax (rows g and g+8 of this warp) ----
        float rm0 = s[0][0], rm1 = s[0][2];
#pragma unroll
        for (int nt = 0; nt < 4; nt++) {
            rm0 = fmaxf(rm0, fmaxf(s[nt][0], s[nt][1]));
            rm1 = fmaxf(rm1, fmaxf(s[nt][2], s[nt][3]));
        }
        rm0 = fmaxf(rm0, __shfl_xor_sync(0xffffffffu, rm0, 1));
        rm0 = fmaxf(rm0, __shfl_xor_sync(0xffffffffu, rm0, 2));
        rm1 = fmaxf(rm1, __shfl_xor_sync(0xffffffffu, rm1, 1));
        rm1 = fmaxf(rm1, __shfl_xor_sync(0xffffffffu, rm1, 2));
        const float nm0 = fmaxf(m0, rm0), nm1 = fmaxf(m1, rm1);
        const float sc0 = __expf(m0 - nm0), sc1 = __expf(m1 - nm1);
        m0 = nm0; m1 = nm1;
        float ps0 = 0.0f, ps1 = 0.0f;
#pragma unroll
        for (int nt = 0; nt < 4; nt++) {
            s[nt][0] = __expf(s[nt][0] - nm0); ps0 += s[nt][0];
            s[nt][1] = __expf(s[nt][1] - nm0); ps0 += s[nt][1];
            s[nt][2] = __expf(s[nt][2] - nm1); ps1 += s[nt][2];
            s[nt][3] = __expf(s[nt][3] - nm1); ps1 += s[nt][3];
        }
        ps0 += __shfl_xor_sync(0xffffffffu, ps0, 1);
        ps0 += __shfl_xor_sync(0xffffffffu, ps0, 2);
        ps1 += __shfl_xor_sync(0xffffffffu, ps1, 1);
        ps1 += __shfl_xor_sync(0xffffffffu, ps1, 2);
        l0 = l0 * sc0 + ps0;
        l1 = l1 * sc1 + ps1;

        // rescale O
#pragma unroll
        for (int nt = 0; nt < 32; nt++) {
            o[nt][0] *= sc0; o[nt][1] *= sc0;
            o[nt][2] *= sc1; o[nt][3] *= sc1;
        }

        // ---- O += P V ----
#pragma unroll
        for (int kc = 0; kc < 2; kc++) {
            uint32_t pah[4], pal[4];
            const float* f0 = s[2 * kc];
            const float* f1 = s[2 * kc + 1];
            pah[0] = pack_hi(f0[0], f0[1]); pal[0] = pack_lo(f0[0], f0[1], pah[0]);
            pah[1] = pack_hi(f0[2], f0[3]); pal[1] = pack_lo(f0[2], f0[3], pah[1]);
            pah[2] = pack_hi(f1[0], f1[1]); pal[2] = pack_lo(f1[0], f1[1], pah[2]);
            pah[3] = pack_hi(f1[2], f1[3]); pal[3] = pack_lo(f1[2], f1[3], pah[3]);
            const uint32_t vbase = (uint32_t)(kc * 16 * ASD * 2);
#pragma unroll
            for (int nd = 0; nd < 16; nd++) {
                uint32_t vh[4], vl[4];
                ldsm4t(vh, aVh + vbase + nd * 32);
                ldsm4t(vl, aVl + vbase + nd * 32);
                hmma2(o[2 * nd],     pah, vh[0], vh[1]);
                hmma2(o[2 * nd + 1], pah, vh[2], vh[3]);
                hmma2(o[2 * nd],     pah, vl[0], vl[1]);
                hmma2(o[2 * nd + 1], pah, vl[2], vl[3]);
                hmma2(o[2 * nd],     pal, vh[0], vh[1]);
                hmma2(o[2 * nd + 1], pal, vh[2], vh[3]);
            }
        }
    }

    // ---- finalize ----
    const float i0 = 1.0f / l0, i1 = 1.0f / l1;
    const int g = lane >> 2, t2 = (lane & 3) * 2;
    const int r0 = qrow0 + wid * 16 + g;
#pragma unroll
    for (int nt = 0; nt < 32; nt++) {
        const int col = hcol + nt * 8 + t2;
        float2 v0 = {o[nt][0] * i0, o[nt][1] * i0};
        float2 v1 = {o[nt][2] * i1, o[nt][3] * i1};
        *(float2*)&Xg[(size_t)r0 * HID + col]       = v0;
        *(float2*)&Xg[(size_t)(r0 + 8) * HID + col] = v1;
    }
}

// ---------------------------------------------------------------------------
// Residual + LayerNorm epilogue
// ---------------------------------------------------------------------------
__device__ __forceinline__ float block_sum(float x, float* red)
{
#pragma unroll
    for (int off = 16; off > 0; off >>= 1)
        x += __shfl_xor_sync(0xffffffffu, x, off);
    const int w = threadIdx.x >> 5;
    if ((threadIdx.x & 31) == 0) red[w] = x;
    __syncthreads();
    if (threadIdx.x < 32) {
        float y = (threadIdx.x < 8) ? red[threadIdx.x] : 0.0f;
#pragma unroll
        for (int off = 4; off > 0; off >>= 1)
            y += __shfl_xor_sync(0xffffffffu, y, off);
        if (threadIdx.x == 0) red[0] = y;
    }
    __syncthreads();
    const float r = red[0];
    __syncthreads();
    return r;
}

__global__ __launch_bounds__(256)
void ffln_kernel(const float* __restrict__ OUT, const float* __restrict__ FF,
                 const float* __restrict__ gamma, const float* __restrict__ beta,
                 float* __restrict__ Y)
{
    __shared__ float red[8];
    const int r = blockIdx.x;
    const int tid = threadIdx.x;
    float v[3];
#pragma unroll
    for (int i = 0; i < 3; i++) {
        const int idx = tid + i * 256;
        v[i] = OUT[(size_t)r * TD + idx] + FF[(size_t)r * TD + idx];
    }
    const float mu = block_sum(v[0] + v[1] + v[2], red) * (1.0f / 768.0f);
    const float d0 = v[0] - mu, d1 = v[1] - mu, d2 = v[2] - mu;
    const float var = block_sum(d0 * d0 + d1 * d1 + d2 * d2, red) * (1.0f / 768.0f);
    const float rstd = rsqrtf(var + 1e-5f);
#pragma unroll
    for (int i = 0; i < 3; i++) {
        const int idx = tid + i * 256;
        Y[(size_t)r * TD + idx] = (v[i] - mu) * rstd * gamma[idx] + beta[idx];
    }
}

// ---------------------------------------------------------------------------
extern "C" void kernel_launch(void* const* d_in, const int* in_sizes, int n_in,
                              void* d_out, int out_size)
{
    const float* text  = (const float*)d_in[0];
    const float* image = (const float*)d_in[1];
    const float* wq = (const float*)d_in[2];
    const float* bq = (const float*)d_in[3];
    const float* wk = (const float*)d_in[4];
    const float* bk = (const float*)d_in[5];
    const float* wv = (const float*)d_in[6];
    const float* bv = (const float*)d_in[7];
    const float* wr = (const float*)d_in[8];
    const float* br = (const float*)d_in[9];
    const float* w1 = (const float*)d_in[10];
    const float* b1 = (const float*)d_in[11];
    const float* w2 = (const float*)d_in[12];
    const float* b2 = (const float*)d_in[13];
    const float* gamma = (const float*)d_in[14];
    const float* beta  = (const float*)d_in[15];
    float* Y = (float*)d_out;

    __nv_bfloat16 *Qh, *Ql, *Kh, *Kl, *Vh, *Vl;
    float *X, *O, *H, *F;
    cudaGetSymbolAddress((void**)&Qh, g_Qh);
    cudaGetSymbolAddress((void**)&Ql, g_Ql);
    cudaGetSymbolAddress((void**)&Kh, g_Kh);
    cudaGetSymbolAddress((void**)&Kl, g_Kl);
    cudaGetSymbolAddress((void**)&Vh, g_Vh);
    cudaGetSymbolAddress((void**)&Vl, g_Vl);
    cudaGetSymbolAddress((void**)&X, g_X);
    cudaGetSymbolAddress((void**)&O, g_O);
    cudaGetSymbolAddress((void**)&H, g_H);
    cudaGetSymbolAddress((void**)&F, g_F);

    cudaFuncSetAttribute(gemm_mma, cudaFuncAttributeMaxDynamicSharedMemorySize, GSMEM_BYTES);
    cudaFuncSetAttribute(attn2, cudaFuncAttributeMaxDynamicSharedMemorySize, ASMEM_BYTES);

    // Projections -> bf16 hi/lo (Q scaled by 1/sqrt(256))
    gemm_mma<<<dim3(HID / 128, (B_ * LT) / 128), 256, GSMEM_BYTES>>>(
        text,  wq, bq, nullptr, Qh, Ql, B_ * LT, HID, TD, 0, 0.0625f);
    gemm_mma<<<dim3(HID / 128, (B_ * LI) / 128), 256, GSMEM_BYTES>>>(
        image, wk, bk, nullptr, Kh, Kl, B_ * LI, HID, ID, 0, 1.0f);
    gemm_mma<<<dim3(HID / 128, (B_ * LI) / 128), 256, GSMEM_BYTES>>>(
        image, wv, bv, nullptr, Vh, Vl, B_ * LI, HID, ID, 0, 1.0f);

    // Attention (tensor core)
    attn2<<<dim3(LT / 128, NH, B_), 256, ASMEM_BYTES>>>(Qh, Ql, Kh, Kl, Vh, Vl, X);

    // Output projection + FF
    gemm_mma<<<dim3(TD / 128,  (B_ * LT) / 128), 256, GSMEM_BYTES>>>(
        X, wr, br, O, nullptr, nullptr, B_ * LT, TD,  HID, 0, 1.0f);
    gemm_mma<<<dim3(FFD / 128, (B_ * LT) / 128), 256, GSMEM_BYTES>>>(
        O, w1, b1, H, nullptr, nullptr, B_ * LT, FFD, TD,  1, 1.0f);
    gemm_mma<<<dim3(TD / 128,  (B_ * LT) / 128), 256, GSMEM_BYTES>>>(
        H, w2, b2, F, nullptr, nullptr, B_ * LT, TD,  FFD, 0, 1.0f);

    // Residual + LayerNorm
    ffln_kernel<<<B_ * LT, 256>>>(O, F, gamma, beta, Y);
}

// round 5
// speedup vs baseline: 3.1188x; 1.1196x over previous
#include <cuda_runtime.h>
#include <cuda_bf16.h>
#include <cstdint>
#include <math.h>

#define B_   16
#define LT   512
#define LI   576
#define TD   768
#define ID   1024
#define HID  2048
#define NH   8
#define HD   256
#define FFD  128

typedef __nv_bfloat16 bf16;

// ---- scratch (device globals; zero-init, no runtime allocation) ----
__device__ bf16 g_th[B_ * LT * TD],  g_tl[B_ * LT * TD];    // text hi/lo
__device__ bf16 g_ih[B_ * LI * ID],  g_il[B_ * LI * ID];    // image hi/lo
__device__ bf16 g_wqh[HID * TD],  g_wql[HID * TD];          // wq^T [N=HID,K=TD]
__device__ bf16 g_wkh[HID * ID],  g_wkl[HID * ID];
__device__ bf16 g_wvh[HID * ID],  g_wvl[HID * ID];
__device__ bf16 g_wrh[TD * HID],  g_wrl[TD * HID];          // wr^T [TD,HID]
__device__ bf16 g_w1h[FFD * TD],  g_w1l[FFD * TD];
__device__ bf16 g_w2h[TD * FFD],  g_w2l[TD * FFD];
__device__ bf16 g_Qh[B_ * LT * HID], g_Ql[B_ * LT * HID];
__device__ bf16 g_Kh[B_ * LI * HID], g_Kl[B_ * LI * HID];
__device__ bf16 g_Vh[B_ * LI * HID], g_Vl[B_ * LI * HID];
__device__ bf16 g_Xh[B_ * LT * HID], g_Xl[B_ * LT * HID];
__device__ bf16 g_Oh[B_ * LT * TD],  g_Ol[B_ * LT * TD];
__device__ bf16 g_Hh[B_ * LT * FFD], g_Hl[B_ * LT * FFD];
__device__ float g_O[B_ * LT * TD];
__device__ float g_F[B_ * LT * TD];

// ===========================================================================
// helpers
// ===========================================================================
__device__ __forceinline__ void hmma2(float* c, const uint32_t* a, uint32_t b0, uint32_t b1)
{
    asm volatile(
        "mma.sync.aligned.m16n8k16.row.col.f32.bf16.bf16.f32 "
        "{%0,%1,%2,%3}, {%4,%5,%6,%7}, {%8,%9}, {%0,%1,%2,%3};"
        : "+f"(c[0]), "+f"(c[1]), "+f"(c[2]), "+f"(c[3])
        : "r"(a[0]), "r"(a[1]), "r"(a[2]), "r"(a[3]), "r"(b0), "r"(b1));
}
__device__ __forceinline__ void ldsm4(uint32_t* r, uint32_t addr)
{
    asm volatile("ldmatrix.sync.aligned.m8n8.x4.shared.b16 {%0,%1,%2,%3}, [%4];"
                 : "=r"(r[0]), "=r"(r[1]), "=r"(r[2]), "=r"(r[3]) : "r"(addr));
}
__device__ __forceinline__ void ldsm4t(uint32_t* r, uint32_t addr)
{
    asm volatile("ldmatrix.sync.aligned.m8n8.x4.trans.shared.b16 {%0,%1,%2,%3}, [%4];"
                 : "=r"(r[0]), "=r"(r[1]), "=r"(r[2]), "=r"(r[3]) : "r"(addr));
}
__device__ __forceinline__ uint32_t smem_u32(const void* p) {
    uint32_t a;
    asm("{ .reg .u64 t; cvta.to.shared.u64 t, %1; cvt.u32.u64 %0, t; }" : "=r"(a) : "l"(p));
    return a;
}
__device__ __forceinline__ uint32_t pack_hi(float x0, float x1)
{
    __nv_bfloat162 h = __floats2bfloat162_rn(x0, x1);
    return *(uint32_t*)&h;
}
__device__ __forceinline__ uint32_t pack_lo(float x0, float x1, uint32_t hi)
{
    __nv_bfloat162 hv = *(__nv_bfloat162*)&hi;
    float r0 = x0 - __bfloat162float(hv.x);
    float r1 = x1 - __bfloat162float(hv.y);
    __nv_bfloat162 l = __floats2bfloat162_rn(r0, r1);
    return *(uint32_t*)&l;
}
#define CP16(s, g) \
    asm volatile("cp.async.cg.shared.global [%0], [%1], 16;" :: "r"(s), "l"(g) : "memory")
#define CPCOMMIT() asm volatile("cp.async.commit_group;" ::: "memory")
#define CPWAIT(n)  asm volatile("cp.async.wait_group %0;" :: "n"(n) : "memory")

// ===========================================================================
// Pre-passes: split fp32 -> bf16 hi/lo; weight transpose+split
// ===========================================================================
__global__ __launch_bounds__(256)
void split_act(const float* __restrict__ X, bf16* __restrict__ H, bf16* __restrict__ L)
{
    const int i = (blockIdx.x * 256 + threadIdx.x) * 4;
    float4 v = *(const float4*)&X[i];
    uint32_t h0 = pack_hi(v.x, v.y), h1 = pack_hi(v.z, v.w);
    uint32_t l0 = pack_lo(v.x, v.y, h0), l1 = pack_lo(v.z, v.w, h1);
    *(uint32_t*)&H[i]     = h0; *(uint32_t*)&H[i + 2] = h1;
    *(uint32_t*)&L[i]     = l0; *(uint32_t*)&L[i + 2] = l1;
}

// W[K,N] fp32 -> Wt hi/lo [N,K] bf16
__global__ __launch_bounds__(256)
void tsplit(const float* __restrict__ W, bf16* __restrict__ Th, bf16* __restrict__ Tl,
            int K, int N)
{
    __shared__ float t[32][33];
    const int n0 = blockIdx.x * 32, k0 = blockIdx.y * 32;
    const int tx = threadIdx.x & 31, ty4 = (threadIdx.x >> 5) * 4;
#pragma unroll
    for (int i = 0; i < 4; i++)
        t[ty4 + i][tx] = W[(size_t)(k0 + ty4 + i) * N + n0 + tx];
    __syncthreads();
#pragma unroll
    for (int i = 0; i < 4; i++) {
        const float x = t[tx][ty4 + i];
        bf16 h = __float2bfloat16(x);
        const size_t o = (size_t)(n0 + ty4 + i) * K + k0 + tx;
        Th[o] = h;
        Tl[o] = __float2bfloat16(x - __bfloat162float(h));
    }
}

// ===========================================================================
// bf16 GEMM: C[M,N] = (Ah+Al)[M,K] @ (Bh+Bl)[N,K]^T + bias (3-term)
// cp.async double-buffer, ldmatrix fragments, 128x128 block, BK=32.
// ===========================================================================
#define KPAD 40
#define CB   (128 * KPAD * 2)       // bytes per component tile (10240)
#define STGB (4 * CB)               // stage bytes (40960)
#define GSMEM_BYTES (2 * STGB)      // 81920

__global__ __launch_bounds__(256, 1)
void gemm_bf16(const bf16* __restrict__ Ah, const bf16* __restrict__ Al,
               const bf16* __restrict__ Bh, const bf16* __restrict__ Bl,
               const float* __restrict__ bias,
               float* __restrict__ Cf, bf16* __restrict__ Chi, bf16* __restrict__ Clo,
               int M, int N, int Kd, int relu, float oscale)
{
    extern __shared__ char smc[];
    const uint32_t sbase = smem_u32(smc);

    const int tid  = threadIdx.x;
    const int wid  = tid >> 5;
    const int lane = tid & 31;
    const int bm   = blockIdx.y * 128;
    const int bn   = blockIdx.x * 128;
    const int wm = (wid >> 2) * 64;
    const int wn = (wid & 3) * 32;

    const int NC = Kd >> 5;

    float acc[4][4][4];
#pragma unroll
    for (int i = 0; i < 4; i++)
#pragma unroll
        for (int j = 0; j < 4; j++)
#pragma unroll
            for (int l = 0; l < 4; l++) acc[i][j][l] = 0.0f;

    // issue chunk c into stage c&1
    auto issue = [&](int c) {
        const uint32_t sb = sbase + (uint32_t)((c & 1) * STGB);
        const int k0 = c << 5;
#pragma unroll
        for (int i = 0; i < 2; i++) {
            const int t = tid + i * 256;
            const int row = t >> 2, sg = (t & 3) << 3;
            const uint32_t so = (uint32_t)((row * KPAD + sg) * 2);
            const size_t ga = (size_t)(bm + row) * Kd + k0 + sg;
            const size_t gb = (size_t)(bn + row) * Kd + k0 + sg;
            CP16(sb + so,          Ah + ga);
            CP16(sb + CB + so,     Al + ga);
            CP16(sb + 2 * CB + so, Bh + gb);
            CP16(sb + 3 * CB + so, Bl + gb);
        }
        CPCOMMIT();
    };

    issue(0);

    const int lrow = lane & 15, lc8 = (lane >> 4) << 3;

    for (int c = 0; c < NC; c++) {
        if (c + 1 < NC) { issue(c + 1); CPWAIT(1); } else { CPWAIT(0); }
        __syncthreads();

        const uint32_t sb = sbase + (uint32_t)((c & 1) * STGB);
#pragma unroll
        for (int ks = 0; ks < 2; ks++) {
            const int kf = ks * 16 + lc8;
            uint32_t ah[4][4], al[4][4], bh[2][4], bl[2][4];
#pragma unroll
            for (int mt = 0; mt < 4; mt++) {
                const uint32_t ro = (uint32_t)(((wm + mt * 16 + lrow) * KPAD + kf) * 2);
                ldsm4(ah[mt], sb + ro);
                ldsm4(al[mt], sb + CB + ro);
            }
#pragma unroll
            for (int ng = 0; ng < 2; ng++) {
                const uint32_t ro = (uint32_t)(((wn + ng * 16 + lrow) * KPAD + kf) * 2);
                ldsm4(bh[ng], sb + 2 * CB + ro);
                ldsm4(bl[ng], sb + 3 * CB + ro);
            }
#pragma unroll
            for (int mt = 0; mt < 4; mt++)
#pragma unroll
                for (int ng = 0; ng < 2; ng++)
#pragma unroll
                    for (int j = 0; j < 2; j++) {
                        float* a = acc[mt][ng * 2 + j];
                        hmma2(a, ah[mt], bh[ng][j], bh[ng][j + 2]);
                        hmma2(a, ah[mt], bl[ng][j], bl[ng][j + 2]);
                        hmma2(a, al[mt], bh[ng][j], bh[ng][j + 2]);
                    }
        }
        __syncthreads();
    }

    // epilogue
    const int g = lane >> 2, t2 = (lane & 3) * 2;
#pragma unroll
    for (int mt = 0; mt < 4; mt++) {
        const int r0 = bm + wm + mt * 16 + g;
#pragma unroll
        for (int nt = 0; nt < 4; nt++) {
            const int cn = bn + wn + nt * 8 + t2;
            float2 v0, v1;
            v0.x = acc[mt][nt][0] + bias[cn];
            v0.y = acc[mt][nt][1] + bias[cn + 1];
            v1.x = acc[mt][nt][2] + bias[cn];
            v1.y = acc[mt][nt][3] + bias[cn + 1];
            if (relu) {
                v0.x = fmaxf(v0.x, 0.0f); v0.y = fmaxf(v0.y, 0.0f);
                v1.x = fmaxf(v1.x, 0.0f); v1.y = fmaxf(v1.y, 0.0f);
            }
            v0.x *= oscale; v0.y *= oscale; v1.x *= oscale; v1.y *= oscale;
            if (Cf) {
                *(float2*)&Cf[(size_t)r0 * N + cn]       = v0;
                *(float2*)&Cf[(size_t)(r0 + 8) * N + cn] = v1;
            }
            if (Chi) {
                uint32_t h0 = pack_hi(v0.x, v0.y);
                uint32_t h1 = pack_hi(v1.x, v1.y);
                *(uint32_t*)&Chi[(size_t)r0 * N + cn]       = h0;
                *(uint32_t*)&Chi[(size_t)(r0 + 8) * N + cn] = h1;
                *(uint32_t*)&Clo[(size_t)r0 * N + cn]       = pack_lo(v0.x, v0.y, h0);
                *(uint32_t*)&Clo[(size_t)(r0 + 8) * N + cn] = pack_lo(v1.x, v1.y, h1);
            }
        }
    }
}

// ===========================================================================
// HMMA flash attention (as R4) — outputs bf16 hi/lo directly.
// ===========================================================================
#define ASD 264
#define ASMEM_BYTES ((2 * 128 + 4 * 32) * ASD * 2)

__global__ __launch_bounds__(256, 1)
void attn2(const bf16* __restrict__ Qh, const bf16* __restrict__ Ql,
           const bf16* __restrict__ Kh, const bf16* __restrict__ Kl,
           const bf16* __restrict__ Vh, const bf16* __restrict__ Vl,
           bf16* __restrict__ Xh, bf16* __restrict__ Xl)
{
    extern __shared__ bf16 sm2[];
    bf16* sQh = sm2;
    bf16* sQl = sQh + 128 * ASD;
    bf16* sKh = sQl + 128 * ASD;
    bf16* sKl = sKh + 32 * ASD;
    bf16* sVh = sKl + 32 * ASD;
    bf16* sVl = sVh + 32 * ASD;

    const int tid  = threadIdx.x;
    const int wid  = tid >> 5;
    const int lane = tid & 31;
    const int qt = blockIdx.x, h = blockIdx.y, b = blockIdx.z;
    const int qrow0  = b * LT + qt * 128;
    const int kvrow0 = b * LI;
    const int hcol   = h * HD;

#pragma unroll
    for (int i = 0; i < 16; i++) {
        const int gi = tid + i * 256;
        const int r = gi >> 5, c8 = (gi & 31) << 3;
        const size_t ga = (size_t)(qrow0 + r) * HID + hcol + c8;
        *(float4*)&sQh[r * ASD + c8] = *(const float4*)&Qh[ga];
        *(float4*)&sQl[r * ASD + c8] = *(const float4*)&Ql[ga];
    }

    const int lrow = lane & 15, lc8 = (lane >> 4) << 3;
    const uint32_t aQh = smem_u32(sQh) + (uint32_t)(((wid * 16 + lrow) * ASD + lc8) * 2);
    const uint32_t aQl = smem_u32(sQl) + (uint32_t)(((wid * 16 + lrow) * ASD + lc8) * 2);
    const uint32_t aKh = smem_u32(sKh) + (uint32_t)((lrow * ASD + lc8) * 2);
    const uint32_t aKl = smem_u32(sKl) + (uint32_t)((lrow * ASD + lc8) * 2);
    const uint32_t aVh = smem_u32(sVh) + (uint32_t)((lrow * ASD + lc8) * 2);
    const uint32_t aVl = smem_u32(sVl) + (uint32_t)((lrow * ASD + lc8) * 2);

    float o[32][4];
#pragma unroll
    for (int i = 0; i < 32; i++)
#pragma unroll
        for (int j = 0; j < 4; j++) o[i][j] = 0.0f;
    float m0 = -1e30f, m1 = -1e30f, l0 = 0.0f, l1 = 0.0f;

    for (int st = 0; st < 18; st++) {
        __syncthreads();
#pragma unroll
        for (int i = 0; i < 4; i++) {
            const int gi = tid + i * 256;
            const int r = gi >> 5, c8 = (gi & 31) << 3;
            const size_t ga = (size_t)(kvrow0 + st * 32 + r) * HID + hcol + c8;
            *(float4*)&sKh[r * ASD + c8] = *(const float4*)&Kh[ga];
            *(float4*)&sKl[r * ASD + c8] = *(const float4*)&Kl[ga];
            *(float4*)&sVh[r * ASD + c8] = *(const float4*)&Vh[ga];
            *(float4*)&sVl[r * ASD + c8] = *(const float4*)&Vl[ga];
        }
        __syncthreads();

        float s[4][4];
#pragma unroll
        for (int i = 0; i < 4; i++)
#pragma unroll
            for (int j = 0; j < 4; j++) s[i][j] = 0.0f;

#pragma unroll
        for (int dc = 0; dc < 16; dc++) {
            uint32_t qh[4], ql[4], kh[4], kl[4];
            ldsm4(qh, aQh + dc * 32);
            ldsm4(ql, aQl + dc * 32);
            ldsm4(kh, aKh + dc * 32);
            ldsm4(kl, aKl + dc * 32);
            hmma2(s[0], qh, kh[0], kh[2]);
            hmma2(s[1], qh, kh[1], kh[3]);
            hmma2(s[0], qh, kl[0], kl[2]);
            hmma2(s[1], qh, kl[1], kl[3]);
            hmma2(s[0], ql, kh[0], kh[2]);
            hmma2(s[1], ql, kh[1], kh[3]);
            ldsm4(kh, aKh + 16 * ASD * 2 + dc * 32);
            ldsm4(kl, aKl + 16 * ASD * 2 + dc * 32);
            hmma2(s[2], qh, kh[0], kh[2]);
            hmma2(s[3], qh, kh[1], kh[3]);
            hmma2(s[2], qh, kl[0], kl[2]);
            hmma2(s[3], qh, kl[1], kl[3]);
            hmma2(s[2], ql, kh[0], kh[2]);
            hmma2(s[3], ql, kh[1], kh[3]);
        }

        float rm0 = s[0][0], rm1 = s[0][2];
#pragma unroll
        for (int nt = 0; nt < 4; nt++) {
            rm0 = fmaxf(rm0, fmaxf(s[nt][0], s[nt][1]));
            rm1 = fmaxf(rm1, fmaxf(s[nt][2], s[nt][3]));
        }
        rm0 = fmaxf(rm0, __shfl_xor_sync(0xffffffffu, rm0, 1));
        rm0 = fmaxf(rm0, __shfl_xor_sync(0xffffffffu, rm0, 2));
        rm1 = fmaxf(rm1, __shfl_xor_sync(0xffffffffu, rm1, 1));
        rm1 = fmaxf(rm1, __shfl_xor_sync(0xffffffffu, rm1, 2));
        const float nm0 = fmaxf(m0, rm0), nm1 = fmaxf(m1, rm1);
        const float sc0 = __expf(m0 - nm0), sc1 = __expf(m1 - nm1);
        m0 = nm0; m1 = nm1;
        float ps0 = 0.0f, ps1 = 0.0f;
#pragma unroll
        for (int nt = 0; nt < 4; nt++) {
            s[nt][0] = __expf(s[nt][0] - nm0); ps0 += s[nt][0];
            s[nt][1] = __expf(s[nt][1] - nm0); ps0 += s[nt][1];
            s[nt][2] = __expf(s[nt][2] - nm1); ps1 += s[nt][2];
            s[nt][3] = __expf(s[nt][3] - nm1); ps1 += s[nt][3];
        }
        ps0 += __shfl_xor_sync(0xffffffffu, ps0, 1);
        ps0 += __shfl_xor_sync(0xffffffffu, ps0, 2);
        ps1 += __shfl_xor_sync(0xffffffffu, ps1, 1);
        ps1 += __shfl_xor_sync(0xffffffffu, ps1, 2);
        l0 = l0 * sc0 + ps0;
        l1 = l1 * sc1 + ps1;

#pragma unroll
        for (int nt = 0; nt < 32; nt++) {
            o[nt][0] *= sc0; o[nt][1] *= sc0;
            o[nt][2] *= sc1; o[nt][3] *= sc1;
        }

#pragma unroll
        for (int kc = 0; kc < 2; kc++) {
            uint32_t pah[4], pal[4];
            const float* f0 = s[2 * kc];
            const float* f1 = s[2 * kc + 1];
            pah[0] = pack_hi(f0[0], f0[1]); pal[0] = pack_lo(f0[0], f0[1], pah[0]);
            pah[1] = pack_hi(f0[2], f0[3]); pal[1] = pack_lo(f0[2], f0[3], pah[1]);
            pah[2] = pack_hi(f1[0], f1[1]); pal[2] = pack_lo(f1[0], f1[1], pah[2]);
            pah[3] = pack_hi(f1[2], f1[3]); pal[3] = pack_lo(f1[2], f1[3], pah[3]);
            const uint32_t vbase = (uint32_t)(kc * 16 * ASD * 2);
#pragma unroll
            for (int nd = 0; nd < 16; nd++) {
                uint32_t vh[4], vl[4];
                ldsm4t(vh, aVh + vbase + nd * 32);
                ldsm4t(vl, aVl + vbase + nd * 32);
                hmma2(o[2 * nd],     pah, vh[0], vh[1]);
                hmma2(o[2 * nd + 1], pah, vh[2], vh[3]);
                hmma2(o[2 * nd],     pah, vl[0], vl[1]);
                hmma2(o[2 * nd + 1], pah, vl[2], vl[3]);
                hmma2(o[2 * nd],     pal, vh[0], vh[1]);
                hmma2(o[2 * nd + 1], pal, vh[2], vh[3]);
            }
        }
    }

    const float i0 = 1.0f / l0, i1 = 1.0f / l1;
    const int g = lane >> 2, t2 = (lane & 3) * 2;
    const int r0 = qrow0 + wid * 16 + g;
#pragma unroll
    for (int nt = 0; nt < 32; nt++) {
        const int col = hcol + nt * 8 + t2;
        const float a0 = o[nt][0] * i0, a1 = o[nt][1] * i0;
        const float b0 = o[nt][2] * i1, b1 = o[nt][3] * i1;
        uint32_t h0 = pack_hi(a0, a1), h1 = pack_hi(b0, b1);
        *(uint32_t*)&Xh[(size_t)r0 * HID + col]       = h0;
        *(uint32_t*)&Xh[(size_t)(r0 + 8) * HID + col] = h1;
        *(uint32_t*)&Xl[(size_t)r0 * HID + col]       = pack_lo(a0, a1, h0);
        *(uint32_t*)&Xl[(size_t)(r0 + 8) * HID + col] = pack_lo(b0, b1, h1);
    }
}

// ---------------------------------------------------------------------------
// Residual + LayerNorm epilogue
// ---------------------------------------------------------------------------
__device__ __forceinline__ float block_sum(float x, float* red)
{
#pragma unroll
    for (int off = 16; off > 0; off >>= 1)
        x += __shfl_xor_sync(0xffffffffu, x, off);
    const int w = threadIdx.x >> 5;
    if ((threadIdx.x & 31) == 0) red[w] = x;
    __syncthreads();
    if (threadIdx.x < 32) {
        float y = (threadIdx.x < 8) ? red[threadIdx.x] : 0.0f;
#pragma unroll
        for (int off = 4; off > 0; off >>= 1)
            y += __shfl_xor_sync(0xffffffffu, y, off);
        if (threadIdx.x == 0) red[0] = y;
    }
    __syncthreads();
    const float r = red[0];
    __syncthreads();
    return r;
}

__global__ __launch_bounds__(256)
void ffln_kernel(const float* __restrict__ OUT, const float* __restrict__ FF,
                 const float* __restrict__ gamma, const float* __restrict__ beta,
                 float* __restrict__ Y)
{
    __shared__ float red[8];
    const int r = blockIdx.x;
    const int tid = threadIdx.x;
    float v[3];
#pragma unroll
    for (int i = 0; i < 3; i++) {
        const int idx = tid + i * 256;
        v[i] = OUT[(size_t)r * TD + idx] + FF[(size_t)r * TD + idx];
    }
    const float mu = block_sum(v[0] + v[1] + v[2], red) * (1.0f / 768.0f);
    const float d0 = v[0] - mu, d1 = v[1] - mu, d2 = v[2] - mu;
    const float var = block_sum(d0 * d0 + d1 * d1 + d2 * d2, red) * (1.0f / 768.0f);
    const float rstd = rsqrtf(var + 1e-5f);
#pragma unroll
    for (int i = 0; i < 3; i++) {
        const int idx = tid + i * 256;
        Y[(size_t)r * TD + idx] = (v[i] - mu) * rstd * gamma[idx] + beta[idx];
    }
}

// ---------------------------------------------------------------------------
extern "C" void kernel_launch(void* const* d_in, const int* in_sizes, int n_in,
                              void* d_out, int out_size)
{
    const float* text  = (const float*)d_in[0];
    const float* image = (const float*)d_in[1];
    const float* wq = (const float*)d_in[2];
    const float* bq = (const float*)d_in[3];
    const float* wk = (const float*)d_in[4];
    const float* bk = (const float*)d_in[5];
    const float* wv = (const float*)d_in[6];
    const float* bv = (const float*)d_in[7];
    const float* wr = (const float*)d_in[8];
    const float* br = (const float*)d_in[9];
    const float* w1 = (const float*)d_in[10];
    const float* b1 = (const float*)d_in[11];
    const float* w2 = (const float*)d_in[12];
    const float* b2 = (const float*)d_in[13];
    const float* gamma = (const float*)d_in[14];
    const float* beta  = (const float*)d_in[15];
    float* Y = (float*)d_out;

    bf16 *th, *tl, *ih, *il;
    bf16 *wqh, *wql, *wkh, *wkl, *wvh, *wvl, *wrh, *wrl, *w1h, *w1l, *w2h, *w2l;
    bf16 *Qh, *Ql, *Kh, *Kl, *Vh, *Vl, *Xh, *Xl, *Oh, *Ol, *Hh, *Hl;
    float *O, *F;
    cudaGetSymbolAddress((void**)&th, g_th);   cudaGetSymbolAddress((void**)&tl, g_tl);
    cudaGetSymbolAddress((void**)&ih, g_ih);   cudaGetSymbolAddress((void**)&il, g_il);
    cudaGetSymbolAddress((void**)&wqh, g_wqh); cudaGetSymbolAddress((void**)&wql, g_wql);
    cudaGetSymbolAddress((void**)&wkh, g_wkh); cudaGetSymbolAddress((void**)&wkl, g_wkl);
    cudaGetSymbolAddress((void**)&wvh, g_wvh); cudaGetSymbolAddress((void**)&wvl, g_wvl);
    cudaGetSymbolAddress((void**)&wrh, g_wrh); cudaGetSymbolAddress((void**)&wrl, g_wrl);
    cudaGetSymbolAddress((void**)&w1h, g_w1h); cudaGetSymbolAddress((void**)&w1l, g_w1l);
    cudaGetSymbolAddress((void**)&w2h, g_w2h); cudaGetSymbolAddress((void**)&w2l, g_w2l);
    cudaGetSymbolAddress((void**)&Qh, g_Qh);   cudaGetSymbolAddress((void**)&Ql, g_Ql);
    cudaGetSymbolAddress((void**)&Kh, g_Kh);   cudaGetSymbolAddress((void**)&Kl, g_Kl);
    cudaGetSymbolAddress((void**)&Vh, g_Vh);   cudaGetSymbolAddress((void**)&Vl, g_Vl);
    cudaGetSymbolAddress((void**)&Xh, g_Xh);   cudaGetSymbolAddress((void**)&Xl, g_Xl);
    cudaGetSymbolAddress((void**)&Oh, g_Oh);   cudaGetSymbolAddress((void**)&Ol, g_Ol);
    cudaGetSymbolAddress((void**)&Hh, g_Hh);   cudaGetSymbolAddress((void**)&Hl, g_Hl);
    cudaGetSymbolAddress((void**)&O, g_O);
    cudaGetSymbolAddress((void**)&F, g_F);

    cudaFuncSetAttribute(gemm_bf16, cudaFuncAttributeMaxDynamicSharedMemorySize, GSMEM_BYTES);
    cudaFuncSetAttribute(attn2, cudaFuncAttributeMaxDynamicSharedMemorySize, ASMEM_BYTES);

    // --- pre-passes ---
    split_act<<<(B_ * LT * TD) / 1024, 256>>>(text, th, tl);
    split_act<<<(B_ * LI * ID) / 1024, 256>>>(image, ih, il);
    tsplit<<<dim3(HID / 32, TD / 32),  256>>>(wq, wqh, wql, TD,  HID);
    tsplit<<<dim3(HID / 32, ID / 32),  256>>>(wk, wkh, wkl, ID,  HID);
    tsplit<<<dim3(HID / 32, ID / 32),  256>>>(wv, wvh, wvl, ID,  HID);
    tsplit<<<dim3(TD / 32,  HID / 32), 256>>>(wr, wrh, wrl, HID, TD);
    tsplit<<<dim3(FFD / 32, TD / 32),  256>>>(w1, w1h, w1l, TD,  FFD);
    tsplit<<<dim3(TD / 32,  FFD / 32), 256>>>(w2, w2h, w2l, FFD, TD);

    // --- projections (Q scaled by 1/sqrt(256)) ---
    gemm_bf16<<<dim3(HID / 128, (B_ * LT) / 128), 256, GSMEM_BYTES>>>(
        th, tl, wqh, wql, bq, nullptr, Qh, Ql, B_ * LT, HID, TD, 0, 0.0625f);
    gemm_bf16<<<dim3(HID / 128, (B_ * LI) / 128), 256, GSMEM_BYTES>>>(
        ih, il, wkh, wkl, bk, nullptr, Kh, Kl, B_ * LI, HID, ID, 0, 1.0f);
    gemm_bf16<<<dim3(HID / 128, (B_ * LI) / 128), 256, GSMEM_BYTES>>>(
        ih, il, wvh, wvl, bv, nullptr, Vh, Vl, B_ * LI, HID, ID, 0, 1.0f);

    // --- attention ---
    attn2<<<dim3(LT / 128, NH, B_), 256, ASMEM_BYTES>>>(Qh, Ql, Kh, Kl, Vh, Vl, Xh, Xl);

    // --- output projection + FF ---
    gemm_bf16<<<dim3(TD / 128, (B_ * LT) / 128), 256, GSMEM_BYTES>>>(
        Xh, Xl, wrh, wrl, br, O, Oh, Ol, B_ * LT, TD, HID, 0, 1.0f);
    gemm_bf16<<<dim3(FFD / 128, (B_ * LT) / 128), 256, GSMEM_BYTES>>>(
        Oh, Ol, w1h, w1l, b1, nullptr, Hh, Hl, B_ * LT, FFD, TD, 1, 1.0f);
    gemm_bf16<<<dim3(TD / 128, (B_ * LT) / 128), 256, GSMEM_BYTES>>>(
        Hh, Hl, w2h, w2l, b2, F, nullptr, nullptr, B_ * LT, TD, FFD, 0, 1.0f);

    // --- residual + LayerNorm ---
    ffln_kernel<<<B_ * LT, 256>>>(O, F, gamma, beta, Y);
}

// round 6
// speedup vs baseline: 3.4196x; 1.0965x over previous
#include <cuda_runtime.h>
#include <cuda_bf16.h>
#include <cstdint>
#include <math.h>

#define B_   16
#define LT   512
#define LI   576
#define TD   768
#define ID   1024
#define HID  2048
#define NH   8
#define HD   256
#define FFD  128

typedef __nv_bfloat16 bf16;

// ---- scratch (device globals) ----
__device__ bf16 g_th[B_ * LT * TD],  g_tl[B_ * LT * TD];
__device__ bf16 g_ih[B_ * LI * ID],  g_il[B_ * LI * ID];
__device__ bf16 g_wqh[HID * TD],  g_wql[HID * TD];
__device__ bf16 g_wkh[HID * ID],  g_wkl[HID * ID];
__device__ bf16 g_wvh[HID * ID],  g_wvl[HID * ID];
__device__ bf16 g_wrh[TD * HID],  g_wrl[TD * HID];
__device__ bf16 g_w1h[FFD * TD],  g_w1l[FFD * TD];
__device__ bf16 g_w2h[TD * FFD],  g_w2l[TD * FFD];
__device__ bf16 g_Qh[B_ * LT * HID], g_Ql[B_ * LT * HID];
__device__ bf16 g_Kh[B_ * LI * HID], g_Kl[B_ * LI * HID];
__device__ bf16 g_Vh[B_ * LI * HID], g_Vl[B_ * LI * HID];
__device__ bf16 g_Xh[B_ * LT * HID], g_Xl[B_ * LT * HID];
__device__ bf16 g_Oh[B_ * LT * TD],  g_Ol[B_ * LT * TD];
__device__ bf16 g_Hh[B_ * LT * FFD], g_Hl[B_ * LT * FFD];
__device__ float g_O[B_ * LT * TD];
__device__ float g_F[B_ * LT * TD];

// ===========================================================================
// helpers
// ===========================================================================
__device__ __forceinline__ void hmma2(float* c, const uint32_t* a, uint32_t b0, uint32_t b1)
{
    asm volatile(
        "mma.sync.aligned.m16n8k16.row.col.f32.bf16.bf16.f32 "
        "{%0,%1,%2,%3}, {%4,%5,%6,%7}, {%8,%9}, {%0,%1,%2,%3};"
        : "+f"(c[0]), "+f"(c[1]), "+f"(c[2]), "+f"(c[3])
        : "r"(a[0]), "r"(a[1]), "r"(a[2]), "r"(a[3]), "r"(b0), "r"(b1));
}
__device__ __forceinline__ void ldsm4(uint32_t* r, uint32_t addr)
{
    asm volatile("ldmatrix.sync.aligned.m8n8.x4.shared.b16 {%0,%1,%2,%3}, [%4];"
                 : "=r"(r[0]), "=r"(r[1]), "=r"(r[2]), "=r"(r[3]) : "r"(addr));
}
__device__ __forceinline__ void ldsm4t(uint32_t* r, uint32_t addr)
{
    asm volatile("ldmatrix.sync.aligned.m8n8.x4.trans.shared.b16 {%0,%1,%2,%3}, [%4];"
                 : "=r"(r[0]), "=r"(r[1]), "=r"(r[2]), "=r"(r[3]) : "r"(addr));
}
__device__ __forceinline__ uint32_t smem_u32(const void* p) {
    uint32_t a;
    asm("{ .reg .u64 t; cvta.to.shared.u64 t, %1; cvt.u32.u64 %0, t; }" : "=r"(a) : "l"(p));
    return a;
}
__device__ __forceinline__ uint32_t pack_hi(float x0, float x1)
{
    __nv_bfloat162 h = __floats2bfloat162_rn(x0, x1);
    return *(uint32_t*)&h;
}
__device__ __forceinline__ uint32_t pack_lo(float x0, float x1, uint32_t hi)
{
    __nv_bfloat162 hv = *(__nv_bfloat162*)&hi;
    float r0 = x0 - __bfloat162float(hv.x);
    float r1 = x1 - __bfloat162float(hv.y);
    __nv_bfloat162 l = __floats2bfloat162_rn(r0, r1);
    return *(uint32_t*)&l;
}
#define CP16(s, g) \
    asm volatile("cp.async.cg.shared.global [%0], [%1], 16;" :: "r"(s), "l"(g) : "memory")
#define CPCOMMIT() asm volatile("cp.async.commit_group;" ::: "memory")
#define CPWAIT(n)  asm volatile("cp.async.wait_group %0;" :: "n"(n) : "memory")

// ===========================================================================
// Pre-passes
// ===========================================================================
__global__ __launch_bounds__(256)
void split_act(const float* __restrict__ X, bf16* __restrict__ H, bf16* __restrict__ L)
{
    const int i = (blockIdx.x * 256 + threadIdx.x) * 4;
    float4 v = *(const float4*)&X[i];
    uint32_t h0 = pack_hi(v.x, v.y), h1 = pack_hi(v.z, v.w);
    uint32_t l0 = pack_lo(v.x, v.y, h0), l1 = pack_lo(v.z, v.w, h1);
    *(uint32_t*)&H[i]     = h0; *(uint32_t*)&H[i + 2] = h1;
    *(uint32_t*)&L[i]     = l0; *(uint32_t*)&L[i + 2] = l1;
}

__global__ __launch_bounds__(256)
void tsplit(const float* __restrict__ W, bf16* __restrict__ Th, bf16* __restrict__ Tl,
            int K, int N)
{
    __shared__ float t[32][33];
    const int n0 = blockIdx.x * 32, k0 = blockIdx.y * 32;
    const int tx = threadIdx.x & 31, ty4 = (threadIdx.x >> 5) * 4;
#pragma unroll
    for (int i = 0; i < 4; i++)
        t[ty4 + i][tx] = W[(size_t)(k0 + ty4 + i) * N + n0 + tx];
    __syncthreads();
#pragma unroll
    for (int i = 0; i < 4; i++) {
        const float x = t[tx][ty4 + i];
        bf16 h = __float2bfloat16(x);
        const size_t o = (size_t)(n0 + ty4 + i) * K + k0 + tx;
        Th[o] = h;
        Tl[o] = __float2bfloat16(x - __bfloat162float(h));
    }
}

// ===========================================================================
// bf16 GEMM, 3-term split, 2 CTAs/SM. 128x128 block, BK=32, double-buffered.
// ===========================================================================
#define KPAD 40
#define CB   (128 * KPAD * 2)
#define STGB (4 * CB)
#define GSMEM_BYTES (2 * STGB)     // 81920 (<= 114KB -> 2 CTAs/SM)

__global__ __launch_bounds__(256, 2)
void gemm_bf16(const bf16* __restrict__ Ah, const bf16* __restrict__ Al,
               const bf16* __restrict__ Bh, const bf16* __restrict__ Bl,
               const float* __restrict__ bias,
               float* __restrict__ Cf, bf16* __restrict__ Chi, bf16* __restrict__ Clo,
               int M, int N, int Kd, int relu, float oscale)
{
    extern __shared__ char smc[];
    const uint32_t sbase = smem_u32(smc);

    const int tid  = threadIdx.x;
    const int wid  = tid >> 5;
    const int lane = tid & 31;
    const int bm   = blockIdx.y * 128;
    const int bn   = blockIdx.x * 128;
    const int wm = (wid >> 2) * 64;
    const int wn = (wid & 3) * 32;

    const int NC = Kd >> 5;

    float acc[4][4][4];
#pragma unroll
    for (int i = 0; i < 4; i++)
#pragma unroll
        for (int j = 0; j < 4; j++)
#pragma unroll
            for (int l = 0; l < 4; l++) acc[i][j][l] = 0.0f;

    // loader mapping (fixed per thread)
    const int l_row = tid >> 2, l_sg = (tid & 3) << 3;
    const uint32_t l_so = (uint32_t)((l_row * KPAD + l_sg) * 2);
    const size_t l_ga0 = (size_t)(bm + l_row) * Kd + l_sg;
    const size_t l_gb0 = (size_t)(bn + l_row) * Kd + l_sg;
    const int l_row2 = l_row + 64;
    const uint32_t l_so2 = (uint32_t)((l_row2 * KPAD + l_sg) * 2);
    const size_t l_ga2 = (size_t)(bm + l_row2) * Kd + l_sg;
    const size_t l_gb2 = (size_t)(bn + l_row2) * Kd + l_sg;

    auto issue = [&](int c) {
        const uint32_t sb = sbase + (uint32_t)((c & 1) * STGB);
        const int k0 = c << 5;
        CP16(sb + l_so,           Ah + l_ga0 + k0);
        CP16(sb + CB + l_so,      Al + l_ga0 + k0);
        CP16(sb + 2 * CB + l_so,  Bh + l_gb0 + k0);
        CP16(sb + 3 * CB + l_so,  Bl + l_gb0 + k0);
        CP16(sb + l_so2,          Ah + l_ga2 + k0);
        CP16(sb + CB + l_so2,     Al + l_ga2 + k0);
        CP16(sb + 2 * CB + l_so2, Bh + l_gb2 + k0);
        CP16(sb + 3 * CB + l_so2, Bl + l_gb2 + k0);
        CPCOMMIT();
    };

    issue(0);

    const int lrow = lane & 15, lc8 = (lane >> 4) << 3;

    for (int c = 0; c < NC; c++) {
        if (c + 1 < NC) { issue(c + 1); CPWAIT(1); } else { CPWAIT(0); }
        __syncthreads();

        const uint32_t sb = sbase + (uint32_t)((c & 1) * STGB);
#pragma unroll
        for (int ks = 0; ks < 2; ks++) {
            const int kf = ks * 16 + lc8;
            uint32_t bh[2][4], bl[2][4];
#pragma unroll
            for (int ng = 0; ng < 2; ng++) {
                const uint32_t ro = (uint32_t)(((wn + ng * 16 + lrow) * KPAD + kf) * 2);
                ldsm4(bh[ng], sb + 2 * CB + ro);
                ldsm4(bl[ng], sb + 3 * CB + ro);
            }
#pragma unroll
            for (int mt = 0; mt < 4; mt++) {
                uint32_t ah[4], al[4];
                const uint32_t ro = (uint32_t)(((wm + mt * 16 + lrow) * KPAD + kf) * 2);
                ldsm4(ah, sb + ro);
                ldsm4(al, sb + CB + ro);
#pragma unroll
                for (int ng = 0; ng < 2; ng++)
#pragma unroll
                    for (int j = 0; j < 2; j++) {
                        float* a = acc[mt][ng * 2 + j];
                        hmma2(a, ah, bh[ng][j], bh[ng][j + 2]);
                        hmma2(a, ah, bl[ng][j], bl[ng][j + 2]);
                        hmma2(a, al, bh[ng][j], bh[ng][j + 2]);
                    }
            }
        }
        __syncthreads();
    }

    // epilogue
    const int g = lane >> 2, t2 = (lane & 3) * 2;
#pragma unroll
    for (int mt = 0; mt < 4; mt++) {
        const int r0 = bm + wm + mt * 16 + g;
#pragma unroll
        for (int nt = 0; nt < 4; nt++) {
            const int cn = bn + wn + nt * 8 + t2;
            float2 v0, v1;
            v0.x = acc[mt][nt][0] + bias[cn];
            v0.y = acc[mt][nt][1] + bias[cn + 1];
            v1.x = acc[mt][nt][2] + bias[cn];
            v1.y = acc[mt][nt][3] + bias[cn + 1];
            if (relu) {
                v0.x = fmaxf(v0.x, 0.0f); v0.y = fmaxf(v0.y, 0.0f);
                v1.x = fmaxf(v1.x, 0.0f); v1.y = fmaxf(v1.y, 0.0f);
            }
            v0.x *= oscale; v0.y *= oscale; v1.x *= oscale; v1.y *= oscale;
            if (Cf) {
                *(float2*)&Cf[(size_t)r0 * N + cn]       = v0;
                *(float2*)&Cf[(size_t)(r0 + 8) * N + cn] = v1;
            }
            if (Chi) {
                uint32_t h0 = pack_hi(v0.x, v0.y);
                uint32_t h1 = pack_hi(v1.x, v1.y);
                *(uint32_t*)&Chi[(size_t)r0 * N + cn]       = h0;
                *(uint32_t*)&Chi[(size_t)(r0 + 8) * N + cn] = h1;
                *(uint32_t*)&Clo[(size_t)r0 * N + cn]       = pack_lo(v0.x, v0.y, h0);
                *(uint32_t*)&Clo[(size_t)(r0 + 8) * N + cn] = pack_lo(v1.x, v1.y, h1);
            }
        }
    }
}

// ===========================================================================
// HMMA flash attention (unchanged from R5)
// ===========================================================================
#define ASD 264
#define ASMEM_BYTES ((2 * 128 + 4 * 32) * ASD * 2)

__global__ __launch_bounds__(256, 1)
void attn2(const bf16* __restrict__ Qh, const bf16* __restrict__ Ql,
           const bf16* __restrict__ Kh, const bf16* __restrict__ Kl,
           const bf16* __restrict__ Vh, const bf16* __restrict__ Vl,
           bf16* __restrict__ Xh, bf16* __restrict__ Xl)
{
    extern __shared__ bf16 sm2[];
    bf16* sQh = sm2;
    bf16* sQl = sQh + 128 * ASD;
    bf16* sKh = sQl + 128 * ASD;
    bf16* sKl = sKh + 32 * ASD;
    bf16* sVh = sKl + 32 * ASD;
    bf16* sVl = sVh + 32 * ASD;

    const int tid  = threadIdx.x;
    const int wid  = tid >> 5;
    const int lane = tid & 31;
    const int qt = blockIdx.x, h = blockIdx.y, b = blockIdx.z;
    const int qrow0  = b * LT + qt * 128;
    const int kvrow0 = b * LI;
    const int hcol   = h * HD;

#pragma unroll
    for (int i = 0; i < 16; i++) {
        const int gi = tid + i * 256;
        const int r = gi >> 5, c8 = (gi & 31) << 3;
        const size_t ga = (size_t)(qrow0 + r) * HID + hcol + c8;
        *(float4*)&sQh[r * ASD + c8] = *(const float4*)&Qh[ga];
        *(float4*)&sQl[r * ASD + c8] = *(const float4*)&Ql[ga];
    }

    const int lrow = lane & 15, lc8 = (lane >> 4) << 3;
    const uint32_t aQh = smem_u32(sQh) + (uint32_t)(((wid * 16 + lrow) * ASD + lc8) * 2);
    const uint32_t aQl = smem_u32(sQl) + (uint32_t)(((wid * 16 + lrow) * ASD + lc8) * 2);
    const uint32_t aKh = smem_u32(sKh) + (uint32_t)((lrow * ASD + lc8) * 2);
    const uint32_t aKl = smem_u32(sKl) + (uint32_t)((lrow * ASD + lc8) * 2);
    const uint32_t aVh = smem_u32(sVh) + (uint32_t)((lrow * ASD + lc8) * 2);
    const uint32_t aVl = smem_u32(sVl) + (uint32_t)((lrow * ASD + lc8) * 2);

    float o[32][4];
#pragma unroll
    for (int i = 0; i < 32; i++)
#pragma unroll
        for (int j = 0; j < 4; j++) o[i][j] = 0.0f;
    float m0 = -1e30f, m1 = -1e30f, l0 = 0.0f, l1 = 0.0f;

    for (int st = 0; st < 18; st++) {
        __syncthreads();
#pragma unroll
        for (int i = 0; i < 4; i++) {
            const int gi = tid + i * 256;
            const int r = gi >> 5, c8 = (gi & 31) << 3;
            const size_t ga = (size_t)(kvrow0 + st * 32 + r) * HID + hcol + c8;
            *(float4*)&sKh[r * ASD + c8] = *(const float4*)&Kh[ga];
            *(float4*)&sKl[r * ASD + c8] = *(const float4*)&Kl[ga];
            *(float4*)&sVh[r * ASD + c8] = *(const float4*)&Vh[ga];
            *(float4*)&sVl[r * ASD + c8] = *(const float4*)&Vl[ga];
        }
        __syncthreads();

        float s[4][4];
#pragma unroll
        for (int i = 0; i < 4; i++)
#pragma unroll
            for (int j = 0; j < 4; j++) s[i][j] = 0.0f;

#pragma unroll
        for (int dc = 0; dc < 16; dc++) {
            uint32_t qh[4], ql[4], kh[4], kl[4];
            ldsm4(qh, aQh + dc * 32);
            ldsm4(ql, aQl + dc * 32);
            ldsm4(kh, aKh + dc * 32);
            ldsm4(kl, aKl + dc * 32);
            hmma2(s[0], qh, kh[0], kh[2]);
            hmma2(s[1], qh, kh[1], kh[3]);
            hmma2(s[0], qh, kl[0], kl[2]);
            hmma2(s[1], qh, kl[1], kl[3]);
            hmma2(s[0], ql, kh[0], kh[2]);
            hmma2(s[1], ql, kh[1], kh[3]);
            ldsm4(kh, aKh + 16 * ASD * 2 + dc * 32);
            ldsm4(kl, aKl + 16 * ASD * 2 + dc * 32);
            hmma2(s[2], qh, kh[0], kh[2]);
            hmma2(s[3], qh, kh[1], kh[3]);
            hmma2(s[2], qh, kl[0], kl[2]);
            hmma2(s[3], qh, kl[1], kl[3]);
            hmma2(s[2], ql, kh[0], kh[2]);
            hmma2(s[3], ql, kh[1], kh[3]);
        }

        float rm0 = s[0][0], rm1 = s[0][2];
#pragma unroll
        for (int nt = 0; nt < 4; nt++) {
            rm0 = fmaxf(rm0, fmaxf(s[nt][0], s[nt][1]));
            rm1 = fmaxf(rm1, fmaxf(s[nt][2], s[nt][3]));
        }
        rm0 = fmaxf(rm0, __shfl_xor_sync(0xffffffffu, rm0, 1));
        rm0 = fmaxf(rm0, __shfl_xor_sync(0xffffffffu, rm0, 2));
        rm1 = fmaxf(rm1, __shfl_xor_sync(0xffffffffu, rm1, 1));
        rm1 = fmaxf(rm1, __shfl_xor_sync(0xffffffffu, rm1, 2));
        const float nm0 = fmaxf(m0, rm0), nm1 = fmaxf(m1, rm1);
        const float sc0 = __expf(m0 - nm0), sc1 = __expf(m1 - nm1);
        m0 = nm0; m1 = nm1;
        float ps0 = 0.0f, ps1 = 0.0f;
#pragma unroll
        for (int nt = 0; nt < 4; nt++) {
            s[nt][0] = __expf(s[nt][0] - nm0); ps0 += s[nt][0];
            s[nt][1] = __expf(s[nt][1] - nm0); ps0 += s[nt][1];
            s[nt][2] = __expf(s[nt][2] - nm1); ps1 += s[nt][2];
            s[nt][3] = __expf(s[nt][3] - nm1); ps1 += s[nt][3];
        }
        ps0 += __shfl_xor_sync(0xffffffffu, ps0, 1);
        ps0 += __shfl_xor_sync(0xffffffffu, ps0, 2);
        ps1 += __shfl_xor_sync(0xffffffffu, ps1, 1);
        ps1 += __shfl_xor_sync(0xffffffffu, ps1, 2);
        l0 = l0 * sc0 + ps0;
        l1 = l1 * sc1 + ps1;

#pragma unroll
        for (int nt = 0; nt < 32; nt++) {
            o[nt][0] *= sc0; o[nt][1] *= sc0;
            o[nt][2] *= sc1; o[nt][3] *= sc1;
        }

#pragma unroll
        for (int kc = 0; kc < 2; kc++) {
            uint32_t pah[4], pal[4];
            const float* f0 = s[2 * kc];
            const float* f1 = s[2 * kc + 1];
            pah[0] = pack_hi(f0[0], f0[1]); pal[0] = pack_lo(f0[0], f0[1], pah[0]);
            pah[1] = pack_hi(f0[2], f0[3]); pal[1] = pack_lo(f0[2], f0[3], pah[1]);
            pah[2] = pack_hi(f1[0], f1[1]); pal[2] = pack_lo(f1[0], f1[1], pah[2]);
            pah[3] = pack_hi(f1[2], f1[3]); pal[3] = pack_lo(f1[2], f1[3], pah[3]);
            const uint32_t vbase = (uint32_t)(kc * 16 * ASD * 2);
#pragma unroll
            for (int nd = 0; nd < 16; nd++) {
                uint32_t vh[4], vl[4];
                ldsm4t(vh, aVh + vbase + nd * 32);
                ldsm4t(vl, aVl + vbase + nd * 32);
                hmma2(o[2 * nd],     pah, vh[0], vh[1]);
                hmma2(o[2 * nd + 1], pah, vh[2], vh[3]);
                hmma2(o[2 * nd],     pah, vl[0], vl[1]);
                hmma2(o[2 * nd + 1], pah, vl[2], vl[3]);
                hmma2(o[2 * nd],     pal, vh[0], vh[1]);
                hmma2(o[2 * nd + 1], pal, vh[2], vh[3]);
            }
        }
    }

    const float i0 = 1.0f / l0, i1 = 1.0f / l1;
    const int g = lane >> 2, t2 = (lane & 3) * 2;
    const int r0 = qrow0 + wid * 16 + g;
#pragma unroll
    for (int nt = 0; nt < 32; nt++) {
        const int col = hcol + nt * 8 + t2;
        const float a0 = o[nt][0] * i0, a1 = o[nt][1] * i0;
        const float b0 = o[nt][2] * i1, b1 = o[nt][3] * i1;
        uint32_t h0 = pack_hi(a0, a1), h1 = pack_hi(b0, b1);
        *(uint32_t*)&Xh[(size_t)r0 * HID + col]       = h0;
        *(uint32_t*)&Xh[(size_t)(r0 + 8) * HID + col] = h1;
        *(uint32_t*)&Xl[(size_t)r0 * HID + col]       = pack_lo(a0, a1, h0);
        *(uint32_t*)&Xl[(size_t)(r0 + 8) * HID + col] = pack_lo(b0, b1, h1);
    }
}

// ---------------------------------------------------------------------------
// Residual + LayerNorm epilogue
// ---------------------------------------------------------------------------
__device__ __forceinline__ float block_sum(float x, float* red)
{
#pragma unroll
    for (int off = 16; off > 0; off >>= 1)
        x += __shfl_xor_sync(0xffffffffu, x, off);
    const int w = threadIdx.x >> 5;
    if ((threadIdx.x & 31) == 0) red[w] = x;
    __syncthreads();
    if (threadIdx.x < 32) {
        float y = (threadIdx.x < 8) ? red[threadIdx.x] : 0.0f;
#pragma unroll
        for (int off = 4; off > 0; off >>= 1)
            y += __shfl_xor_sync(0xffffffffu, y, off);
        if (threadIdx.x == 0) red[0] = y;
    }
    __syncthreads();
    const float r = red[0];
    __syncthreads();
    return r;
}

__global__ __launch_bounds__(256)
void ffln_kernel(const float* __restrict__ OUT, const float* __restrict__ FF,
                 const float* __restrict__ gamma, const float* __restrict__ beta,
                 float* __restrict__ Y)
{
    __shared__ float red[8];
    const int r = blockIdx.x;
    const int tid = threadIdx.x;
    float v[3];
#pragma unroll
    for (int i = 0; i < 3; i++) {
        const int idx = tid + i * 256;
        v[i] = OUT[(size_t)r * TD + idx] + FF[(size_t)r * TD + idx];
    }
    const float mu = block_sum(v[0] + v[1] + v[2], red) * (1.0f / 768.0f);
    const float d0 = v[0] - mu, d1 = v[1] - mu, d2 = v[2] - mu;
    const float var = block_sum(d0 * d0 + d1 * d1 + d2 * d2, red) * (1.0f / 768.0f);
    const float rstd = rsqrtf(var + 1e-5f);
#pragma unroll
    for (int i = 0; i < 3; i++) {
        const int idx = tid + i * 256;
        Y[(size_t)r * TD + idx] = (v[i] - mu) * rstd * gamma[idx] + beta[idx];
    }
}

// ---------------------------------------------------------------------------
extern "C" void kernel_launch(void* const* d_in, const int* in_sizes, int n_in,
                              void* d_out, int out_size)
{
    const float* text  = (const float*)d_in[0];
    const float* image = (const float*)d_in[1];
    const float* wq = (const float*)d_in[2];
    const float* bq = (const float*)d_in[3];
    const float* wk = (const float*)d_in[4];
    const float* bk = (const float*)d_in[5];
    const float* wv = (const float*)d_in[6];
    const float* bv = (const float*)d_in[7];
    const float* wr = (const float*)d_in[8];
    const float* br = (const float*)d_in[9];
    const float* w1 = (const float*)d_in[10];
    const float* b1 = (const float*)d_in[11];
    const float* w2 = (const float*)d_in[12];
    const float* b2 = (const float*)d_in[13];
    const float* gamma = (const float*)d_in[14];
    const float* beta  = (const float*)d_in[15];
    float* Y = (float*)d_out;

    bf16 *th, *tl, *ih, *il;
    bf16 *wqh, *wql, *wkh, *wkl, *wvh, *wvl, *wrh, *wrl, *w1h, *w1l, *w2h, *w2l;
    bf16 *Qh, *Ql, *Kh, *Kl, *Vh, *Vl, *Xh, *Xl, *Oh, *Ol, *Hh, *Hl;
    float *O, *F;
    cudaGetSymbolAddress((void**)&th, g_th);   cudaGetSymbolAddress((void**)&tl, g_tl);
    cudaGetSymbolAddress((void**)&ih, g_ih);   cudaGetSymbolAddress((void**)&il, g_il);
    cudaGetSymbolAddress((void**)&wqh, g_wqh); cudaGetSymbolAddress((void**)&wql, g_wql);
    cudaGetSymbolAddress((void**)&wkh, g_wkh); cudaGetSymbolAddress((void**)&wkl, g_wkl);
    cudaGetSymbolAddress((void**)&wvh, g_wvh); cudaGetSymbolAddress((void**)&wvl, g_wvl);
    cudaGetSymbolAddress((void**)&wrh, g_wrh); cudaGetSymbolAddress((void**)&wrl, g_wrl);
    cudaGetSymbolAddress((void**)&w1h, g_w1h); cudaGetSymbolAddress((void**)&w1l, g_w1l);
    cudaGetSymbolAddress((void**)&w2h, g_w2h); cudaGetSymbolAddress((void**)&w2l, g_w2l);
    cudaGetSymbolAddress((void**)&Qh, g_Qh);   cudaGetSymbolAddress((void**)&Ql, g_Ql);
    cudaGetSymbolAddress((void**)&Kh, g_Kh);   cudaGetSymbolAddress((void**)&Kl, g_Kl);
    cudaGetSymbolAddress((void**)&Vh, g_Vh);   cudaGetSymbolAddress((void**)&Vl, g_Vl);
    cudaGetSymbolAddress((void**)&Xh, g_Xh);   cudaGetSymbolAddress((void**)&Xl, g_Xl);
    cudaGetSymbolAddress((void**)&Oh, g_Oh);   cudaGetSymbolAddress((void**)&Ol, g_Ol);
    cudaGetSymbolAddress((void**)&Hh, g_Hh);   cudaGetSymbolAddress((void**)&Hl, g_Hl);
    cudaGetSymbolAddress((void**)&O, g_O);
    cudaGetSymbolAddress((void**)&F, g_F);

    cudaFuncSetAttribute(gemm_bf16, cudaFuncAttributeMaxDynamicSharedMemorySize, GSMEM_BYTES);
    cudaFuncSetAttribute(attn2, cudaFuncAttributeMaxDynamicSharedMemorySize, ASMEM_BYTES);

    // --- pre-passes ---
    split_act<<<(B_ * LT * TD) / 1024, 256>>>(text, th, tl);
    split_act<<<(B_ * LI * ID) / 1024, 256>>>(image, ih, il);
    tsplit<<<dim3(HID / 32, TD / 32),  256>>>(wq, wqh, wql, TD,  HID);
    tsplit<<<dim3(HID / 32, ID / 32),  256>>>(wk, wkh, wkl, ID,  HID);
    tsplit<<<dim3(HID / 32, ID / 32),  256>>>(wv, wvh, wvl, ID,  HID);
    tsplit<<<dim3(TD / 32,  HID / 32), 256>>>(wr, wrh, wrl, HID, TD);
    tsplit<<<dim3(FFD / 32, TD / 32),  256>>>(w1, w1h, w1l, TD,  FFD);
    tsplit<<<dim3(TD / 32,  FFD / 32), 256>>>(w2, w2h, w2l, FFD, TD);

    // --- projections (Q scaled by 1/sqrt(256)) ---
    gemm_bf16<<<dim3(HID / 128, (B_ * LT) / 128), 256, GSMEM_BYTES>>>(
        th, tl, wqh, wql, bq, nullptr, Qh, Ql, B_ * LT, HID, TD, 0, 0.0625f);
    gemm_bf16<<<dim3(HID / 128, (B_ * LI) / 128), 256, GSMEM_BYTES>>>(
        ih, il, wkh, wkl, bk, nullptr, Kh, Kl, B_ * LI, HID, ID, 0, 1.0f);
    gemm_bf16<<<dim3(HID / 128, (B_ * LI) / 128), 256, GSMEM_BYTES>>>(
        ih, il, wvh, wvl, bv, nullptr, Vh, Vl, B_ * LI, HID, ID, 0, 1.0f);

    // --- attention ---
    attn2<<<dim3(LT / 128, NH, B_), 256, ASMEM_BYTES>>>(Qh, Ql, Kh, Kl, Vh, Vl, Xh, Xl);

    // --- output projection + FF ---
    gemm_bf16<<<dim3(TD / 128, (B_ * LT) / 128), 256, GSMEM_BYTES>>>(
        Xh, Xl, wrh, wrl, br, O, Oh, Ol, B_ * LT, TD, HID, 0, 1.0f);
    gemm_bf16<<<dim3(FFD / 128, (B_ * LT) / 128), 256, GSMEM_BYTES>>>(
        Oh, Ol, w1h, w1l, b1, nullptr, Hh, Hl, B_ * LT, FFD, TD, 1, 1.0f);
    gemm_bf16<<<dim3(TD / 128, (B_ * LT) / 128), 256, GSMEM_BYTES>>>(
        Hh, Hl, w2h, w2l, b2, F, nullptr, nullptr, B_ * LT, TD, FFD, 0, 1.0f);

    // --- residual + LayerNorm ---
    ffln_kernel<<<B_ * LT, 256>>>(O, F, gamma, beta, Y);
}

// round 8
// speedup vs baseline: 4.9367x; 1.4437x over previous
#include <cuda_runtime.h>
#include <cuda_fp16.h>
#include <cstdint>
#include <math.h>

#define B_   16
#define LT   512
#define LI   576
#define TD   768
#define ID   1024
#define HID  2048
#define NH   8
#define HD   256
#define FFD  128

typedef __half fp16;

// ---- scratch (device globals) ----
__device__ fp16 g_th[B_ * LT * TD],  g_tl[B_ * LT * TD];    // text hi/lo
__device__ fp16 g_ih[B_ * LI * ID],  g_il[B_ * LI * ID];    // image hi/lo
__device__ fp16 g_wq[HID * TD];                             // weights^T, 1-term
__device__ fp16 g_wk[HID * ID];
__device__ fp16 g_wv[HID * ID];
__device__ fp16 g_wr[TD * HID];
__device__ fp16 g_w1[FFD * TD];
__device__ fp16 g_w2[TD * FFD];
__device__ fp16 g_Qh[B_ * LT * HID], g_Ql[B_ * LT * HID];   // Q 2-term
__device__ fp16 g_K1[B_ * LI * HID];                        // K 1-term
__device__ fp16 g_V1[B_ * LI * HID];                        // V 1-term
__device__ fp16 g_Xh[B_ * LT * HID], g_Xl[B_ * LT * HID];
__device__ fp16 g_Oh[B_ * LT * TD],  g_Ol[B_ * LT * TD];
__device__ fp16 g_Hh[B_ * LT * FFD], g_Hl[B_ * LT * FFD];
__device__ float g_O[B_ * LT * TD];
__device__ float g_F[B_ * LT * TD];

// ===========================================================================
// helpers
// ===========================================================================
__device__ __forceinline__ void hmma2(float* c, const uint32_t* a, uint32_t b0, uint32_t b1)
{
    asm volatile(
        "mma.sync.aligned.m16n8k16.row.col.f32.f16.f16.f32 "
        "{%0,%1,%2,%3}, {%4,%5,%6,%7}, {%8,%9}, {%0,%1,%2,%3};"
        : "+f"(c[0]), "+f"(c[1]), "+f"(c[2]), "+f"(c[3])
        : "r"(a[0]), "r"(a[1]), "r"(a[2]), "r"(a[3]), "r"(b0), "r"(b1));
}
__device__ __forceinline__ void ldsm4(uint32_t* r, uint32_t addr)
{
    asm volatile("ldmatrix.sync.aligned.m8n8.x4.shared.b16 {%0,%1,%2,%3}, [%4];"
                 : "=r"(r[0]), "=r"(r[1]), "=r"(r[2]), "=r"(r[3]) : "r"(addr));
}
__device__ __forceinline__ void ldsm4t(uint32_t* r, uint32_t addr)
{
    asm volatile("ldmatrix.sync.aligned.m8n8.x4.trans.shared.b16 {%0,%1,%2,%3}, [%4];"
                 : "=r"(r[0]), "=r"(r[1]), "=r"(r[2]), "=r"(r[3]) : "r"(addr));
}
__device__ __forceinline__ uint32_t smem_u32(const void* p) {
    uint32_t a;
    asm("{ .reg .u64 t; cvta.to.shared.u64 t, %1; cvt.u32.u64 %0, t; }" : "=r"(a) : "l"(p));
    return a;
}
__device__ __forceinline__ uint32_t pack_hi(float x0, float x1)
{
    __half2 h = __floats2half2_rn(x0, x1);
    return *(uint32_t*)&h;
}
__device__ __forceinline__ uint32_t pack_lo(float x0, float x1, uint32_t hi)
{
    __half2 hv = *(__half2*)&hi;
    float r0 = x0 - __half2float(hv.x);
    float r1 = x1 - __half2float(hv.y);
    __half2 l = __floats2half2_rn(r0, r1);
    return *(uint32_t*)&l;
}
#define CP16(s, g) \
    asm volatile("cp.async.cg.shared.global [%0], [%1], 16;" :: "r"(s), "l"(g) : "memory")
#define CPCOMMIT() asm volatile("cp.async.commit_group;" ::: "memory")
#define CPWAIT(n)  asm volatile("cp.async.wait_group %0;" :: "n"(n) : "memory")

// ===========================================================================
// Pre-passes
// ===========================================================================
__global__ __launch_bounds__(256)
void split_act(const float* __restrict__ X, fp16* __restrict__ H, fp16* __restrict__ L)
{
    const int i = (blockIdx.x * 256 + threadIdx.x) * 4;
    float4 v = *(const float4*)&X[i];
    uint32_t h0 = pack_hi(v.x, v.y), h1 = pack_hi(v.z, v.w);
    uint32_t l0 = pack_lo(v.x, v.y, h0), l1 = pack_lo(v.z, v.w, h1);
    *(uint32_t*)&H[i]     = h0; *(uint32_t*)&H[i + 2] = h1;
    *(uint32_t*)&L[i]     = l0; *(uint32_t*)&L[i + 2] = l1;
}

// W[K,N] fp32 -> W^T [N,K] fp16 (1-term)
__global__ __launch_bounds__(256)
void tsplit1(const float* __restrict__ W, fp16* __restrict__ T, int K, int N)
{
    __shared__ float t[32][33];
    const int n0 = blockIdx.x * 32, k0 = blockIdx.y * 32;
    const int tx = threadIdx.x & 31, ty4 = (threadIdx.x >> 5) * 4;
#pragma unroll
    for (int i = 0; i < 4; i++)
        t[ty4 + i][tx] = W[(size_t)(k0 + ty4 + i) * N + n0 + tx];
    __syncthreads();
#pragma unroll
    for (int i = 0; i < 4; i++)
        T[(size_t)(n0 + ty4 + i) * K + k0 + tx] = __float2half_rn(t[tx][ty4 + i]);
}

// ===========================================================================
// fp16 2-term GEMM: C = (Ah+Al)[M,K] @ B1[N,K]^T + bias
// 128x128 block, BK=32, 256 threads, 2 CTAs/SM, double-buffered cp.async.
// ===========================================================================
#define KPAD 40
#define CB   (128 * KPAD * 2)      // 10240 B per component tile
#define STGB (3 * CB)              // Ah, Al, B
#define GSMEM_BYTES (2 * STGB)     // 61440

__global__ __launch_bounds__(256, 2)
void gemm_f16(const fp16* __restrict__ Ah, const fp16* __restrict__ Al,
              const fp16* __restrict__ B1,
              const float* __restrict__ bias,
              float* __restrict__ Cf, fp16* __restrict__ Chi, fp16* __restrict__ Clo,
              int M, int N, int Kd, int relu, float oscale)
{
    extern __shared__ char smc[];
    const uint32_t sbase = smem_u32(smc);

    const int tid  = threadIdx.x;
    const int wid  = tid >> 5;
    const int lane = tid & 31;
    const int bm   = blockIdx.y * 128;
    const int bn   = blockIdx.x * 128;
    const int wm = (wid >> 2) * 64;
    const int wn = (wid & 3) * 32;

    const int NC = Kd >> 5;

    float acc[4][4][4];
#pragma unroll
    for (int i = 0; i < 4; i++)
#pragma unroll
        for (int j = 0; j < 4; j++)
#pragma unroll
            for (int l = 0; l < 4; l++) acc[i][j][l] = 0.0f;

    const int l_row = tid >> 2, l_sg = (tid & 3) << 3;
    const uint32_t l_so  = (uint32_t)((l_row * KPAD + l_sg) * 2);
    const uint32_t l_so2 = (uint32_t)(((l_row + 64) * KPAD + l_sg) * 2);
    const size_t l_ga0 = (size_t)(bm + l_row) * Kd + l_sg;
    const size_t l_ga2 = (size_t)(bm + l_row + 64) * Kd + l_sg;
    const size_t l_gb0 = (size_t)(bn + l_row) * Kd + l_sg;
    const size_t l_gb2 = (size_t)(bn + l_row + 64) * Kd + l_sg;

    auto issue = [&](int c) {
        const uint32_t sb = sbase + (uint32_t)((c & 1) * STGB);
        const int k0 = c << 5;
        CP16(sb + l_so,           Ah + l_ga0 + k0);
        CP16(sb + CB + l_so,      Al + l_ga0 + k0);
        CP16(sb + 2 * CB + l_so,  B1 + l_gb0 + k0);
        CP16(sb + l_so2,          Ah + l_ga2 + k0);
        CP16(sb + CB + l_so2,     Al + l_ga2 + k0);
        CP16(sb + 2 * CB + l_so2, B1 + l_gb2 + k0);
        CPCOMMIT();
    };

    issue(0);

    const int lrow = lane & 15, lc8 = (lane >> 4) << 3;

    for (int c = 0; c < NC; c++) {
        if (c + 1 < NC) { issue(c + 1); CPWAIT(1); } else { CPWAIT(0); }
        __syncthreads();

        const uint32_t sb = sbase + (uint32_t)((c & 1) * STGB);
#pragma unroll
        for (int ks = 0; ks < 2; ks++) {
            const int kf = ks * 16 + lc8;
            uint32_t bh[2][4];
#pragma unroll
            for (int ng = 0; ng < 2; ng++) {
                const uint32_t ro = (uint32_t)(((wn + ng * 16 + lrow) * KPAD + kf) * 2);
                ldsm4(bh[ng], sb + 2 * CB + ro);
            }
#pragma unroll
            for (int mt = 0; mt < 4; mt++) {
                uint32_t ah[4], al[4];
                const uint32_t ro = (uint32_t)(((wm + mt * 16 + lrow) * KPAD + kf) * 2);
                ldsm4(ah, sb + ro);
                ldsm4(al, sb + CB + ro);
#pragma unroll
                for (int ng = 0; ng < 2; ng++)
#pragma unroll
                    for (int j = 0; j < 2; j++) {
                        float* a = acc[mt][ng * 2 + j];
                        hmma2(a, ah, bh[ng][j], bh[ng][j + 2]);
                        hmma2(a, al, bh[ng][j], bh[ng][j + 2]);
                    }
            }
        }
        __syncthreads();
    }

    // epilogue
    const int g = lane >> 2, t2 = (lane & 3) * 2;
#pragma unroll
    for (int mt = 0; mt < 4; mt++) {
        const int r0 = bm + wm + mt * 16 + g;
#pragma unroll
        for (int nt = 0; nt < 4; nt++) {
            const int cn = bn + wn + nt * 8 + t2;
            float2 v0, v1;
            v0.x = acc[mt][nt][0] + bias[cn];
            v0.y = acc[mt][nt][1] + bias[cn + 1];
            v1.x = acc[mt][nt][2] + bias[cn];
            v1.y = acc[mt][nt][3] + bias[cn + 1];
            if (relu) {
                v0.x = fmaxf(v0.x, 0.0f); v0.y = fmaxf(v0.y, 0.0f);
                v1.x = fmaxf(v1.x, 0.0f); v1.y = fmaxf(v1.y, 0.0f);
            }
            v0.x *= oscale; v0.y *= oscale; v1.x *= oscale; v1.y *= oscale;
            if (Cf) {
                *(float2*)&Cf[(size_t)r0 * N + cn]       = v0;
                *(float2*)&Cf[(size_t)(r0 + 8) * N + cn] = v1;
            }
            if (Chi) {
                uint32_t h0 = pack_hi(v0.x, v0.y);
                uint32_t h1 = pack_hi(v1.x, v1.y);
                *(uint32_t*)&Chi[(size_t)r0 * N + cn]       = h0;
                *(uint32_t*)&Chi[(size_t)(r0 + 8) * N + cn] = h1;
                if (Clo) {
                    *(uint32_t*)&Clo[(size_t)r0 * N + cn]       = pack_lo(v0.x, v0.y, h0);
                    *(uint32_t*)&Clo[(size_t)(r0 + 8) * N + cn] = pack_lo(v1.x, v1.y, h1);
                }
            }
        }
    }
}

// ===========================================================================
// fp16 flash attention: Q 2-term, K/V 1-term, P 2-term.
// q-tile 128 (8 warps), kv-tile 32, 18 iters.
// ===========================================================================
#define ASD 264
#define ASMEM_BYTES ((2 * 128 + 2 * 32) * ASD * 2)   // 168960

__global__ __launch_bounds__(256, 1)
void attn2(const fp16* __restrict__ Qh, const fp16* __restrict__ Ql,
           const fp16* __restrict__ K1, const fp16* __restrict__ V1,
           fp16* __restrict__ Xh, fp16* __restrict__ Xl)
{
    extern __shared__ fp16 sm2[];
    fp16* sQh = sm2;
    fp16* sQl = sQh + 128 * ASD;
    fp16* sK  = sQl + 128 * ASD;
    fp16* sV  = sK + 32 * ASD;

    const int tid  = threadIdx.x;
    const int wid  = tid >> 5;
    const int lane = tid & 31;
    const int qt = blockIdx.x, h = blockIdx.y, b = blockIdx.z;
    const int qrow0  = b * LT + qt * 128;
    const int kvrow0 = b * LI;
    const int hcol   = h * HD;

#pragma unroll
    for (int i = 0; i < 16; i++) {
        const int gi = tid + i * 256;
        const int r = gi >> 5, c8 = (gi & 31) << 3;
        const size_t ga = (size_t)(qrow0 + r) * HID + hcol + c8;
        *(float4*)&sQh[r * ASD + c8] = *(const float4*)&Qh[ga];
        *(float4*)&sQl[r * ASD + c8] = *(const float4*)&Ql[ga];
    }

    const int lrow = lane & 15, lc8 = (lane >> 4) << 3;
    const uint32_t aQh = smem_u32(sQh) + (uint32_t)(((wid * 16 + lrow) * ASD + lc8) * 2);
    const uint32_t aQl = smem_u32(sQl) + (uint32_t)(((wid * 16 + lrow) * ASD + lc8) * 2);
    const uint32_t aK  = smem_u32(sK)  + (uint32_t)((lrow * ASD + lc8) * 2);
    const uint32_t aV  = smem_u32(sV)  + (uint32_t)((lrow * ASD + lc8) * 2);

    float o[32][4];
#pragma unroll
    for (int i = 0; i < 32; i++)
#pragma unroll
        for (int j = 0; j < 4; j++) o[i][j] = 0.0f;
    float m0 = -1e30f, m1 = -1e30f, l0 = 0.0f, l1 = 0.0f;

    for (int st = 0; st < 18; st++) {
        __syncthreads();
        // K/V tile: 32 rows x 256 cols each -> 8192 halves per array
        // = 4 iterations x 256 threads x 8 halves.
#pragma unroll
        for (int i = 0; i < 4; i++) {
            const int gi = tid + i * 256;
            const int r = gi >> 5, c8 = (gi & 31) << 3;
            const size_t ga = (size_t)(kvrow0 + st * 32 + r) * HID + hcol + c8;
            *(float4*)&sK[r * ASD + c8] = *(const float4*)&K1[ga];
            *(float4*)&sV[r * ASD + c8] = *(const float4*)&V1[ga];
        }
        __syncthreads();

        // S = Q K^T (scale folded into Q)
        float s[4][4];
#pragma unroll
        for (int i = 0; i < 4; i++)
#pragma unroll
            for (int j = 0; j < 4; j++) s[i][j] = 0.0f;

#pragma unroll
        for (int dc = 0; dc < 16; dc++) {
            uint32_t qh[4], ql[4], k0[4], k1r[4];
            ldsm4(qh, aQh + dc * 32);
            ldsm4(ql, aQl + dc * 32);
            ldsm4(k0, aK + dc * 32);
            hmma2(s[0], qh, k0[0], k0[2]);
            hmma2(s[1], qh, k0[1], k0[3]);
            hmma2(s[0], ql, k0[0], k0[2]);
            hmma2(s[1], ql, k0[1], k0[3]);
            ldsm4(k1r, aK + 16 * ASD * 2 + dc * 32);
            hmma2(s[2], qh, k1r[0], k1r[2]);
            hmma2(s[3], qh, k1r[1], k1r[3]);
            hmma2(s[2], ql, k1r[0], k1r[2]);
            hmma2(s[3], ql, k1r[1], k1r[3]);
        }

        // online softmax
        float rm0 = s[0][0], rm1 = s[0][2];
#pragma unroll
        for (int nt = 0; nt < 4; nt++) {
            rm0 = fmaxf(rm0, fmaxf(s[nt][0], s[nt][1]));
            rm1 = fmaxf(rm1, fmaxf(s[nt][2], s[nt][3]));
        }
        rm0 = fmaxf(rm0, __shfl_xor_sync(0xffffffffu, rm0, 1));
        rm0 = fmaxf(rm0, __shfl_xor_sync(0xffffffffu, rm0, 2));
        rm1 = fmaxf(rm1, __shfl_xor_sync(0xffffffffu, rm1, 1));
        rm1 = fmaxf(rm1, __shfl_xor_sync(0xffffffffu, rm1, 2));
        const float nm0 = fmaxf(m0, rm0), nm1 = fmaxf(m1, rm1);
        const float sc0 = __expf(m0 - nm0), sc1 = __expf(m1 - nm1);
        m0 = nm0; m1 = nm1;
        float ps0 = 0.0f, ps1 = 0.0f;
#pragma unroll
        for (int nt = 0; nt < 4; nt++) {
            s[nt][0] = __expf(s[nt][0] - nm0); ps0 += s[nt][0];
            s[nt][1] = __expf(s[nt][1] - nm0); ps0 += s[nt][1];
            s[nt][2] = __expf(s[nt][2] - nm1); ps1 += s[nt][2];
            s[nt][3] = __expf(s[nt][3] - nm1); ps1 += s[nt][3];
        }
        ps0 += __shfl_xor_sync(0xffffffffu, ps0, 1);
        ps0 += __shfl_xor_sync(0xffffffffu, ps0, 2);
        ps1 += __shfl_xor_sync(0xffffffffu, ps1, 1);
        ps1 += __shfl_xor_sync(0xffffffffu, ps1, 2);
        l0 = l0 * sc0 + ps0;
        l1 = l1 * sc1 + ps1;

#pragma unroll
        for (int nt = 0; nt < 32; nt++) {
            o[nt][0] *= sc0; o[nt][1] *= sc0;
            o[nt][2] *= sc1; o[nt][3] *= sc1;
        }

        // O += P V  (P 2-term fp16, V 1-term)
#pragma unroll
        for (int kc = 0; kc < 2; kc++) {
            uint32_t pah[4], pal[4];
            const float* f0 = s[2 * kc];
            const float* f1 = s[2 * kc + 1];
            pah[0] = pack_hi(f0[0], f0[1]); pal[0] = pack_lo(f0[0], f0[1], pah[0]);
            pah[1] = pack_hi(f0[2], f0[3]); pal[1] = pack_lo(f0[2], f0[3], pah[1]);
            pah[2] = pack_hi(f1[0], f1[1]); pal[2] = pack_lo(f1[0], f1[1], pah[2]);
            pah[3] = pack_hi(f1[2], f1[3]); pal[3] = pack_lo(f1[2], f1[3], pah[3]);
            const uint32_t vbase = (uint32_t)(kc * 16 * ASD * 2);
#pragma unroll
            for (int nd = 0; nd < 16; nd++) {
                uint32_t vh[4];
                ldsm4t(vh, aV + vbase + nd * 32);
                hmma2(o[2 * nd],     pah, vh[0], vh[1]);
                hmma2(o[2 * nd + 1], pah, vh[2], vh[3]);
                hmma2(o[2 * nd],     pal, vh[0], vh[1]);
                hmma2(o[2 * nd + 1], pal, vh[2], vh[3]);
            }
        }
    }

    const float i0 = 1.0f / l0, i1 = 1.0f / l1;
    const int g = lane >> 2, t2 = (lane & 3) * 2;
    const int r0 = qrow0 + wid * 16 + g;
#pragma unroll
    for (int nt = 0; nt < 32; nt++) {
        const int col = hcol + nt * 8 + t2;
        const float a0 = o[nt][0] * i0, a1 = o[nt][1] * i0;
        const float b0 = o[nt][2] * i1, b1 = o[nt][3] * i1;
        uint32_t h0 = pack_hi(a0, a1), h1 = pack_hi(b0, b1);
        *(uint32_t*)&Xh[(size_t)r0 * HID + col]       = h0;
        *(uint32_t*)&Xh[(size_t)(r0 + 8) * HID + col] = h1;
        *(uint32_t*)&Xl[(size_t)r0 * HID + col]       = pack_lo(a0, a1, h0);
        *(uint32_t*)&Xl[(size_t)(r0 + 8) * HID + col] = pack_lo(b0, b1, h1);
    }
}

// ---------------------------------------------------------------------------
// Residual + LayerNorm epilogue
// ---------------------------------------------------------------------------
__device__ __forceinline__ float block_sum(float x, float* red)
{
#pragma unroll
    for (int off = 16; off > 0; off >>= 1)
        x += __shfl_xor_sync(0xffffffffu, x, off);
    const int w = threadIdx.x >> 5;
    if ((threadIdx.x & 31) == 0) red[w] = x;
    __syncthreads();
    if (threadIdx.x < 32) {
        float y = (threadIdx.x < 8) ? red[threadIdx.x] : 0.0f;
#pragma unroll
        for (int off = 4; off > 0; off >>= 1)
            y += __shfl_xor_sync(0xffffffffu, y, off);
        if (threadIdx.x == 0) red[0] = y;
    }
    __syncthreads();
    const float r = red[0];
    __syncthreads();
    return r;
}

__global__ __launch_bounds__(256)
void ffln_kernel(const float* __restrict__ OUT, const float* __restrict__ FF,
                 const float* __restrict__ gamma, const float* __restrict__ beta,
                 float* __restrict__ Y)
{
    __shared__ float red[8];
    const int r = blockIdx.x;
    const int tid = threadIdx.x;
    float v[3];
#pragma unroll
    for (int i = 0; i < 3; i++) {
        const int idx = tid + i * 256;
        v[i] = OUT[(size_t)r * TD + idx] + FF[(size_t)r * TD + idx];
    }
    const float mu = block_sum(v[0] + v[1] + v[2], red) * (1.0f / 768.0f);
    const float d0 = v[0] - mu, d1 = v[1] - mu, d2 = v[2] - mu;
    const float var = block_sum(d0 * d0 + d1 * d1 + d2 * d2, red) * (1.0f / 768.0f);
    const float rstd = rsqrtf(var + 1e-5f);
#pragma unroll
    for (int i = 0; i < 3; i++) {
        const int idx = tid + i * 256;
        Y[(size_t)r * TD + idx] = (v[i] - mu) * rstd * gamma[idx] + beta[idx];
    }
}

// ---------------------------------------------------------------------------
extern "C" void kernel_launch(void* const* d_in, const int* in_sizes, int n_in,
                              void* d_out, int out_size)
{
    const float* text  = (const float*)d_in[0];
    const float* image = (const float*)d_in[1];
    const float* wq = (const float*)d_in[2];
    const float* bq = (const float*)d_in[3];
    const float* wk = (const float*)d_in[4];
    const float* bk = (const float*)d_in[5];
    const float* wv = (const float*)d_in[6];
    const float* bv = (const float*)d_in[7];
    const float* wr = (const float*)d_in[8];
    const float* br = (const float*)d_in[9];
    const float* w1 = (const float*)d_in[10];
    const float* b1 = (const float*)d_in[11];
    const float* w2 = (const float*)d_in[12];
    const float* b2 = (const float*)d_in[13];
    const float* gamma = (const float*)d_in[14];
    const float* beta  = (const float*)d_in[15];
    float* Y = (float*)d_out;

    fp16 *th, *tl, *ih, *il;
    fp16 *pwq, *pwk, *pwv, *pwr, *pw1, *pw2;
    fp16 *Qh, *Ql, *K1, *V1, *Xh, *Xl, *Oh, *Ol, *Hh, *Hl;
    float *O, *F;
    cudaGetSymbolAddress((void**)&th, g_th);   cudaGetSymbolAddress((void**)&tl, g_tl);
    cudaGetSymbolAddress((void**)&ih, g_ih);   cudaGetSymbolAddress((void**)&il, g_il);
    cudaGetSymbolAddress((void**)&pwq, g_wq);  cudaGetSymbolAddress((void**)&pwk, g_wk);
    cudaGetSymbolAddress((void**)&pwv, g_wv);  cudaGetSymbolAddress((void**)&pwr, g_wr);
    cudaGetSymbolAddress((void**)&pw1, g_w1);  cudaGetSymbolAddress((void**)&pw2, g_w2);
    cudaGetSymbolAddress((void**)&Qh, g_Qh);   cudaGetSymbolAddress((void**)&Ql, g_Ql);
    cudaGetSymbolAddress((void**)&K1, g_K1);   cudaGetSymbolAddress((void**)&V1, g_V1);
    cudaGetSymbolAddress((void**)&Xh, g_Xh);   cudaGetSymbolAddress((void**)&Xl, g_Xl);
    cudaGetSymbolAddress((void**)&Oh, g_Oh);   cudaGetSymbolAddress((void**)&Ol, g_Ol);
    cudaGetSymbolAddress((void**)&Hh, g_Hh);   cudaGetSymbolAddress((void**)&Hl, g_Hl);
    cudaGetSymbolAddress((void**)&O, g_O);
    cudaGetSymbolAddress((void**)&F, g_F);

    cudaFuncSetAttribute(gemm_f16, cudaFuncAttributeMaxDynamicSharedMemorySize, GSMEM_BYTES);
    cudaFuncSetAttribute(attn2, cudaFuncAttributeMaxDynamicSharedMemorySize, ASMEM_BYTES);

    // --- pre-passes ---
    split_act<<<(B_ * LT * TD) / 1024, 256>>>(text, th, tl);
    split_act<<<(B_ * LI * ID) / 1024, 256>>>(image, ih, il);
    tsplit1<<<dim3(HID / 32, TD / 32),  256>>>(wq, pwq, TD,  HID);
    tsplit1<<<dim3(HID / 32, ID / 32),  256>>>(wk, pwk, ID,  HID);
    tsplit1<<<dim3(HID / 32, ID / 32),  256>>>(wv, pwv, ID,  HID);
    tsplit1<<<dim3(TD / 32,  HID / 32), 256>>>(wr, pwr, HID, TD);
    tsplit1<<<dim3(FFD / 32, TD / 32),  256>>>(w1, pw1, TD,  FFD);
    tsplit1<<<dim3(TD / 32,  FFD / 32), 256>>>(w2, pw2, FFD, TD);

    // --- projections (Q scaled by 1/sqrt(256)) ---
    gemm_f16<<<dim3(HID / 128, (B_ * LT) / 128), 256, GSMEM_BYTES>>>(
        th, tl, pwq, bq, nullptr, Qh, Ql, B_ * LT, HID, TD, 0, 0.0625f);
    gemm_f16<<<dim3(HID / 128, (B_ * LI) / 128), 256, GSMEM_BYTES>>>(
        ih, il, pwk, bk, nullptr, K1, nullptr, B_ * LI, HID, ID, 0, 1.0f);
    gemm_f16<<<dim3(HID / 128, (B_ * LI) / 128), 256, GSMEM_BYTES>>>(
        ih, il, pwv, bv, nullptr, V1, nullptr, B_ * LI, HID, ID, 0, 1.0f);

    // --- attention ---
    attn2<<<dim3(LT / 128, NH, B_), 256, ASMEM_BYTES>>>(Qh, Ql, K1, V1, Xh, Xl);

    // --- output projection + FF ---
    gemm_f16<<<dim3(TD / 128, (B_ * LT) / 128), 256, GSMEM_BYTES>>>(
        Xh, Xl, pwr, br, O, Oh, Ol, B_ * LT, TD, HID, 0, 1.0f);
    gemm_f16<<<dim3(FFD / 128, (B_ * LT) / 128), 256, GSMEM_BYTES>>>(
        Oh, Ol, pw1, b1, nullptr, Hh, Hl, B_ * LT, FFD, TD, 1, 1.0f);
    gemm_f16<<<dim3(TD / 128, (B_ * LT) / 128), 256, GSMEM_BYTES>>>(
        Hh, Hl, pw2, b2, F, nullptr, nullptr, B_ * LT, TD, FFD, 0, 1.0f);

    // --- residual + LayerNorm ---
    ffln_kernel<<<B_ * LT, 256>>>(O, F, gamma, beta, Y);
}

// round 9
// speedup vs baseline: 8.3028x; 1.6818x over previous
#include <cuda_runtime.h>
#include <cuda_fp16.h>
#include <cstdint>
#include <math.h>

#define B_   16
#define LT   512
#define LI   576
#define TD   768
#define ID   1024
#define HID  2048
#define NH   8
#define HD   256
#define FFD  128

typedef __half fp16;

// ---- scratch (device globals) ----
__device__ fp16 g_t1[B_ * LT * TD];        // text fp16
__device__ fp16 g_i1[B_ * LI * ID];        // image fp16
__device__ fp16 g_wq[HID * TD];            // weights^T fp16
__device__ fp16 g_wk[HID * ID];
__device__ fp16 g_wv[HID * ID];
__device__ fp16 g_wr[TD * HID];
__device__ fp16 g_w1[FFD * TD];
__device__ fp16 g_w2[TD * FFD];
__device__ fp16 g_Q1[B_ * LT * HID];
__device__ fp16 g_K1[B_ * LI * HID];
__device__ fp16 g_V1[B_ * LI * HID];
__device__ fp16 g_X1[B_ * LT * HID];
__device__ fp16 g_O1[B_ * LT * TD];
__device__ fp16 g_H1[B_ * LT * FFD];
__device__ float g_O[B_ * LT * TD];
__device__ float g_F[B_ * LT * TD];

// ===========================================================================
// helpers
// ===========================================================================
__device__ __forceinline__ void hmma2(float* c, const uint32_t* a, uint32_t b0, uint32_t b1)
{
    asm volatile(
        "mma.sync.aligned.m16n8k16.row.col.f32.f16.f16.f32 "
        "{%0,%1,%2,%3}, {%4,%5,%6,%7}, {%8,%9}, {%0,%1,%2,%3};"
        : "+f"(c[0]), "+f"(c[1]), "+f"(c[2]), "+f"(c[3])
        : "r"(a[0]), "r"(a[1]), "r"(a[2]), "r"(a[3]), "r"(b0), "r"(b1));
}
__device__ __forceinline__ void ldsm4(uint32_t* r, uint32_t addr)
{
    asm volatile("ldmatrix.sync.aligned.m8n8.x4.shared.b16 {%0,%1,%2,%3}, [%4];"
                 : "=r"(r[0]), "=r"(r[1]), "=r"(r[2]), "=r"(r[3]) : "r"(addr));
}
__device__ __forceinline__ void ldsm4t(uint32_t* r, uint32_t addr)
{
    asm volatile("ldmatrix.sync.aligned.m8n8.x4.trans.shared.b16 {%0,%1,%2,%3}, [%4];"
                 : "=r"(r[0]), "=r"(r[1]), "=r"(r[2]), "=r"(r[3]) : "r"(addr));
}
__device__ __forceinline__ uint32_t smem_u32(const void* p) {
    uint32_t a;
    asm("{ .reg .u64 t; cvta.to.shared.u64 t, %1; cvt.u32.u64 %0, t; }" : "=r"(a) : "l"(p));
    return a;
}
__device__ __forceinline__ uint32_t pack_f16x2(float x0, float x1)
{
    __half2 h = __floats2half2_rn(x0, x1);
    return *(uint32_t*)&h;
}
#define CP16(s, g) \
    asm volatile("cp.async.cg.shared.global [%0], [%1], 16;" :: "r"(s), "l"(g) : "memory")
#define CPCOMMIT() asm volatile("cp.async.commit_group;" ::: "memory")
#define CPWAIT(n)  asm volatile("cp.async.wait_group %0;" :: "n"(n) : "memory")

// ===========================================================================
// Pre-passes
// ===========================================================================
__global__ __launch_bounds__(256)
void cvt_act(const float* __restrict__ X, fp16* __restrict__ H)
{
    const int i = (blockIdx.x * 256 + threadIdx.x) * 4;
    float4 v = *(const float4*)&X[i];
    *(uint32_t*)&H[i]     = pack_f16x2(v.x, v.y);
    *(uint32_t*)&H[i + 2] = pack_f16x2(v.z, v.w);
}

// W[K,N] fp32 -> W^T [N,K] fp16
__global__ __launch_bounds__(256)
void tsplit1(const float* __restrict__ W, fp16* __restrict__ T, int K, int N)
{
    __shared__ float t[32][33];
    const int n0 = blockIdx.x * 32, k0 = blockIdx.y * 32;
    const int tx = threadIdx.x & 31, ty4 = (threadIdx.x >> 5) * 4;
#pragma unroll
    for (int i = 0; i < 4; i++)
        t[ty4 + i][tx] = W[(size_t)(k0 + ty4 + i) * N + n0 + tx];
    __syncthreads();
#pragma unroll
    for (int i = 0; i < 4; i++)
        T[(size_t)(n0 + ty4 + i) * K + k0 + tx] = __float2half_rn(t[tx][ty4 + i]);
}

// ===========================================================================
// fp16 GEMM: C = A[M,K] @ B1[N,K]^T + bias
// 128x128 block, BK=32, 256 threads, 2 CTAs/SM, double-buffered cp.async.
// ===========================================================================
#define KPAD 40
#define CB   (128 * KPAD * 2)      // 10240 B per component tile
#define STGB (2 * CB)              // A, B
#define GSMEM_BYTES (2 * STGB)     // 40960

__global__ __launch_bounds__(256, 2)
void gemm_f16(const fp16* __restrict__ A, const fp16* __restrict__ B1,
              const float* __restrict__ bias,
              float* __restrict__ Cf, fp16* __restrict__ Ch,
              int M, int N, int Kd, int relu, float oscale)
{
    extern __shared__ char smc[];
    const uint32_t sbase = smem_u32(smc);

    const int tid  = threadIdx.x;
    const int wid  = tid >> 5;
    const int lane = tid & 31;
    const int bm   = blockIdx.y * 128;
    const int bn   = blockIdx.x * 128;
    const int wm = (wid >> 2) * 64;
    const int wn = (wid & 3) * 32;

    const int NC = Kd >> 5;

    float acc[4][4][4];
#pragma unroll
    for (int i = 0; i < 4; i++)
#pragma unroll
        for (int j = 0; j < 4; j++)
#pragma unroll
            for (int l = 0; l < 4; l++) acc[i][j][l] = 0.0f;

    const int l_row = tid >> 2, l_sg = (tid & 3) << 3;
    const uint32_t l_so  = (uint32_t)((l_row * KPAD + l_sg) * 2);
    const uint32_t l_so2 = (uint32_t)(((l_row + 64) * KPAD + l_sg) * 2);
    const size_t l_ga0 = (size_t)(bm + l_row) * Kd + l_sg;
    const size_t l_ga2 = (size_t)(bm + l_row + 64) * Kd + l_sg;
    const size_t l_gb0 = (size_t)(bn + l_row) * Kd + l_sg;
    const size_t l_gb2 = (size_t)(bn + l_row + 64) * Kd + l_sg;

    auto issue = [&](int c) {
        const uint32_t sb = sbase + (uint32_t)((c & 1) * STGB);
        const int k0 = c << 5;
        CP16(sb + l_so,       A  + l_ga0 + k0);
        CP16(sb + CB + l_so,  B1 + l_gb0 + k0);
        CP16(sb + l_so2,      A  + l_ga2 + k0);
        CP16(sb + CB + l_so2, B1 + l_gb2 + k0);
        CPCOMMIT();
    };

    issue(0);

    const int lrow = lane & 15, lc8 = (lane >> 4) << 3;

    for (int c = 0; c < NC; c++) {
        if (c + 1 < NC) { issue(c + 1); CPWAIT(1); } else { CPWAIT(0); }
        __syncthreads();

        const uint32_t sb = sbase + (uint32_t)((c & 1) * STGB);
#pragma unroll
        for (int ks = 0; ks < 2; ks++) {
            const int kf = ks * 16 + lc8;
            uint32_t bh[2][4];
#pragma unroll
            for (int ng = 0; ng < 2; ng++) {
                const uint32_t ro = (uint32_t)(((wn + ng * 16 + lrow) * KPAD + kf) * 2);
                ldsm4(bh[ng], sb + CB + ro);
            }
#pragma unroll
            for (int mt = 0; mt < 4; mt++) {
                uint32_t ah[4];
                const uint32_t ro = (uint32_t)(((wm + mt * 16 + lrow) * KPAD + kf) * 2);
                ldsm4(ah, sb + ro);
#pragma unroll
                for (int ng = 0; ng < 2; ng++)
#pragma unroll
                    for (int j = 0; j < 2; j++)
                        hmma2(acc[mt][ng * 2 + j], ah, bh[ng][j], bh[ng][j + 2]);
            }
        }
        __syncthreads();
    }

    // epilogue
    const int g = lane >> 2, t2 = (lane & 3) * 2;
#pragma unroll
    for (int mt = 0; mt < 4; mt++) {
        const int r0 = bm + wm + mt * 16 + g;
#pragma unroll
        for (int nt = 0; nt < 4; nt++) {
            const int cn = bn + wn + nt * 8 + t2;
            float2 v0, v1;
            v0.x = acc[mt][nt][0] + bias[cn];
            v0.y = acc[mt][nt][1] + bias[cn + 1];
            v1.x = acc[mt][nt][2] + bias[cn];
            v1.y = acc[mt][nt][3] + bias[cn + 1];
            if (relu) {
                v0.x = fmaxf(v0.x, 0.0f); v0.y = fmaxf(v0.y, 0.0f);
                v1.x = fmaxf(v1.x, 0.0f); v1.y = fmaxf(v1.y, 0.0f);
            }
            v0.x *= oscale; v0.y *= oscale; v1.x *= oscale; v1.y *= oscale;
            if (Cf) {
                *(float2*)&Cf[(size_t)r0 * N + cn]       = v0;
                *(float2*)&Cf[(size_t)(r0 + 8) * N + cn] = v1;
            }
            if (Ch) {
                *(uint32_t*)&Ch[(size_t)r0 * N + cn]       = pack_f16x2(v0.x, v0.y);
                *(uint32_t*)&Ch[(size_t)(r0 + 8) * N + cn] = pack_f16x2(v1.x, v1.y);
            }
        }
    }
}

// ===========================================================================
// fp16 flash attention: all operands 1-term. q-tile 128 (8 warps),
// kv-tile 64, 9 iters. fp32 accumulators + online softmax.
// ===========================================================================
#define ASD 264
#define ASMEM_BYTES ((128 + 2 * 64) * ASD * 2)   // 135168

__global__ __launch_bounds__(256, 1)
void attn2(const fp16* __restrict__ Q1, const fp16* __restrict__ K1,
           const fp16* __restrict__ V1, fp16* __restrict__ X1)
{
    extern __shared__ fp16 sm2[];
    fp16* sQ = sm2;
    fp16* sK = sQ + 128 * ASD;
    fp16* sV = sK + 64 * ASD;

    const int tid  = threadIdx.x;
    const int wid  = tid >> 5;
    const int lane = tid & 31;
    const int qt = blockIdx.x, h = blockIdx.y, b = blockIdx.z;
    const int qrow0  = b * LT + qt * 128;
    const int kvrow0 = b * LI;
    const int hcol   = h * HD;

    // Q tile: 128 x 256 halves = 16 iters x 256 thr x 8
#pragma unroll
    for (int i = 0; i < 16; i++) {
        const int gi = tid + i * 256;
        const int r = gi >> 5, c8 = (gi & 31) << 3;
        *(float4*)&sQ[r * ASD + c8] =
            *(const float4*)&Q1[(size_t)(qrow0 + r) * HID + hcol + c8];
    }

    const int lrow = lane & 15, lc8 = (lane >> 4) << 3;
    const uint32_t aQ = smem_u32(sQ) + (uint32_t)(((wid * 16 + lrow) * ASD + lc8) * 2);
    const uint32_t aK = smem_u32(sK) + (uint32_t)((lrow * ASD + lc8) * 2);
    const uint32_t aV = smem_u32(sV) + (uint32_t)((lrow * ASD + lc8) * 2);

    float o[32][4];
#pragma unroll
    for (int i = 0; i < 32; i++)
#pragma unroll
        for (int j = 0; j < 4; j++) o[i][j] = 0.0f;
    float m0 = -1e30f, m1 = -1e30f, l0 = 0.0f, l1 = 0.0f;

    for (int st = 0; st < 9; st++) {
        __syncthreads();
        // K/V tile: 64 rows x 256 halves each = 8 iters x 256 thr x 8
#pragma unroll
        for (int i = 0; i < 8; i++) {
            const int gi = tid + i * 256;
            const int r = gi >> 5, c8 = (gi & 31) << 3;
            const size_t ga = (size_t)(kvrow0 + st * 64 + r) * HID + hcol + c8;
            *(float4*)&sK[r * ASD + c8] = *(const float4*)&K1[ga];
            *(float4*)&sV[r * ASD + c8] = *(const float4*)&V1[ga];
        }
        __syncthreads();

        // S = Q K^T (scale folded into Q): s[8] n8-tiles covering 64 kv rows
        float s[8][4];
#pragma unroll
        for (int i = 0; i < 8; i++)
#pragma unroll
            for (int j = 0; j < 4; j++) s[i][j] = 0.0f;

#pragma unroll
        for (int dc = 0; dc < 16; dc++) {
            uint32_t q0[4];
            ldsm4(q0, aQ + dc * 32);
#pragma unroll
            for (int kg = 0; kg < 4; kg++) {
                uint32_t k0[4];
                ldsm4(k0, aK + (uint32_t)(kg * 16 * ASD * 2) + dc * 32);
                hmma2(s[2 * kg],     q0, k0[0], k0[2]);
                hmma2(s[2 * kg + 1], q0, k0[1], k0[3]);
            }
        }

        // online softmax (rows g, g+8 of this warp)
        float rm0 = s[0][0], rm1 = s[0][2];
#pragma unroll
        for (int nt = 0; nt < 8; nt++) {
            rm0 = fmaxf(rm0, fmaxf(s[nt][0], s[nt][1]));
            rm1 = fmaxf(rm1, fmaxf(s[nt][2], s[nt][3]));
        }
        rm0 = fmaxf(rm0, __shfl_xor_sync(0xffffffffu, rm0, 1));
        rm0 = fmaxf(rm0, __shfl_xor_sync(0xffffffffu, rm0, 2));
        rm1 = fmaxf(rm1, __shfl_xor_sync(0xffffffffu, rm1, 1));
        rm1 = fmaxf(rm1, __shfl_xor_sync(0xffffffffu, rm1, 2));
        const float nm0 = fmaxf(m0, rm0), nm1 = fmaxf(m1, rm1);
        const float sc0 = __expf(m0 - nm0), sc1 = __expf(m1 - nm1);
        m0 = nm0; m1 = nm1;
        float ps0 = 0.0f, ps1 = 0.0f;
#pragma unroll
        for (int nt = 0; nt < 8; nt++) {
            s[nt][0] = __expf(s[nt][0] - nm0); ps0 += s[nt][0];
            s[nt][1] = __expf(s[nt][1] - nm0); ps0 += s[nt][1];
            s[nt][2] = __expf(s[nt][2] - nm1); ps1 += s[nt][2];
            s[nt][3] = __expf(s[nt][3] - nm1); ps1 += s[nt][3];
        }
        ps0 += __shfl_xor_sync(0xffffffffu, ps0, 1);
        ps0 += __shfl_xor_sync(0xffffffffu, ps0, 2);
        ps1 += __shfl_xor_sync(0xffffffffu, ps1, 1);
        ps1 += __shfl_xor_sync(0xffffffffu, ps1, 2);
        l0 = l0 * sc0 + ps0;
        l1 = l1 * sc1 + ps1;

#pragma unroll
        for (int nt = 0; nt < 32; nt++) {
            o[nt][0] *= sc0; o[nt][1] *= sc0;
            o[nt][2] *= sc1; o[nt][3] *= sc1;
        }

        // P (1-term fp16) fragments for 4 k16-groups
        uint32_t pa[4][4];
#pragma unroll
        for (int kc = 0; kc < 4; kc++) {
            const float* f0 = s[2 * kc];
            const float* f1 = s[2 * kc + 1];
            pa[kc][0] = pack_f16x2(f0[0], f0[1]);
            pa[kc][1] = pack_f16x2(f0[2], f0[3]);
            pa[kc][2] = pack_f16x2(f1[0], f1[1]);
            pa[kc][3] = pack_f16x2(f1[2], f1[3]);
        }

        // O += P V
#pragma unroll
        for (int kc = 0; kc < 4; kc++) {
            const uint32_t vbase = (uint32_t)(kc * 16 * ASD * 2);
#pragma unroll
            for (int nd = 0; nd < 16; nd++) {
                uint32_t vh[4];
                ldsm4t(vh, aV + vbase + nd * 32);
                hmma2(o[2 * nd],     pa[kc], vh[0], vh[1]);
                hmma2(o[2 * nd + 1], pa[kc], vh[2], vh[3]);
            }
        }
    }

    const float i0 = 1.0f / l0, i1 = 1.0f / l1;
    const int g = lane >> 2, t2 = (lane & 3) * 2;
    const int r0 = qrow0 + wid * 16 + g;
#pragma unroll
    for (int nt = 0; nt < 32; nt++) {
        const int col = hcol + nt * 8 + t2;
        *(uint32_t*)&X1[(size_t)r0 * HID + col] =
            pack_f16x2(o[nt][0] * i0, o[nt][1] * i0);
        *(uint32_t*)&X1[(size_t)(r0 + 8) * HID + col] =
            pack_f16x2(o[nt][2] * i1, o[nt][3] * i1);
    }
}

// ---------------------------------------------------------------------------
// Residual + LayerNorm epilogue
// ---------------------------------------------------------------------------
__device__ __forceinline__ float block_sum(float x, float* red)
{
#pragma unroll
    for (int off = 16; off > 0; off >>= 1)
        x += __shfl_xor_sync(0xffffffffu, x, off);
    const int w = threadIdx.x >> 5;
    if ((threadIdx.x & 31) == 0) red[w] = x;
    __syncthreads();
    if (threadIdx.x < 32) {
        float y = (threadIdx.x < 8) ? red[threadIdx.x] : 0.0f;
#pragma unroll
        for (int off = 4; off > 0; off >>= 1)
            y += __shfl_xor_sync(0xffffffffu, y, off);
        if (threadIdx.x == 0) red[0] = y;
    }
    __syncthreads();
    const float r = red[0];
    __syncthreads();
    return r;
}

__global__ __launch_bounds__(256)
void ffln_kernel(const float* __restrict__ OUT, const float* __restrict__ FF,
                 const float* __restrict__ gamma, const float* __restrict__ beta,
                 float* __restrict__ Y)
{
    __shared__ float red[8];
    const int r = blockIdx.x;
    const int tid = threadIdx.x;
    float v[3];
#pragma unroll
    for (int i = 0; i < 3; i++) {
        const int idx = tid + i * 256;
        v[i] = OUT[(size_t)r * TD + idx] + FF[(size_t)r * TD + idx];
    }
    const float mu = block_sum(v[0] + v[1] + v[2], red) * (1.0f / 768.0f);
    const float d0 = v[0] - mu, d1 = v[1] - mu, d2 = v[2] - mu;
    const float var = block_sum(d0 * d0 + d1 * d1 + d2 * d2, red) * (1.0f / 768.0f);
    const float rstd = rsqrtf(var + 1e-5f);
#pragma unroll
    for (int i = 0; i < 3; i++) {
        const int idx = tid + i * 256;
        Y[(size_t)r * TD + idx] = (v[i] - mu) * rstd * gamma[idx] + beta[idx];
    }
}

// ---------------------------------------------------------------------------
extern "C" void kernel_launch(void* const* d_in, const int* in_sizes, int n_in,
                              void* d_out, int out_size)
{
    const float* text  = (const float*)d_in[0];
    const float* image = (const float*)d_in[1];
    const float* wq = (const float*)d_in[2];
    const float* bq = (const float*)d_in[3];
    const float* wk = (const float*)d_in[4];
    const float* bk = (const float*)d_in[5];
    const float* wv = (const float*)d_in[6];
    const float* bv = (const float*)d_in[7];
    const float* wr = (const float*)d_in[8];
    const float* br = (const float*)d_in[9];
    const float* w1 = (const float*)d_in[10];
    const float* b1 = (const float*)d_in[11];
    const float* w2 = (const float*)d_in[12];
    const float* b2 = (const float*)d_in[13];
    const float* gamma = (const float*)d_in[14];
    const float* beta  = (const float*)d_in[15];
    float* Y = (float*)d_out;

    fp16 *t1, *i1, *pwq, *pwk, *pwv, *pwr, *pw1, *pw2;
    fp16 *Q1, *K1, *V1, *X1, *O1, *H1;
    float *O, *F;
    cudaGetSymbolAddress((void**)&t1, g_t1);
    cudaGetSymbolAddress((void**)&i1, g_i1);
    cudaGetSymbolAddress((void**)&pwq, g_wq);  cudaGetSymbolAddress((void**)&pwk, g_wk);
    cudaGetSymbolAddress((void**)&pwv, g_wv);  cudaGetSymbolAddress((void**)&pwr, g_wr);
    cudaGetSymbolAddress((void**)&pw1, g_w1);  cudaGetSymbolAddress((void**)&pw2, g_w2);
    cudaGetSymbolAddress((void**)&Q1, g_Q1);   cudaGetSymbolAddress((void**)&K1, g_K1);
    cudaGetSymbolAddress((void**)&V1, g_V1);   cudaGetSymbolAddress((void**)&X1, g_X1);
    cudaGetSymbolAddress((void**)&O1, g_O1);   cudaGetSymbolAddress((void**)&H1, g_H1);
    cudaGetSymbolAddress((void**)&O, g_O);
    cudaGetSymbolAddress((void**)&F, g_F);

    cudaFuncSetAttribute(gemm_f16, cudaFuncAttributeMaxDynamicSharedMemorySize, GSMEM_BYTES);
    cudaFuncSetAttribute(attn2, cudaFuncAttributeMaxDynamicSharedMemorySize, ASMEM_BYTES);

    // --- pre-passes ---
    cvt_act<<<(B_ * LT * TD) / 1024, 256>>>(text, t1);
    cvt_act<<<(B_ * LI * ID) / 1024, 256>>>(image, i1);
    tsplit1<<<dim3(HID / 32, TD / 32),  256>>>(wq, pwq, TD,  HID);
    tsplit1<<<dim3(HID / 32, ID / 32),  256>>>(wk, pwk, ID,  HID);
    tsplit1<<<dim3(HID / 32, ID / 32),  256>>>(wv, pwv, ID,  HID);
    tsplit1<<<dim3(TD / 32,  HID / 32), 256>>>(wr, pwr, HID, TD);
    tsplit1<<<dim3(FFD / 32, TD / 32),  256>>>(w1, pw1, TD,  FFD);
    tsplit1<<<dim3(TD / 32,  FFD / 32), 256>>>(w2, pw2, FFD, TD);

    // --- projections (Q scaled by 1/sqrt(256)) ---
    gemm_f16<<<dim3(HID / 128, (B_ * LT) / 128), 256, GSMEM_BYTES>>>(
        t1, pwq, bq, nullptr, Q1, B_ * LT, HID, TD, 0, 0.0625f);
    gemm_f16<<<dim3(HID / 128, (B_ * LI) / 128), 256, GSMEM_BYTES>>>(
        i1, pwk, bk, nullptr, K1, B_ * LI, HID, ID, 0, 1.0f);
    gemm_f16<<<dim3(HID / 128, (B_ * LI) / 128), 256, GSMEM_BYTES>>>(
        i1, pwv, bv, nullptr, V1, B_ * LI, HID, ID, 0, 1.0f);

    // --- attention ---
    attn2<<<dim3(LT / 128, NH, B_), 256, ASMEM_BYTES>>>(Q1, K1, V1, X1);

    // --- output projection + FF ---
    gemm_f16<<<dim3(TD / 128, (B_ * LT) / 128), 256, GSMEM_BYTES>>>(
        X1, pwr, br, O, O1, B_ * LT, TD, HID, 0, 1.0f);
    gemm_f16<<<dim3(FFD / 128, (B_ * LT) / 128), 256, GSMEM_BYTES>>>(
        O1, pw1, b1, nullptr, H1, B_ * LT, FFD, TD, 1, 1.0f);
    gemm_f16<<<dim3(TD / 128, (B_ * LT) / 128), 256, GSMEM_BYTES>>>(
        H1, pw2, b2, F, nullptr, B_ * LT, TD, FFD, 0, 1.0f);

    // --- residual + LayerNorm ---
    ffln_kernel<<<B_ * LT, 256>>>(O, F, gamma, beta, Y);
}

// round 10
// speedup vs baseline: 8.6955x; 1.0473x over previous
#include <cuda_runtime.h>
#include <cuda_fp16.h>
#include <cstdint>
#include <math.h>

#define B_   16
#define LT   512
#define LI   576
#define TD   768
#define ID   1024
#define HID  2048
#define NH   8
#define HD   256
#define FFD  128

typedef __half fp16;

// ---- scratch (device globals) ----
__device__ fp16 g_t1[B_ * LT * TD];
__device__ fp16 g_i1[B_ * LI * ID];
__device__ fp16 g_wq[HID * TD];
__device__ fp16 g_wk[HID * ID];
__device__ fp16 g_wv[HID * ID];
__device__ fp16 g_wr[TD * HID];
__device__ fp16 g_w1[FFD * TD];
__device__ fp16 g_w2[TD * FFD];
__device__ fp16 g_Q1[B_ * LT * HID];
__device__ fp16 g_K1[B_ * LI * HID];
__device__ fp16 g_V1[B_ * LI * HID];
__device__ fp16 g_X1[B_ * LT * HID];
__device__ fp16 g_O1[B_ * LT * TD];
__device__ fp16 g_H1[B_ * LT * FFD];
__device__ float g_O[B_ * LT * TD];
__device__ float g_F[B_ * LT * TD];

// ===========================================================================
// helpers
// ===========================================================================
__device__ __forceinline__ void hmma2(float* c, const uint32_t* a, uint32_t b0, uint32_t b1)
{
    asm volatile(
        "mma.sync.aligned.m16n8k16.row.col.f32.f16.f16.f32 "
        "{%0,%1,%2,%3}, {%4,%5,%6,%7}, {%8,%9}, {%0,%1,%2,%3};"
        : "+f"(c[0]), "+f"(c[1]), "+f"(c[2]), "+f"(c[3])
        : "r"(a[0]), "r"(a[1]), "r"(a[2]), "r"(a[3]), "r"(b0), "r"(b1));
}
__device__ __forceinline__ void ldsm4(uint32_t* r, uint32_t addr)
{
    asm volatile("ldmatrix.sync.aligned.m8n8.x4.shared.b16 {%0,%1,%2,%3}, [%4];"
                 : "=r"(r[0]), "=r"(r[1]), "=r"(r[2]), "=r"(r[3]) : "r"(addr));
}
__device__ __forceinline__ void ldsm4t(uint32_t* r, uint32_t addr)
{
    asm volatile("ldmatrix.sync.aligned.m8n8.x4.trans.shared.b16 {%0,%1,%2,%3}, [%4];"
                 : "=r"(r[0]), "=r"(r[1]), "=r"(r[2]), "=r"(r[3]) : "r"(addr));
}
__device__ __forceinline__ uint32_t smem_u32(const void* p) {
    uint32_t a;
    asm("{ .reg .u64 t; cvta.to.shared.u64 t, %1; cvt.u32.u64 %0, t; }" : "=r"(a) : "l"(p));
    return a;
}
__device__ __forceinline__ uint32_t pack_f16x2(float x0, float x1)
{
    __half2 h = __floats2half2_rn(x0, x1);
    return *(uint32_t*)&h;
}
#define CP16(s, g) \
    asm volatile("cp.async.cg.shared.global [%0], [%1], 16;" :: "r"(s), "l"(g) : "memory")
#define CPCOMMIT() asm volatile("cp.async.commit_group;" ::: "memory")
#define CPWAIT(n)  asm volatile("cp.async.wait_group %0;" :: "n"(n) : "memory")

// ===========================================================================
// Pre-passes
// ===========================================================================
__global__ __launch_bounds__(256)
void cvt_act(const float* __restrict__ X, fp16* __restrict__ H)
{
    const int i = (blockIdx.x * 256 + threadIdx.x) * 4;
    float4 v = *(const float4*)&X[i];
    *(uint32_t*)&H[i]     = pack_f16x2(v.x, v.y);
    *(uint32_t*)&H[i + 2] = pack_f16x2(v.z, v.w);
}

__global__ __launch_bounds__(256)
void tsplit1(const float* __restrict__ W, fp16* __restrict__ T, int K, int N)
{
    __shared__ float t[32][33];
    const int n0 = blockIdx.x * 32, k0 = blockIdx.y * 32;
    const int tx = threadIdx.x & 31, ty4 = (threadIdx.x >> 5) * 4;
#pragma unroll
    for (int i = 0; i < 4; i++)
        t[ty4 + i][tx] = W[(size_t)(k0 + ty4 + i) * N + n0 + tx];
    __syncthreads();
#pragma unroll
    for (int i = 0; i < 4; i++)
        T[(size_t)(n0 + ty4 + i) * K + k0 + tx] = __float2half_rn(t[tx][ty4 + i]);
}

// ===========================================================================
// fp16 GEMM body: C = A[M,K] @ B1[N,K]^T + bias
// 128x128 block, BK=32, 3-stage cp.async pipeline, 2 CTAs/SM.
// ===========================================================================
#define KPAD 40
#define CB   (128 * KPAD * 2)      // 10240 B per operand tile
#define STGB (2 * CB)              // A + B per stage
#define GSMEM_BYTES (3 * STGB)     // 61440

__device__ __forceinline__ void gemm_body(
    const fp16* __restrict__ A, const fp16* __restrict__ B1,
    const float* __restrict__ bias,
    float* Cf, fp16* Ch,
    int N, int Kd, int relu, float oscale,
    int bm, int bn, uint32_t sbase)
{
    const int tid  = threadIdx.x;
    const int wid  = tid >> 5;
    const int lane = tid & 31;
    const int wm = (wid >> 2) * 64;
    const int wn = (wid & 3) * 32;
    const int NC = Kd >> 5;

    float acc[4][4][4];
#pragma unroll
    for (int i = 0; i < 4; i++)
#pragma unroll
        for (int j = 0; j < 4; j++)
#pragma unroll
            for (int l = 0; l < 4; l++) acc[i][j][l] = 0.0f;

    const int l_row = tid >> 2, l_sg = (tid & 3) << 3;
    const uint32_t l_so  = (uint32_t)((l_row * KPAD + l_sg) * 2);
    const uint32_t l_so2 = (uint32_t)(((l_row + 64) * KPAD + l_sg) * 2);
    const size_t l_ga0 = (size_t)(bm + l_row) * Kd + l_sg;
    const size_t l_ga2 = (size_t)(bm + l_row + 64) * Kd + l_sg;
    const size_t l_gb0 = (size_t)(bn + l_row) * Kd + l_sg;
    const size_t l_gb2 = (size_t)(bn + l_row + 64) * Kd + l_sg;

    auto issue = [&](int c) {
        const uint32_t sb = sbase + (uint32_t)((c % 3) * STGB);
        const int k0 = c << 5;
        CP16(sb + l_so,       A  + l_ga0 + k0);
        CP16(sb + CB + l_so,  B1 + l_gb0 + k0);
        CP16(sb + l_so2,      A  + l_ga2 + k0);
        CP16(sb + CB + l_so2, B1 + l_gb2 + k0);
        CPCOMMIT();
    };

    issue(0);
    if (NC > 1) issue(1);

    const int lrow = lane & 15, lc8 = (lane >> 4) << 3;

    for (int c = 0; c < NC; c++) {
        if (c + 2 < NC) { issue(c + 2); CPWAIT(2); }
        else if (c + 1 < NC) { CPWAIT(1); }
        else { CPWAIT(0); }
        __syncthreads();

        const uint32_t sb = sbase + (uint32_t)((c % 3) * STGB);
#pragma unroll
        for (int ks = 0; ks < 2; ks++) {
            const int kf = ks * 16 + lc8;
            uint32_t bh[2][4];
#pragma unroll
            for (int ng = 0; ng < 2; ng++) {
                const uint32_t ro = (uint32_t)(((wn + ng * 16 + lrow) * KPAD + kf) * 2);
                ldsm4(bh[ng], sb + CB + ro);
            }
#pragma unroll
            for (int mt = 0; mt < 4; mt++) {
                uint32_t ah[4];
                const uint32_t ro = (uint32_t)(((wm + mt * 16 + lrow) * KPAD + kf) * 2);
                ldsm4(ah, sb + ro);
#pragma unroll
                for (int ng = 0; ng < 2; ng++)
#pragma unroll
                    for (int j = 0; j < 2; j++)
                        hmma2(acc[mt][ng * 2 + j], ah, bh[ng][j], bh[ng][j + 2]);
            }
        }
        __syncthreads();
    }

    const int g = lane >> 2, t2 = (lane & 3) * 2;
#pragma unroll
    for (int mt = 0; mt < 4; mt++) {
        const int r0 = bm + wm + mt * 16 + g;
#pragma unroll
        for (int nt = 0; nt < 4; nt++) {
            const int cn = bn + wn + nt * 8 + t2;
            float2 v0, v1;
            v0.x = acc[mt][nt][0] + bias[cn];
            v0.y = acc[mt][nt][1] + bias[cn + 1];
            v1.x = acc[mt][nt][2] + bias[cn];
            v1.y = acc[mt][nt][3] + bias[cn + 1];
            if (relu) {
                v0.x = fmaxf(v0.x, 0.0f); v0.y = fmaxf(v0.y, 0.0f);
                v1.x = fmaxf(v1.x, 0.0f); v1.y = fmaxf(v1.y, 0.0f);
            }
            v0.x *= oscale; v0.y *= oscale; v1.x *= oscale; v1.y *= oscale;
            if (Cf) {
                *(float2*)&Cf[(size_t)r0 * N + cn]       = v0;
                *(float2*)&Cf[(size_t)(r0 + 8) * N + cn] = v1;
            }
            if (Ch) {
                *(uint32_t*)&Ch[(size_t)r0 * N + cn]       = pack_f16x2(v0.x, v0.y);
                *(uint32_t*)&Ch[(size_t)(r0 + 8) * N + cn] = pack_f16x2(v1.x, v1.y);
            }
        }
    }
}

__global__ __launch_bounds__(256, 2)
void gemm_f16(const fp16* __restrict__ A, const fp16* __restrict__ B1,
              const float* __restrict__ bias,
              float* Cf, fp16* Ch, int N, int Kd, int relu, float oscale)
{
    extern __shared__ char smc[];
    gemm_body(A, B1, bias, Cf, Ch, N, Kd, relu, oscale,
              blockIdx.y * 128, blockIdx.x * 128, smem_u32(smc));
}

// Fused Q/K/V projections: one launch, 3328 CTAs.
// gid < 1024: Q (64x16 tiles); < 2176: K (72x16); else V (72x16).
__global__ __launch_bounds__(256, 2)
void qkv_f16(const fp16* __restrict__ t1, const fp16* __restrict__ i1,
             const fp16* __restrict__ wq, const fp16* __restrict__ wk,
             const fp16* __restrict__ wv,
             const float* __restrict__ bq, const float* __restrict__ bk,
             const float* __restrict__ bv,
             fp16* __restrict__ Q1, fp16* __restrict__ K1, fp16* __restrict__ V1)
{
    extern __shared__ char smc[];
    const int gid = blockIdx.x;
    const fp16 *A, *Bw;
    const float* bias;
    fp16* C;
    int Kd, loc;
    float osc;
    if (gid < 1024)      { loc = gid;        A = t1; Bw = wq; bias = bq; C = Q1; Kd = TD; osc = 0.0625f; }
    else if (gid < 2176) { loc = gid - 1024; A = i1; Bw = wk; bias = bk; C = K1; Kd = ID; osc = 1.0f; }
    else                 { loc = gid - 2176; A = i1; Bw = wv; bias = bv; C = V1; Kd = ID; osc = 1.0f; }
    const int bn = (loc & 15) * 128;
    const int bm = (loc >> 4) * 128;
    gemm_body(A, Bw, bias, nullptr, C, HID, Kd, 0, osc, bm, bn, smem_u32(smc));
}

// ===========================================================================
// fp16 flash attention, cp.async double-buffered K/V.
// q-tile 128 (8 warps), kv-tile 64, 9 iters.
// ===========================================================================
#define ASD 264
#define KVB (64 * ASD * 2)                       // 33792 B per K or V buffer
#define ASMEM_BYTES (128 * ASD * 2 + 4 * KVB)    // 67584 + 135168 = 202752

__global__ __launch_bounds__(256, 1)
void attn2(const fp16* __restrict__ Q1, const fp16* __restrict__ K1,
           const fp16* __restrict__ V1, fp16* __restrict__ X1)
{
    extern __shared__ fp16 sm2[];
    fp16* sQ = sm2;
    const uint32_t sQb = smem_u32(sm2);
    const uint32_t sK0 = sQb + 128 * ASD * 2;
    const uint32_t sV0 = sK0 + 2 * KVB;

    const int tid  = threadIdx.x;
    const int wid  = tid >> 5;
    const int lane = tid & 31;
    const int qt = blockIdx.x, h = blockIdx.y, b = blockIdx.z;
    const int qrow0  = b * LT + qt * 128;
    const int kvrow0 = b * LI;
    const int hcol   = h * HD;

    // Q tile: 128 x 256 halves
#pragma unroll
    for (int i = 0; i < 16; i++) {
        const int gi = tid + i * 256;
        const int r = gi >> 5, c8 = (gi & 31) << 3;
        *(float4*)&sQ[r * ASD + c8] =
            *(const float4*)&Q1[(size_t)(qrow0 + r) * HID + hcol + c8];
    }

    const int lrow = lane & 15, lc8 = (lane >> 4) << 3;
    const uint32_t aQ = sQb + (uint32_t)(((wid * 16 + lrow) * ASD + lc8) * 2);
    const uint32_t fro = (uint32_t)((lrow * ASD + lc8) * 2);

    // K/V tile loader via cp.async: 64 rows x 512 B = 8 CP16/thread/array
    auto issue_kv = [&](int st) {
        const uint32_t kb = sK0 + (uint32_t)((st & 1) * KVB);
        const uint32_t vb = sV0 + (uint32_t)((st & 1) * KVB);
#pragma unroll
        for (int i = 0; i < 8; i++) {
            const int gi = tid + i * 256;
            const int r = gi >> 5, c8 = (gi & 31) << 3;
            const uint32_t so = (uint32_t)((r * ASD + c8) * 2);
            const size_t ga = (size_t)(kvrow0 + st * 64 + r) * HID + hcol + c8;
            CP16(kb + so, K1 + ga);
            CP16(vb + so, V1 + ga);
        }
        CPCOMMIT();
    };

    float o[32][4];
#pragma unroll
    for (int i = 0; i < 32; i++)
#pragma unroll
        for (int j = 0; j < 4; j++) o[i][j] = 0.0f;
    float m0 = -1e30f, m1 = -1e30f, l0 = 0.0f, l1 = 0.0f;

    issue_kv(0);

    for (int st = 0; st < 9; st++) {
        if (st + 1 < 9) { issue_kv(st + 1); CPWAIT(1); } else { CPWAIT(0); }
        __syncthreads();

        const uint32_t aK = sK0 + (uint32_t)((st & 1) * KVB) + fro;
        const uint32_t aV = sV0 + (uint32_t)((st & 1) * KVB) + fro;

        // S = Q K^T (scale folded into Q)
        float s[8][4];
#pragma unroll
        for (int i = 0; i < 8; i++)
#pragma unroll
            for (int j = 0; j < 4; j++) s[i][j] = 0.0f;

#pragma unroll
        for (int dc = 0; dc < 16; dc++) {
            uint32_t q0[4];
            ldsm4(q0, aQ + dc * 32);
#pragma unroll
            for (int kg = 0; kg < 4; kg++) {
                uint32_t k0[4];
                ldsm4(k0, aK + (uint32_t)(kg * 16 * ASD * 2) + dc * 32);
                hmma2(s[2 * kg],     q0, k0[0], k0[2]);
                hmma2(s[2 * kg + 1], q0, k0[1], k0[3]);
            }
        }

        // online softmax (rows g, g+8 of this warp)
        float rm0 = s[0][0], rm1 = s[0][2];
#pragma unroll
        for (int nt = 0; nt < 8; nt++) {
            rm0 = fmaxf(rm0, fmaxf(s[nt][0], s[nt][1]));
            rm1 = fmaxf(rm1, fmaxf(s[nt][2], s[nt][3]));
        }
        rm0 = fmaxf(rm0, __shfl_xor_sync(0xffffffffu, rm0, 1));
        rm0 = fmaxf(rm0, __shfl_xor_sync(0xffffffffu, rm0, 2));
        rm1 = fmaxf(rm1, __shfl_xor_sync(0xffffffffu, rm1, 1));
        rm1 = fmaxf(rm1, __shfl_xor_sync(0xffffffffu, rm1, 2));
        const float nm0 = fmaxf(m0, rm0), nm1 = fmaxf(m1, rm1);
        const float sc0 = __expf(m0 - nm0), sc1 = __expf(m1 - nm1);
        m0 = nm0; m1 = nm1;
        float ps0 = 0.0f, ps1 = 0.0f;
#pragma unroll
        for (int nt = 0; nt < 8; nt++) {
            s[nt][0] = __expf(s[nt][0] - nm0); ps0 += s[nt][0];
            s[nt][1] = __expf(s[nt][1] - nm0); ps0 += s[nt][1];
            s[nt][2] = __expf(s[nt][2] - nm1); ps1 += s[nt][2];
            s[nt][3] = __expf(s[nt][3] - nm1); ps1 += s[nt][3];
        }
        ps0 += __shfl_xor_sync(0xffffffffu, ps0, 1);
        ps0 += __shfl_xor_sync(0xffffffffu, ps0, 2);
        ps1 += __shfl_xor_sync(0xffffffffu, ps1, 1);
        ps1 += __shfl_xor_sync(0xffffffffu, ps1, 2);
        l0 = l0 * sc0 + ps0;
        l1 = l1 * sc1 + ps1;

#pragma unroll
        for (int nt = 0; nt < 32; nt++) {
            o[nt][0] *= sc0; o[nt][1] *= sc0;
            o[nt][2] *= sc1; o[nt][3] *= sc1;
        }

        // P fragments
        uint32_t pa[4][4];
#pragma unroll
        for (int kc = 0; kc < 4; kc++) {
            const float* f0 = s[2 * kc];
            const float* f1 = s[2 * kc + 1];
            pa[kc][0] = pack_f16x2(f0[0], f0[1]);
            pa[kc][1] = pack_f16x2(f0[2], f0[3]);
            pa[kc][2] = pack_f16x2(f1[0], f1[1]);
            pa[kc][3] = pack_f16x2(f1[2], f1[3]);
        }

        // O += P V
#pragma unroll
        for (int kc = 0; kc < 4; kc++) {
            const uint32_t vbase = (uint32_t)(kc * 16 * ASD * 2);
#pragma unroll
            for (int nd = 0; nd < 16; nd++) {
                uint32_t vh[4];
                ldsm4t(vh, aV + vbase + nd * 32);
                hmma2(o[2 * nd],     pa[kc], vh[0], vh[1]);
                hmma2(o[2 * nd + 1], pa[kc], vh[2], vh[3]);
            }
        }
        __syncthreads();   // compute done before next issue overwrites this buffer
    }

    const float i0 = 1.0f / l0, i1 = 1.0f / l1;
    const int g = lane >> 2, t2 = (lane & 3) * 2;
    const int r0 = qrow0 + wid * 16 + g;
#pragma unroll
    for (int nt = 0; nt < 32; nt++) {
        const int col = hcol + nt * 8 + t2;
        *(uint32_t*)&X1[(size_t)r0 * HID + col] =
            pack_f16x2(o[nt][0] * i0, o[nt][1] * i0);
        *(uint32_t*)&X1[(size_t)(r0 + 8) * HID + col] =
            pack_f16x2(o[nt][2] * i1, o[nt][3] * i1);
    }
}

// ---------------------------------------------------------------------------
// Residual + LayerNorm epilogue
// ---------------------------------------------------------------------------
__device__ __forceinline__ float block_sum(float x, float* red)
{
#pragma unroll
    for (int off = 16; off > 0; off >>= 1)
        x += __shfl_xor_sync(0xffffffffu, x, off);
    const int w = threadIdx.x >> 5;
    if ((threadIdx.x & 31) == 0) red[w] = x;
    __syncthreads();
    if (threadIdx.x < 32) {
        float y = (threadIdx.x < 8) ? red[threadIdx.x] : 0.0f;
#pragma unroll
        for (int off = 4; off > 0; off >>= 1)
            y += __shfl_xor_sync(0xffffffffu, y, off);
        if (threadIdx.x == 0) red[0] = y;
    }
    __syncthreads();
    const float r = red[0];
    __syncthreads();
    return r;
}

__global__ __launch_bounds__(256)
void ffln_kernel(const float* __restrict__ OUT, const float* __restrict__ FF,
                 const float* __restrict__ gamma, const float* __restrict__ beta,
                 float* __restrict__ Y)
{
    __shared__ float red[8];
    const int r = blockIdx.x;
    const int tid = threadIdx.x;
    float v[3];
#pragma unroll
    for (int i = 0; i < 3; i++) {
        const int idx = tid + i * 256;
        v[i] = OUT[(size_t)r * TD + idx] + FF[(size_t)r * TD + idx];
    }
    const float mu = block_sum(v[0] + v[1] + v[2], red) * (1.0f / 768.0f);
    const float d0 = v[0] - mu, d1 = v[1] - mu, d2 = v[2] - mu;
    const float var = block_sum(d0 * d0 + d1 * d1 + d2 * d2, red) * (1.0f / 768.0f);
    const float rstd = rsqrtf(var + 1e-5f);
#pragma unroll
    for (int i = 0; i < 3; i++) {
        const int idx = tid + i * 256;
        Y[(size_t)r * TD + idx] = (v[i] - mu) * rstd * gamma[idx] + beta[idx];
    }
}

// ---------------------------------------------------------------------------
extern "C" void kernel_launch(void* const* d_in, const int* in_sizes, int n_in,
                              void* d_out, int out_size)
{
    const float* text  = (const float*)d_in[0];
    const float* image = (const float*)d_in[1];
    const float* wq = (const float*)d_in[2];
    const float* bq = (const float*)d_in[3];
    const float* wk = (const float*)d_in[4];
    const float* bk = (const float*)d_in[5];
    const float* wv = (const float*)d_in[6];
    const float* bv = (const float*)d_in[7];
    const float* wr = (const float*)d_in[8];
    const float* br = (const float*)d_in[9];
    const float* w1 = (const float*)d_in[10];
    const float* b1 = (const float*)d_in[11];
    const float* w2 = (const float*)d_in[12];
    const float* b2 = (const float*)d_in[13];
    const float* gamma = (const float*)d_in[14];
    const float* beta  = (const float*)d_in[15];
    float* Y = (float*)d_out;

    fp16 *t1, *i1, *pwq, *pwk, *pwv, *pwr, *pw1, *pw2;
    fp16 *Q1, *K1, *V1, *X1, *O1, *H1;
    float *O, *F;
    cudaGetSymbolAddress((void**)&t1, g_t1);
    cudaGetSymbolAddress((void**)&i1, g_i1);
    cudaGetSymbolAddress((void**)&pwq, g_wq);  cudaGetSymbolAddress((void**)&pwk, g_wk);
    cudaGetSymbolAddress((void**)&pwv, g_wv);  cudaGetSymbolAddress((void**)&pwr, g_wr);
    cudaGetSymbolAddress((void**)&pw1, g_w1);  cudaGetSymbolAddress((void**)&pw2, g_w2);
    cudaGetSymbolAddress((void**)&Q1, g_Q1);   cudaGetSymbolAddress((void**)&K1, g_K1);
    cudaGetSymbolAddress((void**)&V1, g_V1);   cudaGetSymbolAddress((void**)&X1, g_X1);
    cudaGetSymbolAddress((void**)&O1, g_O1);   cudaGetSymbolAddress((void**)&H1, g_H1);
    cudaGetSymbolAddress((void**)&O, g_O);
    cudaGetSymbolAddress((void**)&F, g_F);

    cudaFuncSetAttribute(gemm_f16, cudaFuncAttributeMaxDynamicSharedMemorySize, GSMEM_BYTES);
    cudaFuncSetAttribute(qkv_f16,  cudaFuncAttributeMaxDynamicSharedMemorySize, GSMEM_BYTES);
    cudaFuncSetAttribute(attn2, cudaFuncAttributeMaxDynamicSharedMemorySize, ASMEM_BYTES);

    // --- pre-passes ---
    cvt_act<<<(B_ * LT * TD) / 1024, 256>>>(text, t1);
    cvt_act<<<(B_ * LI * ID) / 1024, 256>>>(image, i1);
    tsplit1<<<dim3(HID / 32, TD / 32),  256>>>(wq, pwq, TD,  HID);
    tsplit1<<<dim3(HID / 32, ID / 32),  256>>>(wk, pwk, ID,  HID);
    tsplit1<<<dim3(HID / 32, ID / 32),  256>>>(wv, pwv, ID,  HID);
    tsplit1<<<dim3(TD / 32,  HID / 32), 256>>>(wr, pwr, HID, TD);
    tsplit1<<<dim3(FFD / 32, TD / 32),  256>>>(w1, pw1, TD,  FFD);
    tsplit1<<<dim3(TD / 32,  FFD / 32), 256>>>(w2, pw2, FFD, TD);

    // --- fused Q/K/V projections (Q scaled by 1/sqrt(256)) ---
    qkv_f16<<<3328, 256, GSMEM_BYTES>>>(t1, i1, pwq, pwk, pwv, bq, bk, bv, Q1, K1, V1);

    // --- attention ---
    attn2<<<dim3(LT / 128, NH, B_), 256, ASMEM_BYTES>>>(Q1, K1, V1, X1);

    // --- output projection + FF ---
    gemm_f16<<<dim3(TD / 128, (B_ * LT) / 128), 256, GSMEM_BYTES>>>(
        X1, pwr, br, O, O1, TD, HID, 0, 1.0f);
    gemm_f16<<<dim3(FFD / 128, (B_ * LT) / 128), 256, GSMEM_BYTES>>>(
        O1, pw1, b1, nullptr, H1, FFD, TD, 1, 1.0f);
    gemm_f16<<<dim3(TD / 128, (B_ * LT) / 128), 256, GSMEM_BYTES>>>(
        H1, pw2, b2, F, nullptr, TD, FFD, 0, 1.0f);

    // --- residual + LayerNorm ---
    ffln_kernel<<<B_ * LT, 256>>>(O, F, gamma, beta, Y);
}

// round 12
// speedup vs baseline: 8.7923x; 1.0111x over previous
#include <cuda_runtime.h>
#include <cuda_fp16.h>
#include <cstdint>
#include <math.h>

#define B_   16
#define LT   512
#define LI   576
#define TD   768
#define ID   1024
#define HID  2048
#define NH   8
#define HD   256
#define FFD  128

typedef __half fp16;

// ---- scratch (device globals) ----
__device__ fp16 g_t1[B_ * LT * TD];
__device__ fp16 g_i1[B_ * LI * ID];
__device__ fp16 g_wq[HID * TD];
__device__ fp16 g_wk[HID * ID];
__device__ fp16 g_wv[HID * ID];
__device__ fp16 g_wr[TD * HID];
__device__ fp16 g_w1[FFD * TD];
__device__ fp16 g_w2[TD * FFD];
__device__ fp16 g_Q1[B_ * LT * HID];
__device__ fp16 g_K1[B_ * LI * HID];
__device__ fp16 g_V1[B_ * LI * HID];
__device__ fp16 g_X1[B_ * LT * HID];
__device__ fp16 g_O1[B_ * LT * TD];
__device__ fp16 g_H1[B_ * LT * FFD];
__device__ float g_O[B_ * LT * TD];
__device__ float g_F[B_ * LT * TD];

// ===========================================================================
// helpers
// ===========================================================================
__device__ __forceinline__ void hmma2(float* c, const uint32_t* a, uint32_t b0, uint32_t b1)
{
    asm volatile(
        "mma.sync.aligned.m16n8k16.row.col.f32.f16.f16.f32 "
        "{%0,%1,%2,%3}, {%4,%5,%6,%7}, {%8,%9}, {%0,%1,%2,%3};"
        : "+f"(c[0]), "+f"(c[1]), "+f"(c[2]), "+f"(c[3])
        : "r"(a[0]), "r"(a[1]), "r"(a[2]), "r"(a[3]), "r"(b0), "r"(b1));
}
__device__ __forceinline__ void ldsm4(uint32_t* r, uint32_t addr)
{
    asm volatile("ldmatrix.sync.aligned.m8n8.x4.shared.b16 {%0,%1,%2,%3}, [%4];"
                 : "=r"(r[0]), "=r"(r[1]), "=r"(r[2]), "=r"(r[3]) : "r"(addr));
}
__device__ __forceinline__ void ldsm4t(uint32_t* r, uint32_t addr)
{
    asm volatile("ldmatrix.sync.aligned.m8n8.x4.trans.shared.b16 {%0,%1,%2,%3}, [%4];"
                 : "=r"(r[0]), "=r"(r[1]), "=r"(r[2]), "=r"(r[3]) : "r"(addr));
}
__device__ __forceinline__ uint32_t smem_u32(const void* p) {
    uint32_t a;
    asm("{ .reg .u64 t; cvta.to.shared.u64 t, %1; cvt.u32.u64 %0, t; }" : "=r"(a) : "l"(p));
    return a;
}
__device__ __forceinline__ uint32_t pack_f16x2(float x0, float x1)
{
    __half2 h = __floats2half2_rn(x0, x1);
    return *(uint32_t*)&h;
}
#define CP16(s, g) \
    asm volatile("cp.async.cg.shared.global [%0], [%1], 16;" :: "r"(s), "l"(g) : "memory")
#define CPCOMMIT() asm volatile("cp.async.commit_group;" ::: "memory")
#define CPWAIT(n)  asm volatile("cp.async.wait_group %0;" :: "n"(n) : "memory")

// ===========================================================================
// Fused pre-pass: activation fp32->fp16 + 6 weight transposes, one launch.
// Block-id ranges:
//   [0, 6144)        text cvt   (1024 elems per CTA)
//   [6144, 15360)    image cvt
//   [15360, 16896)   wq^T  (N=HID, K=TD,  32x32 tiles)
//   [16896, 18944)   wk^T  (N=HID, K=ID)
//   [18944, 20992)   wv^T  (N=HID, K=ID)
//   [20992, 22528)   wr^T  (N=TD,  K=HID)
//   [22528, 22624)   w1^T  (N=FFD, K=TD)
//   [22624, 22720)   w2^T  (N=TD,  K=FFD)
// ===========================================================================
#define PREP_GRID 22720

__device__ __forceinline__ void cvt_seg(const float* X, fp16* H, int loc)
{
    const int i = (loc * 256 + threadIdx.x) * 4;
    float4 v = *(const float4*)&X[i];
    *(uint32_t*)&H[i]     = pack_f16x2(v.x, v.y);
    *(uint32_t*)&H[i + 2] = pack_f16x2(v.z, v.w);
}
__device__ __forceinline__ void tr_seg(const float* W, fp16* T, int K, int N, int loc)
{
    __shared__ float t[32][33];
    const int nt = loc % (N >> 5), kt = loc / (N >> 5);
    const int n0 = nt * 32, k0 = kt * 32;
    const int tx = threadIdx.x & 31, ty4 = (threadIdx.x >> 5) * 4;
#pragma unroll
    for (int i = 0; i < 4; i++)
        t[ty4 + i][tx] = W[(size_t)(k0 + ty4 + i) * N + n0 + tx];
    __syncthreads();
#pragma unroll
    for (int i = 0; i < 4; i++)
        T[(size_t)(n0 + ty4 + i) * K + k0 + tx] = __float2half_rn(t[tx][ty4 + i]);
}

__global__ __launch_bounds__(256)
void prep(const float* __restrict__ text, const float* __restrict__ image,
          const float* __restrict__ wq, const float* __restrict__ wk,
          const float* __restrict__ wv, const float* __restrict__ wr,
          const float* __restrict__ w1, const float* __restrict__ w2,
          fp16* t1, fp16* i1, fp16* pwq, fp16* pwk, fp16* pwv,
          fp16* pwr, fp16* pw1, fp16* pw2)
{
    const int g = blockIdx.x;
    if      (g < 6144)  cvt_seg(text,  t1, g);
    else if (g < 15360) cvt_seg(image, i1, g - 6144);
    else if (g < 16896) tr_seg(wq, pwq, TD,  HID, g - 15360);
    else if (g < 18944) tr_seg(wk, pwk, ID,  HID, g - 16896);
    else if (g < 20992) tr_seg(wv, pwv, ID,  HID, g - 18944);
    else if (g < 22528) tr_seg(wr, pwr, HID, TD,  g - 20992);
    else if (g < 22624) tr_seg(w1, pw1, TD,  FFD, g - 22528);
    else                tr_seg(w2, pw2, FFD, TD,  g - 22624);
}

// ===========================================================================
// fp16 GEMM body: C = A[M,K] @ B1[N,K]^T + bias
// 128x128 block, BK=32, 3-stage cp.async pipeline, 2 CTAs/SM.
// ===========================================================================
#define KPAD 40
#define CB   (128 * KPAD * 2)
#define STGB (2 * CB)
#define GSMEM_BYTES (3 * STGB)

__device__ __forceinline__ void gemm_body(
    const fp16* __restrict__ A, const fp16* __restrict__ B1,
    const float* __restrict__ bias,
    float* Cf, fp16* Ch,
    int N, int Kd, int relu, float oscale,
    int bm, int bn, uint32_t sbase)
{
    const int tid  = threadIdx.x;
    const int wid  = tid >> 5;
    const int lane = tid & 31;
    const int wm = (wid >> 2) * 64;
    const int wn = (wid & 3) * 32;
    const int NC = Kd >> 5;

    float acc[4][4][4];
#pragma unroll
    for (int i = 0; i < 4; i++)
#pragma unroll
        for (int j = 0; j < 4; j++)
#pragma unroll
            for (int l = 0; l < 4; l++) acc[i][j][l] = 0.0f;

    const int l_row = tid >> 2, l_sg = (tid & 3) << 3;
    const uint32_t l_so  = (uint32_t)((l_row * KPAD + l_sg) * 2);
    const uint32_t l_so2 = (uint32_t)(((l_row + 64) * KPAD + l_sg) * 2);
    const size_t l_ga0 = (size_t)(bm + l_row) * Kd + l_sg;
    const size_t l_ga2 = (size_t)(bm + l_row + 64) * Kd + l_sg;
    const size_t l_gb0 = (size_t)(bn + l_row) * Kd + l_sg;
    const size_t l_gb2 = (size_t)(bn + l_row + 64) * Kd + l_sg;

    auto issue = [&](int c) {
        const uint32_t sb = sbase + (uint32_t)((c % 3) * STGB);
        const int k0 = c << 5;
        CP16(sb + l_so,       A  + l_ga0 + k0);
        CP16(sb + CB + l_so,  B1 + l_gb0 + k0);
        CP16(sb + l_so2,      A  + l_ga2 + k0);
        CP16(sb + CB + l_so2, B1 + l_gb2 + k0);
        CPCOMMIT();
    };

    issue(0);
    if (NC > 1) issue(1);

    const int lrow = lane & 15, lc8 = (lane >> 4) << 3;

    for (int c = 0; c < NC; c++) {
        if (c + 2 < NC) { issue(c + 2); CPWAIT(2); }
        else if (c + 1 < NC) { CPWAIT(1); }
        else { CPWAIT(0); }
        __syncthreads();

        const uint32_t sb = sbase + (uint32_t)((c % 3) * STGB);
#pragma unroll
        for (int ks = 0; ks < 2; ks++) {
            const int kf = ks * 16 + lc8;
            uint32_t bh[2][4];
#pragma unroll
            for (int ng = 0; ng < 2; ng++) {
                const uint32_t ro = (uint32_t)(((wn + ng * 16 + lrow) * KPAD + kf) * 2);
                ldsm4(bh[ng], sb + CB + ro);
            }
#pragma unroll
            for (int mt = 0; mt < 4; mt++) {
                uint32_t ah[4];
                const uint32_t ro = (uint32_t)(((wm + mt * 16 + lrow) * KPAD + kf) * 2);
                ldsm4(ah, sb + ro);
#pragma unroll
                for (int ng = 0; ng < 2; ng++)
#pragma unroll
                    for (int j = 0; j < 2; j++)
                        hmma2(acc[mt][ng * 2 + j], ah, bh[ng][j], bh[ng][j + 2]);
            }
        }
        __syncthreads();
    }

    const int g = lane >> 2, t2 = (lane & 3) * 2;
#pragma unroll
    for (int mt = 0; mt < 4; mt++) {
        const int r0 = bm + wm + mt * 16 + g;
#pragma unroll
        for (int nt = 0; nt < 4; nt++) {
            const int cn = bn + wn + nt * 8 + t2;
            float2 v0, v1;
            v0.x = acc[mt][nt][0] + bias[cn];
            v0.y = acc[mt][nt][1] + bias[cn + 1];
            v1.x = acc[mt][nt][2] + bias[cn];
            v1.y = acc[mt][nt][3] + bias[cn + 1];
            if (relu) {
                v0.x = fmaxf(v0.x, 0.0f); v0.y = fmaxf(v0.y, 0.0f);
                v1.x = fmaxf(v1.x, 0.0f); v1.y = fmaxf(v1.y, 0.0f);
            }
            v0.x *= oscale; v0.y *= oscale; v1.x *= oscale; v1.y *= oscale;
            if (Cf) {
                *(float2*)&Cf[(size_t)r0 * N + cn]       = v0;
                *(float2*)&Cf[(size_t)(r0 + 8) * N + cn] = v1;
            }
            if (Ch) {
                *(uint32_t*)&Ch[(size_t)r0 * N + cn]       = pack_f16x2(v0.x, v0.y);
                *(uint32_t*)&Ch[(size_t)(r0 + 8) * N + cn] = pack_f16x2(v1.x, v1.y);
            }
        }
    }
}

__global__ __launch_bounds__(256, 2)
void gemm_f16(const fp16* __restrict__ A, const fp16* __restrict__ B1,
              const float* __restrict__ bias,
              float* Cf, fp16* Ch, int N, int Kd, int relu, float oscale)
{
    extern __shared__ char smc[];
    gemm_body(A, B1, bias, Cf, Ch, N, Kd, relu, oscale,
              blockIdx.y * 128, blockIdx.x * 128, smem_u32(smc));
}

// Fused Q/K/V projections: one launch, 3328 CTAs.
__global__ __launch_bounds__(256, 2)
void qkv_f16(const fp16* __restrict__ t1, const fp16* __restrict__ i1,
             const fp16* __restrict__ wq, const fp16* __restrict__ wk,
             const fp16* __restrict__ wv,
             const float* __restrict__ bq, const float* __restrict__ bk,
             const float* __restrict__ bv,
             fp16* __restrict__ Q1, fp16* __restrict__ K1, fp16* __restrict__ V1)
{
    extern __shared__ char smc[];
    const int gid = blockIdx.x;
    const fp16 *A, *Bw;
    const float* bias;
    fp16* C;
    int Kd, loc;
    float osc;
    if (gid < 1024)      { loc = gid;        A = t1; Bw = wq; bias = bq; C = Q1; Kd = TD; osc = 0.0625f; }
    else if (gid < 2176) { loc = gid - 1024; A = i1; Bw = wk; bias = bk; C = K1; Kd = ID; osc = 1.0f; }
    else                 { loc = gid - 2176; A = i1; Bw = wv; bias = bv; C = V1; Kd = ID; osc = 1.0f; }
    const int bn = (loc & 15) * 128;
    const int bm = (loc >> 4) * 128;
    gemm_body(A, Bw, bias, nullptr, C, HID, Kd, 0, osc, bm, bn, smem_u32(smc));
}

// ===========================================================================
// fp16 flash attention: 128 threads (4 warps), q-tile 64, kv-tile 32,
// cp.async double-buffered K/V, 2 CTAs/SM. 18 kv iterations.
// ===========================================================================
#define ASD 264
#define AKVB (32 * ASD * 2)                        // 16896 B per K or V buffer
#define ASMEM_BYTES (64 * ASD * 2 + 4 * AKVB)      // 33792 + 67584 = 101376

__global__ __launch_bounds__(128, 2)
void attn2(const fp16* __restrict__ Q1, const fp16* __restrict__ K1,
           const fp16* __restrict__ V1, fp16* __restrict__ X1)
{
    extern __shared__ fp16 sm2[];
    fp16* sQ = sm2;
    const uint32_t sQb = smem_u32(sm2);
    const uint32_t sK0 = sQb + 64 * ASD * 2;
    const uint32_t sV0 = sK0 + 2 * AKVB;

    const int tid  = threadIdx.x;
    const int wid  = tid >> 5;     // 0..3
    const int lane = tid & 31;
    const int qt = blockIdx.x, h = blockIdx.y, b = blockIdx.z;
    const int qrow0  = b * LT + qt * 64;
    const int kvrow0 = b * LI;
    const int hcol   = h * HD;

    // Q tile: 64 x 256 halves = 16 iters x 128 thr x 8
#pragma unroll
    for (int i = 0; i < 16; i++) {
        const int gi = tid + i * 128;
        const int r = gi >> 5, c8 = (gi & 31) << 3;
        *(float4*)&sQ[r * ASD + c8] =
            *(const float4*)&Q1[(size_t)(qrow0 + r) * HID + hcol + c8];
    }

    const int lrow = lane & 15, lc8 = (lane >> 4) << 3;
    const uint32_t aQ = sQb + (uint32_t)(((wid * 16 + lrow) * ASD + lc8) * 2);
    const uint32_t fro = (uint32_t)((lrow * ASD + lc8) * 2);

    // K/V tile loader: 32 rows x 512 B -> 8 CP16/thread/array
    auto issue_kv = [&](int st) {
        const uint32_t kb = sK0 + (uint32_t)((st & 1) * AKVB);
        const uint32_t vb = sV0 + (uint32_t)((st & 1) * AKVB);
#pragma unroll
        for (int i = 0; i < 8; i++) {
            const int gi = tid + i * 128;
            const int r = gi >> 5, c8 = (gi & 31) << 3;
            const uint32_t so = (uint32_t)((r * ASD + c8) * 2);
            const size_t ga = (size_t)(kvrow0 + st * 32 + r) * HID + hcol + c8;
            CP16(kb + so, K1 + ga);
            CP16(vb + so, V1 + ga);
        }
        CPCOMMIT();
    };

    float o[32][4];
#pragma unroll
    for (int i = 0; i < 32; i++)
#pragma unroll
        for (int j = 0; j < 4; j++) o[i][j] = 0.0f;
    float m0 = -1e30f, m1 = -1e30f, l0 = 0.0f, l1 = 0.0f;

    issue_kv(0);

    for (int st = 0; st < 18; st++) {
        if (st + 1 < 18) { issue_kv(st + 1); CPWAIT(1); } else { CPWAIT(0); }
        __syncthreads();

        const uint32_t aK = sK0 + (uint32_t)((st & 1) * AKVB) + fro;
        const uint32_t aV = sV0 + (uint32_t)((st & 1) * AKVB) + fro;

        // S = Q K^T (scale folded into Q); 64q x 32k per CTA
        float s[4][4];
#pragma unroll
        for (int i = 0; i < 4; i++)
#pragma unroll
            for (int j = 0; j < 4; j++) s[i][j] = 0.0f;

#pragma unroll
        for (int dc = 0; dc < 16; dc++) {
            uint32_t q0[4];
            ldsm4(q0, aQ + dc * 32);
#pragma unroll
            for (int kg = 0; kg < 2; kg++) {
                uint32_t k0[4];
                ldsm4(k0, aK + (uint32_t)(kg * 16 * ASD * 2) + dc * 32);
                hmma2(s[2 * kg],     q0, k0[0], k0[2]);
                hmma2(s[2 * kg + 1], q0, k0[1], k0[3]);
            }
        }

        // online softmax (rows g, g+8 of this warp)
        float rm0 = s[0][0], rm1 = s[0][2];
#pragma unroll
        for (int nt = 0; nt < 4; nt++) {
            rm0 = fmaxf(rm0, fmaxf(s[nt][0], s[nt][1]));
            rm1 = fmaxf(rm1, fmaxf(s[nt][2], s[nt][3]));
        }
        rm0 = fmaxf(rm0, __shfl_xor_sync(0xffffffffu, rm0, 1));
        rm0 = fmaxf(rm0, __shfl_xor_sync(0xffffffffu, rm0, 2));
        rm1 = fmaxf(rm1, __shfl_xor_sync(0xffffffffu, rm1, 1));
        rm1 = fmaxf(rm1, __shfl_xor_sync(0xffffffffu, rm1, 2));
        const float nm0 = fmaxf(m0, rm0), nm1 = fmaxf(m1, rm1);
        const float sc0 = __expf(m0 - nm0), sc1 = __expf(m1 - nm1);
        m0 = nm0; m1 = nm1;
        float ps0 = 0.0f, ps1 = 0.0f;
#pragma unroll
        for (int nt = 0; nt < 4; nt++) {
            s[nt][0] = __expf(s[nt][0] - nm0); ps0 += s[nt][0];
            s[nt][1] = __expf(s[nt][1] - nm0); ps0 += s[nt][1];
            s[nt][2] = __expf(s[nt][2] - nm1); ps1 += s[nt][2];
            s[nt][3] = __expf(s[nt][3] - nm1); ps1 += s[nt][3];
        }
        ps0 += __shfl_xor_sync(0xffffffffu, ps0, 1);
        ps0 += __shfl_xor_sync(0xffffffffu, ps0, 2);
        ps1 += __shfl_xor_sync(0xffffffffu, ps1, 1);
        ps1 += __shfl_xor_sync(0xffffffffu, ps1, 2);
        l0 = l0 * sc0 + ps0;
        l1 = l1 * sc1 + ps1;

#pragma unroll
        for (int nt = 0; nt < 32; nt++) {
            o[nt][0] *= sc0; o[nt][1] *= sc0;
            o[nt][2] *= sc1; o[nt][3] *= sc1;
        }

        // P fragments (2 k16-groups over 32 kv rows)
        uint32_t pa[2][4];
#pragma unroll
        for (int kc = 0; kc < 2; kc++) {
            const float* f0 = s[2 * kc];
            const float* f1 = s[2 * kc + 1];
            pa[kc][0] = pack_f16x2(f0[0], f0[1]);
            pa[kc][1] = pack_f16x2(f0[2], f0[3]);
            pa[kc][2] = pack_f16x2(f1[0], f1[1]);
            pa[kc][3] = pack_f16x2(f1[2], f1[3]);
        }

        // O += P V
#pragma unroll
        for (int kc = 0; kc < 2; kc++) {
            const uint32_t vbase = (uint32_t)(kc * 16 * ASD * 2);
#pragma unroll
            for (int nd = 0; nd < 16; nd++) {
                uint32_t vh[4];
                ldsm4t(vh, aV + vbase + nd * 32);
                hmma2(o[2 * nd],     pa[kc], vh[0], vh[1]);
                hmma2(o[2 * nd + 1], pa[kc], vh[2], vh[3]);
            }
        }
        __syncthreads();   // protect buffer (st&1) from issue(st+2)
    }

    const float i0 = 1.0f / l0, i1 = 1.0f / l1;
    const int g = lane >> 2, t2 = (lane & 3) * 2;
    const int r0 = qrow0 + wid * 16 + g;
#pragma unroll
    for (int nt = 0; nt < 32; nt++) {
        const int col = hcol + nt * 8 + t2;
        *(uint32_t*)&X1[(size_t)r0 * HID + col] =
            pack_f16x2(o[nt][0] * i0, o[nt][1] * i0);
        *(uint32_t*)&X1[(size_t)(r0 + 8) * HID + col] =
            pack_f16x2(o[nt][2] * i1, o[nt][3] * i1);
    }
}

// ---------------------------------------------------------------------------
// Residual + LayerNorm epilogue
// ---------------------------------------------------------------------------
__device__ __forceinline__ float block_sum(float x, float* red)
{
#pragma unroll
    for (int off = 16; off > 0; off >>= 1)
        x += __shfl_xor_sync(0xffffffffu, x, off);
    const int w = threadIdx.x >> 5;
    if ((threadIdx.x & 31) == 0) red[w] = x;
    __syncthreads();
    if (threadIdx.x < 32) {
        float y = (threadIdx.x < 8) ? red[threadIdx.x] : 0.0f;
#pragma unroll
        for (int off = 4; off > 0; off >>= 1)
            y += __shfl_xor_sync(0xffffffffu, y, off);
        if (threadIdx.x == 0) red[0] = y;
    }
    __syncthreads();
    const float r = red[0];
    __syncthreads();
    return r;
}

__global__ __launch_bounds__(256)
void ffln_kernel(const float* __restrict__ OUT, const float* __restrict__ FF,
                 const float* __restrict__ gamma, const float* __restrict__ beta,
                 float* __restrict__ Y)
{
    __shared__ float red[8];
    const int r = blockIdx.x;
    const int tid = threadIdx.x;
    float v[3];
#pragma unroll
    for (int i = 0; i < 3; i++) {
        const int idx = tid + i * 256;
        v[i] = OUT[(size_t)r * TD + idx] + FF[(size_t)r * TD + idx];
    }
    const float mu = block_sum(v[0] + v[1] + v[2], red) * (1.0f / 768.0f);
    const float d0 = v[0] - mu, d1 = v[1] - mu, d2 = v[2] - mu;
    const float var = block_sum(d0 * d0 + d1 * d1 + d2 * d2, red) * (1.0f / 768.0f);
    const float rstd = rsqrtf(var + 1e-5f);
#pragma unroll
    for (int i = 0; i < 3; i++) {
        const int idx = tid + i * 256;
        Y[(size_t)r * TD + idx] = (v[i] - mu) * rstd * gamma[idx] + beta[idx];
    }
}

// ---------------------------------------------------------------------------
extern "C" void kernel_launch(void* const* d_in, const int* in_sizes, int n_in,
                              void* d_out, int out_size)
{
    const float* text  = (const float*)d_in[0];
    const float* image = (const float*)d_in[1];
    const float* wq = (const float*)d_in[2];
    const float* bq = (const float*)d_in[3];
    const float* wk = (const float*)d_in[4];
    const float* bk = (const float*)d_in[5];
    const float* wv = (const float*)d_in[6];
    const float* bv = (const float*)d_in[7];
    const float* wr = (const float*)d_in[8];
    const float* br = (const float*)d_in[9];
    const float* w1 = (const float*)d_in[10];
    const float* b1 = (const float*)d_in[11];
    const float* w2 = (const float*)d_in[12];
    const float* b2 = (const float*)d_in[13];
    const float* gamma = (const float*)d_in[14];
    const float* beta  = (const float*)d_in[15];
    float* Y = (float*)d_out;

    fp16 *t1, *i1, *pwq, *pwk, *pwv, *pwr, *pw1, *pw2;
    fp16 *Q1, *K1, *V1, *X1, *O1, *H1;
    float *O, *F;
    cudaGetSymbolAddress((void**)&t1, g_t1);
    cudaGetSymbolAddress((void**)&i1, g_i1);
    cudaGetSymbolAddress((void**)&pwq, g_wq);  cudaGetSymbolAddress((void**)&pwk, g_wk);
    cudaGetSymbolAddress((void**)&pwv, g_wv);  cudaGetSymbolAddress((void**)&pwr, g_wr);
    cudaGetSymbolAddress((void**)&pw1, g_w1);  cudaGetSymbolAddress((void**)&pw2, g_w2);
    cudaGetSymbolAddress((void**)&Q1, g_Q1);   cudaGetSymbolAddress((void**)&K1, g_K1);
    cudaGetSymbolAddress((void**)&V1, g_V1);   cudaGetSymbolAddress((void**)&X1, g_X1);
    cudaGetSymbolAddress((void**)&O1, g_O1);   cudaGetSymbolAddress((void**)&H1, g_H1);
    cudaGetSymbolAddress((void**)&O, g_O);
    cudaGetSymbolAddress((void**)&F, g_F);

    cudaFuncSetAttribute(gemm_f16, cudaFuncAttributeMaxDynamicSharedMemorySize, GSMEM_BYTES);
    cudaFuncSetAttribute(qkv_f16,  cudaFuncAttributeMaxDynamicSharedMemorySize, GSMEM_BYTES);
    cudaFuncSetAttribute(attn2, cudaFuncAttributeMaxDynamicSharedMemorySize, ASMEM_BYTES);

    // --- fused pre-pass (1 launch) ---
    prep<<<PREP_GRID, 256>>>(text, image, wq, wk, wv, wr, w1, w2,
                             t1, i1, pwq, pwk, pwv, pwr, pw1, pw2);

    // --- fused Q/K/V projections (Q scaled by 1/sqrt(256)) ---
    qkv_f16<<<3328, 256, GSMEM_BYTES>>>(t1, i1, pwq, pwk, pwv, bq, bk, bv, Q1, K1, V1);

    // --- attention (2 CTAs/SM) ---
    attn2<<<dim3(LT / 64, NH, B_), 128, ASMEM_BYTES>>>(Q1, K1, V1, X1);

    // --- output projection + FF ---
    gemm_f16<<<dim3(TD / 128, (B_ * LT) / 128), 256, GSMEM_BYTES>>>(
        X1, pwr, br, O, O1, TD, HID, 0, 1.0f);
    gemm_f16<<<dim3(FFD / 128, (B_ * LT) / 128), 256, GSMEM_BYTES>>>(
        O1, pw1, b1, nullptr, H1, FFD, TD, 1, 1.0f);
    gemm_f16<<<dim3(TD / 128, (B_ * LT) / 128), 256, GSMEM_BYTES>>>(
        H1, pw2, b2, F, nullptr, TD, FFD, 0, 1.0f);

    // --- residual + LayerNorm ---
    ffln_kernel<<<B_ * LT, 256>>>(O, F, gamma, beta, Y);
}